// round 3
// baseline (speedup 1.0000x reference)
#include <cuda_runtime.h>
#include <math.h>

// ---------------------------------------------------------------------------
// Problem constants: B=16 graphs, N=1024 points.
//   Layer1: Cin=6,   Cout=128,  K=6
//   Layer2: Cin=128, Cout=512,  K=5
//   Layer3: Cin=512, Cout=1024, K=3
// Output: logits [16,10] (160 floats) then r1, r2, r3 -> 163 floats.
// ---------------------------------------------------------------------------

#define BB 16
#define NN 1024

// Scratch (device globals; no allocation allowed)
__device__ float g_W   [BB * NN * NN];      // adjacency (per layer, reused)
__device__ float g_T   [BB * NN * 1024];    // reg L@out
__device__ float g_out1[BB * NN * 128];
__device__ float g_out2[BB * NN * 512];
__device__ float g_out3[BB * NN * 1024];
__device__ float g_Za  [BB * NN * 512];
__device__ float g_Zb  [BB * NN * 512];
__device__ float g_Zc  [BB * NN * 512];
__device__ float g_M   [1024 * 1024];
__device__ float g_sq  [BB * NN];
__device__ float g_dinv[BB * NN];
__device__ float g_din0[BB * NN];
__device__ float g_part[256];
__device__ float g_pool[BB * 1024];
__device__ float g_h1  [BB * 512];
__device__ float g_h2  [BB * 128];

// ---------------------------------------------------------------------------
// Generic batched tiled SGEMM, C = f(A op B) with epilogues.
//  BM=BN=64, BK=16, 256 threads, 4x4 microtile per thread.
//  epi: 0 store alpha*acc | 1 C += alpha*acc | 2 exp(2acc - e1[i] - e2[j])
//       3 alpha*e1[i]*acc + beta*e2[i,j]
//       5 e2[i,j] - e1[i]*acc      (reg with diag already zeroed in A)
//  bscale: optional per-k scaling of B (dinv folding).
// ---------------------------------------------------------------------------
#define TBM 64
#define TBN 64
#define TBK 16

__global__ void gemm_kernel(
    const float* __restrict__ A, const float* __restrict__ B, float* __restrict__ C,
    int M, int N, int K, int lda, int ldb, int ldc,
    long long sA, long long sB, long long sC,
    int transA, int transB,
    const float* __restrict__ bscale, long long sBS,
    int epi,
    const float* __restrict__ e1, long long sE1,
    const float* __restrict__ e2, long long sE2,
    float alpha, float beta)
{
    int b = blockIdx.z;
    A += (long long)b * sA;
    B += (long long)b * sB;
    C += (long long)b * sC;
    if (bscale) bscale += (long long)b * sBS;
    if (e1) e1 += (long long)b * sE1;
    if (e2) e2 += (long long)b * sE2;

    __shared__ float As[TBK][TBM];
    __shared__ float Bs[TBK][TBN];

    const int tx = threadIdx.x;       // 0..15
    const int ty = threadIdx.y;       // 0..15
    const int tid = ty * 16 + tx;
    const int m0 = blockIdx.y * TBM;
    const int n0 = blockIdx.x * TBN;

    float acc[4][4];
#pragma unroll
    for (int u = 0; u < 4; u++)
#pragma unroll
        for (int v = 0; v < 4; v++) acc[u][v] = 0.f;

    for (int k0 = 0; k0 < K; k0 += TBK) {
        // --- load A tile into As[k][m] ---
        if (!transA) {
            int kk = tid & 15, i0 = tid >> 4;
#pragma unroll
            for (int r = 0; r < 4; r++) {
                int i = i0 + r * 16;
                int gm = m0 + i, gk = k0 + kk;
                As[kk][i] = (gm < M && gk < K) ? A[(long long)gm * lda + gk] : 0.f;
            }
        } else {
            int i = tid & 63, kk0 = tid >> 6;
#pragma unroll
            for (int r = 0; r < 4; r++) {
                int kk = kk0 + r * 4;
                int gm = m0 + i, gk = k0 + kk;
                As[kk][i] = (gm < M && gk < K) ? A[(long long)gk * lda + gm] : 0.f;
            }
        }
        // --- load B tile into Bs[k][n] (optionally scaled by bscale[k]) ---
        if (!transB) {
            int j = tid & 63, kk0 = tid >> 6;
#pragma unroll
            for (int r = 0; r < 4; r++) {
                int kk = kk0 + r * 4;
                int gn = n0 + j, gk = k0 + kk;
                float v = (gn < N && gk < K) ? B[(long long)gk * ldb + gn] : 0.f;
                if (bscale && gk < K) v *= bscale[gk];
                Bs[kk][j] = v;
            }
        } else {
            int kk = tid & 15, j0 = tid >> 4;
#pragma unroll
            for (int r = 0; r < 4; r++) {
                int j = j0 + r * 16;
                int gn = n0 + j, gk = k0 + kk;
                float v = (gn < N && gk < K) ? B[(long long)gn * ldb + gk] : 0.f;
                if (bscale && gk < K) v *= bscale[gk];
                Bs[kk][j] = v;
            }
        }
        __syncthreads();

#pragma unroll
        for (int kk = 0; kk < TBK; kk++) {
            float a[4], bv[4];
#pragma unroll
            for (int u = 0; u < 4; u++) a[u] = As[kk][ty * 4 + u];
#pragma unroll
            for (int v = 0; v < 4; v++) bv[v] = Bs[kk][tx * 4 + v];
#pragma unroll
            for (int u = 0; u < 4; u++)
#pragma unroll
                for (int v = 0; v < 4; v++) acc[u][v] += a[u] * bv[v];
        }
        __syncthreads();
    }

#pragma unroll
    for (int u = 0; u < 4; u++) {
        int gi = m0 + ty * 4 + u;
        if (gi >= M) continue;
#pragma unroll
        for (int v = 0; v < 4; v++) {
            int gj = n0 + tx * 4 + v;
            if (gj >= N) continue;
            float r = acc[u][v];
            long long idx = (long long)gi * ldc + gj;
            switch (epi) {
                case 0: C[idx] = alpha * r; break;
                case 1: C[idx] += alpha * r; break;
                case 2: C[idx] = expf(2.f * r - e1[gi] - e2[gj]); break;
                case 3: {
                    float t = alpha * e1[gi] * r;
                    if (e2) t += beta * e2[idx];
                    C[idx] = t;
                } break;
                case 5: C[idx] = e2[idx] - e1[gi] * r; break;
            }
        }
    }
}

// ---------------------------------------------------------------------------
// Helper kernels
// ---------------------------------------------------------------------------

// sq[row] = ||p_row||^2, one warp per row
__global__ void sqnorm_kernel(const float* __restrict__ P, float* __restrict__ sq, int C)
{
    int row = blockIdx.x * (blockDim.x / 32) + (threadIdx.x >> 5);
    int lane = threadIdx.x & 31;
    if (row >= BB * NN) return;
    const float* p = P + (long long)row * C;
    float s = 0.f;
    for (int c = lane; c < C; c += 32) { float v = p[c]; s += v * v; }
#pragma unroll
    for (int o = 16; o; o >>= 1) s += __shfl_xor_sync(0xFFFFFFFFu, s, o);
    if (!lane) sq[row] = s;
}

// Full row sum (for cheb dinv) and off-diagonal row sum (for reg dinv0,
// accumulated directly -> no cancellation).
__global__ void degree_kernel(const float* __restrict__ W,
                              float* __restrict__ dinv, float* __restrict__ din0)
{
    long long row = blockIdx.x;
    int col = (int)(row % NN);                 // diagonal column within this graph
    const float* w = W + row * NN;
    float s = 0.f, s0 = 0.f;
    for (int i = threadIdx.x; i < NN; i += 256) {
        float v = w[i];
        s += v;
        if (i != col) s0 += v;
    }
    __shared__ float sh[256], sh0[256];
    sh[threadIdx.x] = s;
    sh0[threadIdx.x] = s0;
    __syncthreads();
    for (int st = 128; st; st >>= 1) {
        if (threadIdx.x < st) {
            sh[threadIdx.x]  += sh[threadIdx.x + st];
            sh0[threadIdx.x] += sh0[threadIdx.x + st];
        }
        __syncthreads();
    }
    if (!threadIdx.x) {
        dinv[row] = rsqrtf(sh[0]);
        din0[row] = rsqrtf(sh0[0]);
    }
}

// W[b,i,i] = 0 (exact diagonal removal before the reg GEMM)
__global__ void zero_diag_kernel(float* __restrict__ W)
{
    int i = blockIdx.x * blockDim.x + threadIdx.x;
    if (i >= BB * NN) return;
    int b = i >> 10, n = i & 1023;
    W[(long long)b * NN * NN + (long long)n * NN + n] = 0.f;
}

__global__ void bias_init_kernel(float* __restrict__ out, const float* __restrict__ bias,
                                 int Cmask, long long total)
{
    long long i = blockIdx.x * (long long)blockDim.x + threadIdx.x;
    if (i < total) out[i] = bias[i & Cmask];
}

__global__ void relu_kernel(float* __restrict__ x, long long n)
{
    long long i = blockIdx.x * (long long)blockDim.x + threadIdx.x;
    if (i < n) x[i] = fmaxf(x[i], 0.f);
}

__global__ void normsq_partial_kernel(const float* __restrict__ Mm, long long n,
                                      float* __restrict__ part)
{
    float s = 0.f;
    for (long long i = blockIdx.x * (long long)blockDim.x + threadIdx.x; i < n;
         i += (long long)gridDim.x * blockDim.x) {
        float v = Mm[i];
        s += v * v;
    }
    __shared__ float sh[256];
    sh[threadIdx.x] = s;
    __syncthreads();
    for (int st = 128; st; st >>= 1) {
        if (threadIdx.x < st) sh[threadIdx.x] += sh[threadIdx.x + st];
        __syncthreads();
    }
    if (!threadIdx.x) part[blockIdx.x] = sh[0];
}

__global__ void normsq_final_kernel(const float* __restrict__ part, float* __restrict__ r)
{
    __shared__ float sh[256];
    sh[threadIdx.x] = part[threadIdx.x];
    __syncthreads();
    for (int st = 128; st; st >>= 1) {
        if (threadIdx.x < st) sh[threadIdx.x] += sh[threadIdx.x + st];
        __syncthreads();
    }
    if (!threadIdx.x) *r = sqrtf(sh[0]);
}

// pooled[b,c] = max_n out3[b,n,c]
__global__ void maxpool_kernel(const float* __restrict__ o3, float* __restrict__ pooled)
{
    int c = blockIdx.x * blockDim.x + threadIdx.x;
    int b = blockIdx.y;
    if (c >= 1024) return;
    const float* p = o3 + (long long)b * 1024 * 1024 + c;
    float m = p[0];
    for (int n = 1; n < 1024; n++) m = fmaxf(m, p[(long long)n * 1024]);
    pooled[b * 1024 + c] = m;
}

// out[b,j] = act(sum_k in[b,k]*w[k,j] + bias[j])
__global__ void fc_kernel(const float* __restrict__ in, const float* __restrict__ w,
                          const float* __restrict__ bias, float* __restrict__ out,
                          int K, int Nout, int do_relu)
{
    int j = blockIdx.x * blockDim.x + threadIdx.x;
    int b = blockIdx.y;
    if (j >= Nout) return;
    float s = bias[j];
    const float* ip = in + (long long)b * K;
    for (int k = 0; k < K; k++) s += ip[k] * w[(long long)k * Nout + j];
    if (do_relu) s = fmaxf(s, 0.f);
    out[(long long)b * Nout + j] = s;
}

// ---------------------------------------------------------------------------
// Host orchestration
// ---------------------------------------------------------------------------
static void launch_gemm(const float* A, const float* B, float* C,
                        int M, int N, int K, int lda, int ldb, int ldc,
                        long long sA, long long sB, long long sC,
                        int tA, int tB,
                        const float* bs, long long sBS,
                        int epi, const float* e1, long long sE1,
                        const float* e2, long long sE2,
                        float alpha, float beta, int batch)
{
    dim3 grid((N + TBN - 1) / TBN, (M + TBM - 1) / TBM, batch);
    dim3 thr(16, 16);
    gemm_kernel<<<grid, thr>>>(A, B, C, M, N, K, lda, ldb, ldc, sA, sB, sC,
                               tA, tB, bs, sBS, epi, e1, sE1, e2, sE2,
                               alpha, beta);
}

struct Bufs {
    float *W, *T, *Za, *Zb, *Zc, *Mm, *sq, *dinv, *din0, *part;
};

static void run_layer(const float* X, int Cin, int Cout, int Kcheb,
                      const float* Wk, const float* bias,
                      float* OUT, float* r_out, const Bufs& bf)
{
    const long long sX = (long long)NN * Cin;
    const long long sO = (long long)NN * Cout;
    const long long sW = (long long)NN * NN;

    // 1) squared norms of rows of X
    sqnorm_kernel<<<(BB * NN) / 8, 256>>>(X, bf.sq, Cin);

    // 2) W = exp(-pairwise sq dist) = exp(2*X@X^T - sq_i - sq_j)
    launch_gemm(X, X, bf.W, NN, NN, Cin, Cin, Cin, NN, sX, sX, sW,
                0, 1, nullptr, 0, 2, bf.sq, NN, bf.sq, NN, 1.f, 0.f, BB);

    // 3) degrees (full sum + off-diag sum)
    degree_kernel<<<BB * NN, 256>>>(bf.W, bf.dinv, bf.din0);

    // 4) OUT = bias
    {
        long long tot = (long long)BB * NN * Cout;
        bias_init_kernel<<<(unsigned)((tot + 255) / 256), 256>>>(OUT, bias, Cout - 1, tot);
    }

    // 5) OUT += Z0 @ Wk[0]   (Z0 = X)
    launch_gemm(X, Wk, OUT, NN, Cout, Cin, Cin, Cout, Cout, sX, 0, sO,
                0, 0, nullptr, 0, 1, nullptr, 0, nullptr, 0, 1.f, 0.f, BB);

    if (Kcheb > 1) {
        // Z1 = Lhat @ X = -dinv_i * (W @ (dinv .* X))  -> Za
        launch_gemm(bf.W, X, bf.Za, NN, Cin, NN, NN, Cin, Cin, sW, sX, sX,
                    0, 0, bf.dinv, NN, 3, bf.dinv, NN, nullptr, 0,
                    -1.f, 0.f, BB);
        launch_gemm(bf.Za, Wk + (long long)1 * Cin * Cout, OUT, NN, Cout, Cin,
                    Cin, Cout, Cout, sX, 0, sO,
                    0, 0, nullptr, 0, 1, nullptr, 0, nullptr, 0,
                    1.f, 0.f, BB);

        const float* z0 = X;
        const float* z1 = bf.Za;
        float* rot[3] = { bf.Zb, bf.Zc, bf.Za };
        for (int k = 2; k < Kcheb; k++) {
            float* zn = rot[(k - 2) % 3];
            // Zk = 2*Lhat@Z1 - Z0 = -2*dinv_i*(W@(dinv.*Z1)) - Z0
            launch_gemm(bf.W, z1, zn, NN, Cin, NN, NN, Cin, Cin, sW, sX, sX,
                        0, 0, bf.dinv, NN, 3, bf.dinv, NN, z0, sX,
                        -2.f, -1.f, BB);
            launch_gemm(zn, Wk + (long long)k * Cin * Cout, OUT, NN, Cout, Cin,
                        Cin, Cout, Cout, sX, 0, sO,
                        0, 0, nullptr, 0, 1, nullptr, 0, nullptr, 0,
                        1.f, 0.f, BB);
            z0 = z1;
            z1 = zn;
        }
    }

    // 6) relu
    {
        long long tot = (long long)BB * sO;
        relu_kernel<<<(unsigned)((tot + 255) / 256), 256>>>(OUT, tot);
    }

    // 7) reg: zero W diagonal exactly, then T = out - d0 .* (W0 @ (d0 .* out))
    //    (diagonal never enters the accumulator -> no cancellation)
    zero_diag_kernel<<<(BB * NN + 255) / 256, 256>>>(bf.W);
    launch_gemm(bf.W, OUT, bf.T, NN, Cout, NN, NN, Cout, Cout, sW, sO, sO,
                0, 0, bf.din0, NN, 5, bf.din0, NN, OUT, sO,
                1.f, 0.f, BB);

    // 8) M = sum_b out_b^T @ T_b  (single GEMM, K = B*N)
    launch_gemm(OUT, bf.T, bf.Mm, Cout, Cout, BB * NN, Cout, Cout, Cout,
                0, 0, 0, 1, 0, nullptr, 0, 0, nullptr, 0, nullptr, 0,
                1.f, 0.f, 1);

    // 9) r = ||M||_F (deterministic two-stage reduction)
    normsq_partial_kernel<<<256, 256>>>(bf.Mm, (long long)Cout * Cout, bf.part);
    normsq_final_kernel<<<1, 256>>>(bf.part, r_out);
}

extern "C" void kernel_launch(void* const* d_in, const int* in_sizes, int n_in,
                              void* d_out, int out_size)
{
    (void)in_sizes; (void)out_size;
    const float* x = (const float*)d_in[0];
    int base = n_in - 12;   // 12 weight tensors are always the last inputs
    const float* w1  = (const float*)d_in[base + 0];
    const float* b1  = (const float*)d_in[base + 1];
    const float* w2  = (const float*)d_in[base + 2];
    const float* b2  = (const float*)d_in[base + 3];
    const float* w3  = (const float*)d_in[base + 4];
    const float* b3  = (const float*)d_in[base + 5];
    const float* fw1 = (const float*)d_in[base + 6];
    const float* fb1 = (const float*)d_in[base + 7];
    const float* fw2 = (const float*)d_in[base + 8];
    const float* fb2 = (const float*)d_in[base + 9];
    const float* fw3 = (const float*)d_in[base + 10];
    const float* fb3 = (const float*)d_in[base + 11];
    float* out = (float*)d_out;

    Bufs bf;
    float *o1, *o2, *o3, *pool, *h1, *h2;
    cudaGetSymbolAddress((void**)&bf.W,    g_W);
    cudaGetSymbolAddress((void**)&bf.T,    g_T);
    cudaGetSymbolAddress((void**)&bf.Za,   g_Za);
    cudaGetSymbolAddress((void**)&bf.Zb,   g_Zb);
    cudaGetSymbolAddress((void**)&bf.Zc,   g_Zc);
    cudaGetSymbolAddress((void**)&bf.Mm,   g_M);
    cudaGetSymbolAddress((void**)&bf.sq,   g_sq);
    cudaGetSymbolAddress((void**)&bf.dinv, g_dinv);
    cudaGetSymbolAddress((void**)&bf.din0, g_din0);
    cudaGetSymbolAddress((void**)&bf.part, g_part);
    cudaGetSymbolAddress((void**)&o1,      g_out1);
    cudaGetSymbolAddress((void**)&o2,      g_out2);
    cudaGetSymbolAddress((void**)&o3,      g_out3);
    cudaGetSymbolAddress((void**)&pool,    g_pool);
    cudaGetSymbolAddress((void**)&h1,      g_h1);
    cudaGetSymbolAddress((void**)&h2,      g_h2);

    // Three ChebConv layers (each writes its regularizer scalar)
    run_layer(x,  6,   128,  6, w1, b1, o1, out + 160, bf);
    run_layer(o1, 128, 512,  5, w2, b2, o2, out + 161, bf);
    run_layer(o2, 512, 1024, 3, w3, b3, o3, out + 162, bf);

    // MaxPool over points
    {
        dim3 g(1024 / 256, BB);
        maxpool_kernel<<<g, 256>>>(o3, pool);
    }
    // FC head
    {
        dim3 g1((512 + 127) / 128, BB);
        fc_kernel<<<g1, 128>>>(pool, fw1, fb1, h1, 1024, 512, 1);
        dim3 g2(1, BB);
        fc_kernel<<<g2, 128>>>(h1, fw2, fb2, h2, 512, 128, 1);
        fc_kernel<<<g2, 128>>>(h2, fw3, fb3, out, 128, 10, 0);
    }
}

// round 5
// speedup vs baseline: 2.0295x; 2.0295x over previous
#include <cuda_runtime.h>
#include <math.h>

// ---------------------------------------------------------------------------
// B=16 graphs, N=1024 points.
//   Layer1: Cin=6,   Cout=128,  K=6
//   Layer2: Cin=128, Cout=512,  K=5
//   Layer3: Cin=512, Cout=1024, K=3
// Output: logits [16,10] -> 160 floats, then r1, r2, r3 -> 163 floats.
// ---------------------------------------------------------------------------

#define BB 16
#define NN 1024
#define KCMAX 1536   // max Kcheb*Cin (layer3: 3*512)

// Scratch (device globals; no allocation allowed)
__device__ float g_W   [BB * NN * NN];        // adjacency / M partials (reused)
__device__ float g_T   [BB * NN * 1024];      // reg L@out
__device__ float g_out1[BB * NN * 128];
__device__ float g_out2[BB * NN * 512];
__device__ float g_out3[BB * NN * 1024];
__device__ float g_Zall[BB * NN * KCMAX];     // interleaved Chebyshev basis
__device__ float g_sq  [BB * NN];
__device__ float g_dinv[BB * NN];
__device__ float g_din0[BB * NN];
__device__ float g_part[256];
__device__ float g_pool[BB * 1024];
__device__ float g_h1  [BB * 512];
__device__ float g_h2  [BB * 128];

// ---------------------------------------------------------------------------
// FAST SGEMM: BM=128, BN in {128,64}, BK=16, 256 threads, 8xTN microtile.
// No bounds checks: requires M%128==0, N%BN==0, K%16==0, lda/ldb/ldc%4==0,
// and 16B-aligned base pointers (all call sites guarantee this).
//  EPI: 0 C=alpha*acc | 1 C+=alpha*acc | 2 C=exp(2acc-e1[i]-e2[j])
//       3 C=alpha*e1[i]*acc (+beta*e2[i,j] if e2) | 5 C=e2[i,j]-e1[i]*acc
//  TRA: A is [K,M] (ldA over k rows). TRB: B is [N,K]. BSC: scale B rows by bscale[k].
//  split-K: z -> b = z>>splitLog, ch = z & mask; per-chunk K elements.
// ---------------------------------------------------------------------------
template<int BN, int TN, int EPI, int TRA, int TRB, int BSC>
__global__ __launch_bounds__(256)
void fgemm_kernel(const float* __restrict__ A, const float* __restrict__ B,
                  float* __restrict__ C, int K, int lda, int ldb, int ldc,
                  long long sA, long long sB, long long sC,
                  const float* __restrict__ bscale, long long sBS,
                  const float* __restrict__ e1, long long sE1,
                  const float* __restrict__ e2, long long sE2,
                  float alpha, float beta, int splitLog)
{
    const int z = blockIdx.z;
    const int b = z >> splitLog;
    const int ch = z - (b << splitLog);

    A += (long long)b * sA + (TRA ? (long long)ch * K * lda : (long long)ch * K);
    B += (long long)b * sB + (TRB ? (long long)ch * K : (long long)ch * K * ldb);
    C += (long long)z * sC;
    if (BSC) bscale += (long long)b * sBS + (long long)ch * K;
    if (e1) e1 += (long long)b * sE1;
    if (e2) e2 += (long long)b * sE2;

    __shared__ float As[16][128 + 4];
    __shared__ float Bs[16][BN + 4];

    const int tid = threadIdx.x;
    const int m0 = blockIdx.y * 128;
    const int n0 = blockIdx.x * BN;
    const int tm = (tid >> 4) * 8;
    const int tn = (tid & 15) * TN;

    float acc[8][TN];
#pragma unroll
    for (int u = 0; u < 8; u++)
#pragma unroll
        for (int v = 0; v < TN; v++) acc[u][v] = 0.f;

    for (int k0 = 0; k0 < K; k0 += 16) {
        // ---- A tile -> As[k][m] ----
        if (TRA == 0) {
            const int arow = tid >> 2, ac4 = tid & 3;
#pragma unroll
            for (int r = 0; r < 2; r++) {
                int row = arow + r * 64;
                float4 v = *(const float4*)(A + (long long)(m0 + row) * lda + k0 + ac4 * 4);
                As[ac4 * 4 + 0][row] = v.x;
                As[ac4 * 4 + 1][row] = v.y;
                As[ac4 * 4 + 2][row] = v.z;
                As[ac4 * 4 + 3][row] = v.w;
            }
        } else {
            const int akk = tid >> 5, am4 = tid & 31;
#pragma unroll
            for (int r = 0; r < 2; r++) {
                int kk = akk + r * 8;
                float4 v = *(const float4*)(A + (long long)(k0 + kk) * lda + m0 + am4 * 4);
                *(float4*)&As[kk][am4 * 4] = v;
            }
        }
        // ---- B tile -> Bs[k][n] ----
        if (TRB == 0) {
            if (BN == 128) {
                const int bkk = tid >> 5, bn4 = tid & 31;
#pragma unroll
                for (int r = 0; r < 2; r++) {
                    int kk = bkk + r * 8;
                    float4 v = *(const float4*)(B + (long long)(k0 + kk) * ldb + n0 + bn4 * 4);
                    if (BSC) {
                        float s = bscale[k0 + kk];
                        v.x *= s; v.y *= s; v.z *= s; v.w *= s;
                    }
                    *(float4*)&Bs[kk][bn4 * 4] = v;
                }
            } else {  // BN == 64
                const int bkk = tid >> 4, bn4 = tid & 15;
                float4 v = *(const float4*)(B + (long long)(k0 + bkk) * ldb + n0 + bn4 * 4);
                if (BSC) {
                    float s = bscale[k0 + bkk];
                    v.x *= s; v.y *= s; v.z *= s; v.w *= s;
                }
                *(float4*)&Bs[bkk][bn4 * 4] = v;
            }
        } else {  // TRB: B[n,k]  (only instantiated with BN==128, no BSC)
            const int brow = tid >> 2, bc4 = tid & 3;
#pragma unroll
            for (int r = 0; r < 2; r++) {
                int n = brow + r * 64;
                float4 v = *(const float4*)(B + (long long)(n0 + n) * ldb + k0 + bc4 * 4);
                Bs[bc4 * 4 + 0][n] = v.x;
                Bs[bc4 * 4 + 1][n] = v.y;
                Bs[bc4 * 4 + 2][n] = v.z;
                Bs[bc4 * 4 + 3][n] = v.w;
            }
        }
        __syncthreads();

#pragma unroll
        for (int kk = 0; kk < 16; kk++) {
            float a[8], bv[TN];
            *(float4*)&a[0] = *(const float4*)&As[kk][tm];
            *(float4*)&a[4] = *(const float4*)&As[kk][tm + 4];
            *(float4*)&bv[0] = *(const float4*)&Bs[kk][tn];
            if (TN == 8) *(float4*)&bv[4] = *(const float4*)&Bs[kk][tn + 4];
#pragma unroll
            for (int u = 0; u < 8; u++)
#pragma unroll
                for (int v = 0; v < TN; v++) acc[u][v] += a[u] * bv[v];
        }
        __syncthreads();
    }

#pragma unroll
    for (int u = 0; u < 8; u++) {
        int gi = m0 + tm + u;
#pragma unroll
        for (int v = 0; v < TN; v++) {
            int gj = n0 + tn + v;
            float r = acc[u][v];
            long long idx = (long long)gi * ldc + gj;
            if (EPI == 0) C[idx] = alpha * r;
            else if (EPI == 1) C[idx] += alpha * r;
            else if (EPI == 2) C[idx] = expf(2.f * r - e1[gi] - e2[gj]);
            else if (EPI == 3) {
                float t = alpha * e1[gi] * r;
                if (e2) t += beta * e2[idx];
                C[idx] = t;
            } else if (EPI == 5) C[idx] = e2[idx] - e1[gi] * r;
        }
    }
}

// ---------------------------------------------------------------------------
// Generic fallback SGEMM (bounds-checked), used for layer-1 small dims.
// ---------------------------------------------------------------------------
#define TBM 64
#define TBN 64
#define TBK 16

__global__ void gemm_kernel(
    const float* __restrict__ A, const float* __restrict__ B, float* __restrict__ C,
    int M, int N, int K, int lda, int ldb, int ldc,
    long long sA, long long sB, long long sC,
    int transA, int transB,
    const float* __restrict__ bscale, long long sBS,
    int epi,
    const float* __restrict__ e1, long long sE1,
    const float* __restrict__ e2, long long sE2,
    float alpha, float beta)
{
    int b = blockIdx.z;
    A += (long long)b * sA;
    B += (long long)b * sB;
    C += (long long)b * sC;
    if (bscale) bscale += (long long)b * sBS;
    if (e1) e1 += (long long)b * sE1;
    if (e2) e2 += (long long)b * sE2;

    __shared__ float As[TBK][TBM];
    __shared__ float Bs[TBK][TBN];

    const int tx = threadIdx.x, ty = threadIdx.y;
    const int tid = ty * 16 + tx;
    const int m0 = blockIdx.y * TBM;
    const int n0 = blockIdx.x * TBN;

    float acc[4][4];
#pragma unroll
    for (int u = 0; u < 4; u++)
#pragma unroll
        for (int v = 0; v < 4; v++) acc[u][v] = 0.f;

    for (int k0 = 0; k0 < K; k0 += TBK) {
        if (!transA) {
            int kk = tid & 15, i0 = tid >> 4;
#pragma unroll
            for (int r = 0; r < 4; r++) {
                int i = i0 + r * 16;
                int gm = m0 + i, gk = k0 + kk;
                As[kk][i] = (gm < M && gk < K) ? A[(long long)gm * lda + gk] : 0.f;
            }
        } else {
            int i = tid & 63, kk0 = tid >> 6;
#pragma unroll
            for (int r = 0; r < 4; r++) {
                int kk = kk0 + r * 4;
                int gm = m0 + i, gk = k0 + kk;
                As[kk][i] = (gm < M && gk < K) ? A[(long long)gk * lda + gm] : 0.f;
            }
        }
        if (!transB) {
            int j = tid & 63, kk0 = tid >> 6;
#pragma unroll
            for (int r = 0; r < 4; r++) {
                int kk = kk0 + r * 4;
                int gn = n0 + j, gk = k0 + kk;
                float v = (gn < N && gk < K) ? B[(long long)gk * ldb + gn] : 0.f;
                if (bscale && gk < K) v *= bscale[gk];
                Bs[kk][j] = v;
            }
        } else {
            int kk = tid & 15, j0 = tid >> 4;
#pragma unroll
            for (int r = 0; r < 4; r++) {
                int j = j0 + r * 16;
                int gn = n0 + j, gk = k0 + kk;
                float v = (gn < N && gk < K) ? B[(long long)gn * ldb + gk] : 0.f;
                if (bscale && gk < K) v *= bscale[gk];
                Bs[kk][j] = v;
            }
        }
        __syncthreads();

#pragma unroll
        for (int kk = 0; kk < TBK; kk++) {
            float a[4], bv[4];
#pragma unroll
            for (int u = 0; u < 4; u++) a[u] = As[kk][ty * 4 + u];
#pragma unroll
            for (int v = 0; v < 4; v++) bv[v] = Bs[kk][tx * 4 + v];
#pragma unroll
            for (int u = 0; u < 4; u++)
#pragma unroll
                for (int v = 0; v < 4; v++) acc[u][v] += a[u] * bv[v];
        }
        __syncthreads();
    }

#pragma unroll
    for (int u = 0; u < 4; u++) {
        int gi = m0 + ty * 4 + u;
        if (gi >= M) continue;
#pragma unroll
        for (int v = 0; v < 4; v++) {
            int gj = n0 + tx * 4 + v;
            if (gj >= N) continue;
            float r = acc[u][v];
            long long idx = (long long)gi * ldc + gj;
            switch (epi) {
                case 0: C[idx] = alpha * r; break;
                case 1: C[idx] += alpha * r; break;
                case 2: C[idx] = expf(2.f * r - e1[gi] - e2[gj]); break;
                case 3: {
                    float t = alpha * e1[gi] * r;
                    if (e2) t += beta * e2[idx];
                    C[idx] = t;
                } break;
                case 5: C[idx] = e2[idx] - e1[gi] * r; break;
            }
        }
    }
}

// ---------------------------------------------------------------------------
// Helper kernels
// ---------------------------------------------------------------------------
__global__ void sqnorm_kernel(const float* __restrict__ P, float* __restrict__ sq, int C)
{
    int row = blockIdx.x * (blockDim.x / 32) + (threadIdx.x >> 5);
    int lane = threadIdx.x & 31;
    if (row >= BB * NN) return;
    const float* p = P + (long long)row * C;
    float s = 0.f;
    for (int c = lane; c < C; c += 32) { float v = p[c]; s += v * v; }
#pragma unroll
    for (int o = 16; o; o >>= 1) s += __shfl_xor_sync(0xFFFFFFFFu, s, o);
    if (!lane) sq[row] = s;
}

__global__ void degree_kernel(const float* __restrict__ W,
                              float* __restrict__ dinv, float* __restrict__ din0)
{
    long long row = blockIdx.x;
    int col = (int)(row % NN);
    const float* w = W + row * NN;
    float s = 0.f, s0 = 0.f;
    for (int i = threadIdx.x; i < NN; i += 256) {
        float v = w[i];
        s += v;
        if (i != col) s0 += v;
    }
    __shared__ float sh[256], sh0[256];
    sh[threadIdx.x] = s;
    sh0[threadIdx.x] = s0;
    __syncthreads();
    for (int st = 128; st; st >>= 1) {
        if (threadIdx.x < st) {
            sh[threadIdx.x]  += sh[threadIdx.x + st];
            sh0[threadIdx.x] += sh0[threadIdx.x + st];
        }
        __syncthreads();
    }
    if (!threadIdx.x) {
        dinv[row] = rsqrtf(sh[0]);
        din0[row] = rsqrtf(sh0[0]);
    }
}

__global__ void zero_diag_kernel(float* __restrict__ W)
{
    int i = blockIdx.x * blockDim.x + threadIdx.x;
    if (i >= BB * NN) return;
    int b = i >> 10, n = i & 1023;
    W[(long long)b * NN * NN + (long long)n * NN + n] = 0.f;
}

// dst[row, 0:C] (row stride KC) = src[row, 0:C] (contiguous)
__global__ void copy_slice_kernel(const float* __restrict__ src, float* __restrict__ dst,
                                  int C, int KC, long long total)
{
    long long i = blockIdx.x * (long long)blockDim.x + threadIdx.x;
    if (i < total) {
        long long row = i / C;
        int c = (int)(i - row * C);
        dst[row * KC + c] = src[i];
    }
}

__global__ void bias_init_kernel(float* __restrict__ out, const float* __restrict__ bias,
                                 int Cmask, long long total)
{
    long long i = blockIdx.x * (long long)blockDim.x + threadIdx.x;
    if (i < total) out[i] = bias[i & Cmask];
}

__global__ void relu_kernel(float* __restrict__ x, long long n)
{
    long long i = blockIdx.x * (long long)blockDim.x + threadIdx.x;
    if (i < n) x[i] = fmaxf(x[i], 0.f);
}

// sum slices, then Frobenius partial
__global__ void normsq_partial_kernel(const float* __restrict__ P, long long elems,
                                      int nsl, float* __restrict__ part)
{
    float s = 0.f;
    for (long long i = blockIdx.x * (long long)blockDim.x + threadIdx.x; i < elems;
         i += (long long)gridDim.x * blockDim.x) {
        float t = 0.f;
        for (int z = 0; z < nsl; z++) t += P[(long long)z * elems + i];
        s += t * t;
    }
    __shared__ float sh[256];
    sh[threadIdx.x] = s;
    __syncthreads();
    for (int st = 128; st; st >>= 1) {
        if (threadIdx.x < st) sh[threadIdx.x] += sh[threadIdx.x + st];
        __syncthreads();
    }
    if (!threadIdx.x) part[blockIdx.x] = sh[0];
}

__global__ void normsq_final_kernel(const float* __restrict__ part, float* __restrict__ r)
{
    __shared__ float sh[256];
    sh[threadIdx.x] = part[threadIdx.x];
    __syncthreads();
    for (int st = 128; st; st >>= 1) {
        if (threadIdx.x < st) sh[threadIdx.x] += sh[threadIdx.x + st];
        __syncthreads();
    }
    if (!threadIdx.x) *r = sqrtf(sh[0]);
}

__global__ void maxpool_kernel(const float* __restrict__ o3, float* __restrict__ pooled)
{
    int c = blockIdx.x * blockDim.x + threadIdx.x;
    int b = blockIdx.y;
    if (c >= 1024) return;
    const float* p = o3 + (long long)b * 1024 * 1024 + c;
    float m = p[0];
    for (int n = 1; n < 1024; n++) m = fmaxf(m, p[(long long)n * 1024]);
    pooled[b * 1024 + c] = m;
}

__global__ void fc_kernel(const float* __restrict__ in, const float* __restrict__ w,
                          const float* __restrict__ bias, float* __restrict__ out,
                          int K, int Nout, int do_relu)
{
    int j = blockIdx.x * blockDim.x + threadIdx.x;
    int b = blockIdx.y;
    if (j >= Nout) return;
    float s = bias[j];
    const float* ip = in + (long long)b * K;
    for (int k = 0; k < K; k++) s += ip[k] * w[(long long)k * Nout + j];
    if (do_relu) s = fmaxf(s, 0.f);
    out[(long long)b * Nout + j] = s;
}

// ---------------------------------------------------------------------------
// Host orchestration
// ---------------------------------------------------------------------------
static void launch_generic(const float* A, const float* B, float* C,
                           int M, int N, int K, int lda, int ldb, int ldc,
                           long long sA, long long sB, long long sC,
                           int tA, int tB,
                           const float* bs, long long sBS,
                           int epi, const float* e1, long long sE1,
                           const float* e2, long long sE2,
                           float alpha, float beta, int batch)
{
    dim3 grid((N + TBN - 1) / TBN, (M + TBM - 1) / TBM, batch);
    dim3 thr(16, 16);
    gemm_kernel<<<grid, thr>>>(A, B, C, M, N, K, lda, ldb, ldc, sA, sB, sC,
                               tA, tB, bs, sBS, epi, e1, sE1, e2, sE2, alpha, beta);
}

struct Bufs {
    float *W, *T, *Zall, *sq, *dinv, *din0, *part;
};

static void run_layer(const float* X, int Cin, int Cout, int Kcheb,
                      const float* Wk, const float* bias,
                      float* OUT, float* r_out, const Bufs& bf)
{
    const int KC = Kcheb * Cin;
    const long long sX = (long long)NN * Cin;
    const long long sZ = (long long)NN * KC;
    const long long sO = (long long)NN * Cout;
    const long long sW = (long long)NN * NN;

    // 1) squared norms
    sqnorm_kernel<<<(BB * NN) / 8, 256>>>(X, bf.sq, Cin);

    // 2) W = exp(2*X@X^T - sq_i - sq_j)
    if (Cin % 16 == 0) {
        dim3 g(NN / 128, NN / 128, BB);
        fgemm_kernel<128, 8, 2, 0, 1, 0><<<g, 256>>>(
            X, X, bf.W, Cin, Cin, Cin, NN, sX, sX, sW,
            nullptr, 0, bf.sq, NN, bf.sq, NN, 1.f, 0.f, 0);
    } else {
        launch_generic(X, X, bf.W, NN, NN, Cin, Cin, Cin, NN, sX, sX, sW,
                       0, 1, nullptr, 0, 2, bf.sq, NN, bf.sq, NN, 1.f, 0.f, BB);
    }

    // 3) degrees
    degree_kernel<<<BB * NN, 256>>>(bf.W, bf.dinv, bf.din0);

    // 4) Zall slice 0 = X
    copy_slice_kernel<<<(unsigned)(((long long)BB * NN * Cin + 255) / 256), 256>>>(
        X, bf.Zall, Cin, KC, (long long)BB * NN * Cin);

    // 5) Chebyshev recursion into Zall slices 1..Kcheb-1
    for (int k = 1; k < Kcheb; k++) {
        float* Ck = bf.Zall + (long long)k * Cin;
        const float* Bk = bf.Zall + (long long)(k - 1) * Cin;
        const float* Ek = (k >= 2) ? (bf.Zall + (long long)(k - 2) * Cin) : nullptr;
        float alpha = (k == 1) ? -1.f : -2.f;
        if (Cin == 128) {
            dim3 g(Cin / 64, NN / 128, BB);
            fgemm_kernel<64, 4, 3, 0, 0, 1><<<g, 256>>>(
                bf.W, Bk, Ck, NN, NN, KC, KC, sW, sZ, sZ,
                bf.dinv, NN, bf.dinv, NN, Ek, sZ, alpha, -1.f, 0);
        } else if (Cin % 128 == 0) {
            dim3 g(Cin / 128, NN / 128, BB);
            fgemm_kernel<128, 8, 3, 0, 0, 1><<<g, 256>>>(
                bf.W, Bk, Ck, NN, NN, KC, KC, sW, sZ, sZ,
                bf.dinv, NN, bf.dinv, NN, Ek, sZ, alpha, -1.f, 0);
        } else {
            launch_generic(bf.W, Bk, Ck, NN, Cin, NN, NN, KC, KC, sW, sZ, sZ,
                           0, 0, bf.dinv, NN, 3, bf.dinv, NN, Ek, sZ,
                           alpha, -1.f, BB);
        }
    }

    // 6) OUT = bias, then OUT += Zall @ Wk_flat (one fused combine GEMM)
    {
        long long tot = (long long)BB * NN * Cout;
        bias_init_kernel<<<(unsigned)((tot + 255) / 256), 256>>>(OUT, bias, Cout - 1, tot);
    }
    if (KC % 16 == 0 && Cout % 128 == 0) {
        dim3 g(Cout / 128, NN / 128, BB);
        fgemm_kernel<128, 8, 1, 0, 0, 0><<<g, 256>>>(
            bf.Zall, Wk, OUT, KC, KC, Cout, Cout, sZ, 0, sO,
            nullptr, 0, nullptr, 0, nullptr, 0, 1.f, 0.f, 0);
    } else {
        launch_generic(bf.Zall, Wk, OUT, NN, Cout, KC, KC, Cout, Cout, sZ, 0, sO,
                       0, 0, nullptr, 0, 1, nullptr, 0, nullptr, 0, 1.f, 0.f, BB);
    }

    // 7) relu
    {
        long long tot = (long long)BB * sO;
        relu_kernel<<<(unsigned)((tot + 255) / 256), 256>>>(OUT, tot);
    }

    // 8) reg: zero diag, T = out - d0 .* (W0 @ (d0 .* out))
    zero_diag_kernel<<<(BB * NN + 255) / 256, 256>>>(bf.W);
    {
        dim3 g(Cout / 128, NN / 128, BB);
        fgemm_kernel<128, 8, 5, 0, 0, 1><<<g, 256>>>(
            bf.W, OUT, bf.T, NN, NN, Cout, Cout, sW, sO, sO,
            bf.din0, NN, bf.din0, NN, OUT, sO, 1.f, 0.f, 0);
    }

    // 9) M partials: per (batch, K-chunk) slice of out^T @ T into g_W (dead now)
    int splitLog = (Cout == 128) ? 3 : (Cout == 512) ? 1 : 0;
    int chunkK = NN >> splitLog;
    int nsl = BB << splitLog;
    {
        dim3 g(Cout / 128, Cout / 128, nsl);
        fgemm_kernel<128, 8, 0, 1, 0, 0><<<g, 256>>>(
            OUT, bf.T, bf.W, chunkK, Cout, Cout, Cout,
            sO, sO, (long long)Cout * Cout,
            nullptr, 0, nullptr, 0, nullptr, 0, 1.f, 0.f, splitLog);
    }

    // 10) r = ||sum_z M_z||_F
    normsq_partial_kernel<<<256, 256>>>(bf.W, (long long)Cout * Cout, nsl, bf.part);
    normsq_final_kernel<<<1, 256>>>(bf.part, r_out);
}

extern "C" void kernel_launch(void* const* d_in, const int* in_sizes, int n_in,
                              void* d_out, int out_size)
{
    (void)in_sizes; (void)out_size;
    const float* x = (const float*)d_in[0];
    int base = n_in - 12;
    const float* w1  = (const float*)d_in[base + 0];
    const float* b1  = (const float*)d_in[base + 1];
    const float* w2  = (const float*)d_in[base + 2];
    const float* b2  = (const float*)d_in[base + 3];
    const float* w3  = (const float*)d_in[base + 4];
    const float* b3  = (const float*)d_in[base + 5];
    const float* fw1 = (const float*)d_in[base + 6];
    const float* fb1 = (const float*)d_in[base + 7];
    const float* fw2 = (const float*)d_in[base + 8];
    const float* fb2 = (const float*)d_in[base + 9];
    const float* fw3 = (const float*)d_in[base + 10];
    const float* fb3 = (const float*)d_in[base + 11];
    float* out = (float*)d_out;

    Bufs bf;
    float *o1, *o2, *o3, *pool, *h1, *h2;
    cudaGetSymbolAddress((void**)&bf.W,    g_W);
    cudaGetSymbolAddress((void**)&bf.T,    g_T);
    cudaGetSymbolAddress((void**)&bf.Zall, g_Zall);
    cudaGetSymbolAddress((void**)&bf.sq,   g_sq);
    cudaGetSymbolAddress((void**)&bf.dinv, g_dinv);
    cudaGetSymbolAddress((void**)&bf.din0, g_din0);
    cudaGetSymbolAddress((void**)&bf.part, g_part);
    cudaGetSymbolAddress((void**)&o1,      g_out1);
    cudaGetSymbolAddress((void**)&o2,      g_out2);
    cudaGetSymbolAddress((void**)&o3,      g_out3);
    cudaGetSymbolAddress((void**)&pool,    g_pool);
    cudaGetSymbolAddress((void**)&h1,      g_h1);
    cudaGetSymbolAddress((void**)&h2,      g_h2);

    run_layer(x,  6,   128,  6, w1, b1, o1, out + 160, bf);
    run_layer(o1, 128, 512,  5, w2, b2, o2, out + 161, bf);
    run_layer(o2, 512, 1024, 3, w3, b3, o3, out + 162, bf);

    {
        dim3 g(1024 / 256, BB);
        maxpool_kernel<<<g, 256>>>(o3, pool);
    }
    {
        dim3 g1((512 + 127) / 128, BB);
        fc_kernel<<<g1, 128>>>(pool, fw1, fb1, h1, 1024, 512, 1);
        dim3 g2(1, BB);
        fc_kernel<<<g2, 128>>>(h1, fw2, fb2, h2, 512, 128, 1);
        fc_kernel<<<g2, 128>>>(h2, fw3, fb3, out, 128, 10, 0);
    }
}

// round 7
// speedup vs baseline: 2.2086x; 1.0882x over previous
#include <cuda_runtime.h>
#include <math.h>

// ---------------------------------------------------------------------------
// B=16 graphs, N=1024 points.
//   Layer1: Cin=6,   Cout=128,  K=6
//   Layer2: Cin=128, Cout=512,  K=5
//   Layer3: Cin=512, Cout=1024, K=3
// Output: logits [16,10] -> 160 floats, then r1, r2, r3 -> 163 floats.
// ---------------------------------------------------------------------------

#define BB 16
#define NN 1024
#define KCMAX 1536   // max Kcheb*Cin (layer3: 3*512)

// Scratch (device globals; no allocation allowed)
__device__ float g_W   [BB * NN * NN];        // adjacency / M partials (reused)
__device__ float g_T   [BB * NN * 1024];      // reg L@out
__device__ float g_out1[BB * NN * 128];
__device__ float g_out2[BB * NN * 512];
__device__ float g_out3[BB * NN * 1024];
__device__ float g_Zall[BB * NN * KCMAX];     // interleaved Chebyshev basis
__device__ float g_sq  [BB * NN];
__device__ float g_dinv[BB * NN];
__device__ float g_din0[BB * NN];
__device__ float g_part[256];
__device__ float g_pool[BB * 1024];
__device__ float g_h1  [BB * 512];
__device__ float g_h2  [BB * 128];

// ---------------------------------------------------------------------------
// FAST SGEMM, double-buffered: BM=128, BN in {128,64}, BK=16, 256 threads,
// 8xTN microtile. Register-staged prefetch of tile k+1 overlaps the FMA block
// of tile k; ONE __syncthreads per K-tile.
// No bounds checks: requires M%128==0, N%BN==0, K%16==0, ld%4==0, 16B-aligned.
//  EPI: 0 C=alpha*acc | 2 C=exp(2acc-e1[i]-e2[j])
//       3 C=alpha*e1[i]*acc (+beta*e2[i,j] if e2) | 5 C=e2[i,j]-e1[i]*acc
//       6 C=relu(acc + e2[j])          (fused bias+relu combine)
//  TRA: A is [K,M]. TRB: B is [N,K]. BSC: scale B rows by bscale[k].
//  split-K: z -> b = z>>splitLog, ch = remainder; per-chunk K elements.
// ---------------------------------------------------------------------------
template<int BN, int TN, int EPI, int TRA, int TRB, int BSC>
__global__ __launch_bounds__(256)
void fgemm_kernel(const float* __restrict__ A, const float* __restrict__ B,
                  float* __restrict__ C, int K, int lda, int ldb, int ldc,
                  long long sA, long long sB, long long sC,
                  const float* __restrict__ bscale, long long sBS,
                  const float* __restrict__ e1, long long sE1,
                  const float* __restrict__ e2, long long sE2,
                  float alpha, float beta, int splitLog)
{
    const int z = blockIdx.z;
    const int b = z >> splitLog;
    const int ch = z - (b << splitLog);

    A += (long long)b * sA + (TRA ? (long long)ch * K * lda : (long long)ch * K);
    B += (long long)b * sB + (TRB ? (long long)ch * K : (long long)ch * K * ldb);
    C += (long long)z * sC;
    if (BSC) bscale += (long long)b * sBS + (long long)ch * K;
    if (e1) e1 += (long long)b * sE1;
    if (e2) e2 += (long long)b * sE2;

    __shared__ float As[2][16][128 + 4];
    __shared__ float Bs[2][16][BN + 4];

    const int tid = threadIdx.x;
    const int m0 = blockIdx.y * 128;
    const int n0 = blockIdx.x * BN;
    const int tm = (tid >> 4) * 8;
    const int tn = (tid & 15) * TN;

    float4 aReg[2], bReg[2];

    // ---- load tile k0 from gmem into registers (apply bscale on B) ----
    auto LOAD = [&](int k0) {
        if (TRA == 0) {
            const int arow = tid >> 2, ac4 = tid & 3;
            aReg[0] = *(const float4*)(A + (long long)(m0 + arow) * lda + k0 + ac4 * 4);
            aReg[1] = *(const float4*)(A + (long long)(m0 + arow + 64) * lda + k0 + ac4 * 4);
        } else {
            const int akk = tid >> 5, am4 = tid & 31;
            aReg[0] = *(const float4*)(A + (long long)(k0 + akk) * lda + m0 + am4 * 4);
            aReg[1] = *(const float4*)(A + (long long)(k0 + akk + 8) * lda + m0 + am4 * 4);
        }
        if (TRB == 0) {
            if (BN == 128) {
                const int bkk = tid >> 5, bn4 = tid & 31;
                bReg[0] = *(const float4*)(B + (long long)(k0 + bkk) * ldb + n0 + bn4 * 4);
                bReg[1] = *(const float4*)(B + (long long)(k0 + bkk + 8) * ldb + n0 + bn4 * 4);
                if (BSC) {
                    float s0 = bscale[k0 + bkk], s1 = bscale[k0 + bkk + 8];
                    bReg[0].x *= s0; bReg[0].y *= s0; bReg[0].z *= s0; bReg[0].w *= s0;
                    bReg[1].x *= s1; bReg[1].y *= s1; bReg[1].z *= s1; bReg[1].w *= s1;
                }
            } else {  // BN == 64
                const int bkk = tid >> 4, bn4 = tid & 15;
                bReg[0] = *(const float4*)(B + (long long)(k0 + bkk) * ldb + n0 + bn4 * 4);
                if (BSC) {
                    float s0 = bscale[k0 + bkk];
                    bReg[0].x *= s0; bReg[0].y *= s0; bReg[0].z *= s0; bReg[0].w *= s0;
                }
            }
        } else {  // TRB: B[n,k] (BN==128, no BSC at call sites)
            const int brow = tid >> 2, bc4 = tid & 3;
            bReg[0] = *(const float4*)(B + (long long)(n0 + brow) * ldb + k0 + bc4 * 4);
            bReg[1] = *(const float4*)(B + (long long)(n0 + brow + 64) * ldb + k0 + bc4 * 4);
        }
    };

    // ---- store staged registers into smem buffer `buf` ----
    auto STORE = [&](int buf) {
        if (TRA == 0) {
            const int arow = tid >> 2, ac4 = tid & 3;
            As[buf][ac4 * 4 + 0][arow] = aReg[0].x;
            As[buf][ac4 * 4 + 1][arow] = aReg[0].y;
            As[buf][ac4 * 4 + 2][arow] = aReg[0].z;
            As[buf][ac4 * 4 + 3][arow] = aReg[0].w;
            As[buf][ac4 * 4 + 0][arow + 64] = aReg[1].x;
            As[buf][ac4 * 4 + 1][arow + 64] = aReg[1].y;
            As[buf][ac4 * 4 + 2][arow + 64] = aReg[1].z;
            As[buf][ac4 * 4 + 3][arow + 64] = aReg[1].w;
        } else {
            const int akk = tid >> 5, am4 = tid & 31;
            *(float4*)&As[buf][akk][am4 * 4] = aReg[0];
            *(float4*)&As[buf][akk + 8][am4 * 4] = aReg[1];
        }
        if (TRB == 0) {
            if (BN == 128) {
                const int bkk = tid >> 5, bn4 = tid & 31;
                *(float4*)&Bs[buf][bkk][bn4 * 4] = bReg[0];
                *(float4*)&Bs[buf][bkk + 8][bn4 * 4] = bReg[1];
            } else {
                const int bkk = tid >> 4, bn4 = tid & 15;
                *(float4*)&Bs[buf][bkk][bn4 * 4] = bReg[0];
            }
        } else {
            const int brow = tid >> 2, bc4 = tid & 3;
            Bs[buf][bc4 * 4 + 0][brow] = bReg[0].x;
            Bs[buf][bc4 * 4 + 1][brow] = bReg[0].y;
            Bs[buf][bc4 * 4 + 2][brow] = bReg[0].z;
            Bs[buf][bc4 * 4 + 3][brow] = bReg[0].w;
            Bs[buf][bc4 * 4 + 0][brow + 64] = bReg[1].x;
            Bs[buf][bc4 * 4 + 1][brow + 64] = bReg[1].y;
            Bs[buf][bc4 * 4 + 2][brow + 64] = bReg[1].z;
            Bs[buf][bc4 * 4 + 3][brow + 64] = bReg[1].w;
        }
    };

    float acc[8][TN];
#pragma unroll
    for (int u = 0; u < 8; u++)
#pragma unroll
        for (int v = 0; v < TN; v++) acc[u][v] = 0.f;

    auto COMPUTE = [&](int buf) {
#pragma unroll
        for (int kk = 0; kk < 16; kk++) {
            float a[8], bv[TN];
            *(float4*)&a[0] = *(const float4*)&As[buf][kk][tm];
            *(float4*)&a[4] = *(const float4*)&As[buf][kk][tm + 4];
            *(float4*)&bv[0] = *(const float4*)&Bs[buf][kk][tn];
            if (TN == 8) *(float4*)&bv[4] = *(const float4*)&Bs[buf][kk][tn + 4];
#pragma unroll
            for (int u = 0; u < 8; u++)
#pragma unroll
                for (int v = 0; v < TN; v++) acc[u][v] += a[u] * bv[v];
        }
    };

    // ---- pipelined mainloop ----
    LOAD(0);
    STORE(0);
    __syncthreads();
    int cur = 0;
    for (int k0 = 16; k0 < K; k0 += 16) {
        LOAD(k0);          // prefetch next tile (latency hidden under COMPUTE)
        COMPUTE(cur);
        STORE(cur ^ 1);
        __syncthreads();
        cur ^= 1;
    }
    COMPUTE(cur);

    // ---- epilogue ----
#pragma unroll
    for (int u = 0; u < 8; u++) {
        int gi = m0 + tm + u;
#pragma unroll
        for (int v = 0; v < TN; v++) {
            int gj = n0 + tn + v;
            float r = acc[u][v];
            long long idx = (long long)gi * ldc + gj;
            if (EPI == 0) C[idx] = alpha * r;
            else if (EPI == 2) C[idx] = expf(2.f * r - e1[gi] - e2[gj]);
            else if (EPI == 3) {
                float t = alpha * e1[gi] * r;
                if (e2) t += beta * e2[idx];
                C[idx] = t;
            } else if (EPI == 5) C[idx] = e2[idx] - e1[gi] * r;
            else if (EPI == 6) C[idx] = fmaxf(r + e2[gj], 0.f);
        }
    }
}

// ---------------------------------------------------------------------------
// Generic fallback SGEMM (bounds-checked), used for layer-1 small dims.
// ---------------------------------------------------------------------------
#define TBM 64
#define TBN 64
#define TBK 16

__global__ void gemm_kernel(
    const float* __restrict__ A, const float* __restrict__ B, float* __restrict__ C,
    int M, int N, int K, int lda, int ldb, int ldc,
    long long sA, long long sB, long long sC,
    int transA, int transB,
    const float* __restrict__ bscale, long long sBS,
    int epi,
    const float* __restrict__ e1, long long sE1,
    const float* __restrict__ e2, long long sE2,
    float alpha, float beta)
{
    int b = blockIdx.z;
    A += (long long)b * sA;
    B += (long long)b * sB;
    C += (long long)b * sC;
    if (bscale) bscale += (long long)b * sBS;
    if (e1) e1 += (long long)b * sE1;
    if (e2) e2 += (long long)b * sE2;

    __shared__ float As[TBK][TBM];
    __shared__ float Bs[TBK][TBN];

    const int tx = threadIdx.x, ty = threadIdx.y;
    const int tid = ty * 16 + tx;
    const int m0 = blockIdx.y * TBM;
    const int n0 = blockIdx.x * TBN;

    float acc[4][4];
#pragma unroll
    for (int u = 0; u < 4; u++)
#pragma unroll
        for (int v = 0; v < 4; v++) acc[u][v] = 0.f;

    for (int k0 = 0; k0 < K; k0 += TBK) {
        if (!transA) {
            int kk = tid & 15, i0 = tid >> 4;
#pragma unroll
            for (int r = 0; r < 4; r++) {
                int i = i0 + r * 16;
                int gm = m0 + i, gk = k0 + kk;
                As[kk][i] = (gm < M && gk < K) ? A[(long long)gm * lda + gk] : 0.f;
            }
        } else {
            int i = tid & 63, kk0 = tid >> 6;
#pragma unroll
            for (int r = 0; r < 4; r++) {
                int kk = kk0 + r * 4;
                int gm = m0 + i, gk = k0 + kk;
                As[kk][i] = (gm < M && gk < K) ? A[(long long)gk * lda + gm] : 0.f;
            }
        }
        if (!transB) {
            int j = tid & 63, kk0 = tid >> 6;
#pragma unroll
            for (int r = 0; r < 4; r++) {
                int kk = kk0 + r * 4;
                int gn = n0 + j, gk = k0 + kk;
                float v = (gn < N && gk < K) ? B[(long long)gk * ldb + gn] : 0.f;
                if (bscale && gk < K) v *= bscale[gk];
                Bs[kk][j] = v;
            }
        } else {
            int kk = tid & 15, j0 = tid >> 4;
#pragma unroll
            for (int r = 0; r < 4; r++) {
                int j = j0 + r * 16;
                int gn = n0 + j, gk = k0 + kk;
                float v = (gn < N && gk < K) ? B[(long long)gn * ldb + gk] : 0.f;
                if (bscale && gk < K) v *= bscale[gk];
                Bs[kk][j] = v;
            }
        }
        __syncthreads();

#pragma unroll
        for (int kk = 0; kk < TBK; kk++) {
            float a[4], bv[4];
#pragma unroll
            for (int u = 0; u < 4; u++) a[u] = As[kk][ty * 4 + u];
#pragma unroll
            for (int v = 0; v < 4; v++) bv[v] = Bs[kk][tx * 4 + v];
#pragma unroll
            for (int u = 0; u < 4; u++)
#pragma unroll
                for (int v = 0; v < 4; v++) acc[u][v] += a[u] * bv[v];
        }
        __syncthreads();
    }

#pragma unroll
    for (int u = 0; u < 4; u++) {
        int gi = m0 + ty * 4 + u;
        if (gi >= M) continue;
#pragma unroll
        for (int v = 0; v < 4; v++) {
            int gj = n0 + tx * 4 + v;
            if (gj >= N) continue;
            float r = acc[u][v];
            long long idx = (long long)gi * ldc + gj;
            switch (epi) {
                case 0: C[idx] = alpha * r; break;
                case 1: C[idx] += alpha * r; break;
                case 2: C[idx] = expf(2.f * r - e1[gi] - e2[gj]); break;
                case 3: {
                    float t = alpha * e1[gi] * r;
                    if (e2) t += beta * e2[idx];
                    C[idx] = t;
                } break;
                case 5: C[idx] = e2[idx] - e1[gi] * r; break;
                case 6: C[idx] = fmaxf(r + e2[gj], 0.f); break;
            }
        }
    }
}

// ---------------------------------------------------------------------------
// Helper kernels
// ---------------------------------------------------------------------------
__global__ void sqnorm_kernel(const float* __restrict__ P, float* __restrict__ sq, int C)
{
    int row = blockIdx.x * (blockDim.x / 32) + (threadIdx.x >> 5);
    int lane = threadIdx.x & 31;
    if (row >= BB * NN) return;
    const float* p = P + (long long)row * C;
    float s = 0.f;
    for (int c = lane; c < C; c += 32) { float v = p[c]; s += v * v; }
#pragma unroll
    for (int o = 16; o; o >>= 1) s += __shfl_xor_sync(0xFFFFFFFFu, s, o);
    if (!lane) sq[row] = s;
}

__global__ void degree_kernel(const float* __restrict__ W,
                              float* __restrict__ dinv, float* __restrict__ din0)
{
    long long row = blockIdx.x;
    int col = (int)(row % NN);
    const float* w = W + row * NN;
    float s = 0.f, s0 = 0.f;
    for (int i = threadIdx.x; i < NN; i += 256) {
        float v = w[i];
        s += v;
        if (i != col) s0 += v;
    }
    __shared__ float sh[256], sh0[256];
    sh[threadIdx.x] = s;
    sh0[threadIdx.x] = s0;
    __syncthreads();
    for (int st = 128; st; st >>= 1) {
        if (threadIdx.x < st) {
            sh[threadIdx.x]  += sh[threadIdx.x + st];
            sh0[threadIdx.x] += sh0[threadIdx.x + st];
        }
        __syncthreads();
    }
    if (!threadIdx.x) {
        dinv[row] = rsqrtf(sh[0]);
        din0[row] = rsqrtf(sh0[0]);
    }
}

__global__ void zero_diag_kernel(float* __restrict__ W)
{
    int i = blockIdx.x * blockDim.x + threadIdx.x;
    if (i >= BB * NN) return;
    int b = i >> 10, n = i & 1023;
    W[(long long)b * NN * NN + (long long)n * NN + n] = 0.f;
}

// dst[row, 0:C] (row stride KC) = src[row, 0:C] (contiguous)
__global__ void copy_slice_kernel(const float* __restrict__ src, float* __restrict__ dst,
                                  int C, int KC, long long total)
{
    long long i = blockIdx.x * (long long)blockDim.x + threadIdx.x;
    if (i < total) {
        long long row = i / C;
        int c = (int)(i - row * C);
        dst[row * KC + c] = src[i];
    }
}

// sum slices, then Frobenius partial
__global__ void normsq_partial_kernel(const float* __restrict__ P, long long elems,
                                      int nsl, float* __restrict__ part)
{
    float s = 0.f;
    for (long long i = blockIdx.x * (long long)blockDim.x + threadIdx.x; i < elems;
         i += (long long)gridDim.x * blockDim.x) {
        float t = 0.f;
        for (int z = 0; z < nsl; z++) t += P[(long long)z * elems + i];
        s += t * t;
    }
    __shared__ float sh[256];
    sh[threadIdx.x] = s;
    __syncthreads();
    for (int st = 128; st; st >>= 1) {
        if (threadIdx.x < st) sh[threadIdx.x] += sh[threadIdx.x + st];
        __syncthreads();
    }
    if (!threadIdx.x) part[blockIdx.x] = sh[0];
}

__global__ void normsq_final_kernel(const float* __restrict__ part, float* __restrict__ r)
{
    __shared__ float sh[256];
    sh[threadIdx.x] = part[threadIdx.x];
    __syncthreads();
    for (int st = 128; st; st >>= 1) {
        if (threadIdx.x < st) sh[threadIdx.x] += sh[threadIdx.x + st];
        __syncthreads();
    }
    if (!threadIdx.x) *r = sqrtf(sh[0]);
}

__global__ void maxpool_kernel(const float* __restrict__ o3, float* __restrict__ pooled)
{
    int c = blockIdx.x * blockDim.x + threadIdx.x;
    int b = blockIdx.y;
    if (c >= 1024) return;
    const float* p = o3 + (long long)b * 1024 * 1024 + c;
    float m = p[0];
    for (int n = 1; n < 1024; n++) m = fmaxf(m, p[(long long)n * 1024]);
    pooled[b * 1024 + c] = m;
}

__global__ void fc_kernel(const float* __restrict__ in, const float* __restrict__ w,
                          const float* __restrict__ bias, float* __restrict__ out,
                          int K, int Nout, int do_relu)
{
    int j = blockIdx.x * blockDim.x + threadIdx.x;
    int b = blockIdx.y;
    if (j >= Nout) return;
    float s = bias[j];
    const float* ip = in + (long long)b * K;
    for (int k = 0; k < K; k++) s += ip[k] * w[(long long)k * Nout + j];
    if (do_relu) s = fmaxf(s, 0.f);
    out[(long long)b * Nout + j] = s;
}

// ---------------------------------------------------------------------------
// Host orchestration
// ---------------------------------------------------------------------------
static void launch_generic(const float* A, const float* B, float* C,
                           int M, int N, int K, int lda, int ldb, int ldc,
                           long long sA, long long sB, long long sC,
                           int tA, int tB,
                           const float* bs, long long sBS,
                           int epi, const float* e1, long long sE1,
                           const float* e2, long long sE2,
                           float alpha, float beta, int batch)
{
    dim3 grid((N + TBN - 1) / TBN, (M + TBM - 1) / TBM, batch);
    dim3 thr(16, 16);
    gemm_kernel<<<grid, thr>>>(A, B, C, M, N, K, lda, ldb, ldc, sA, sB, sC,
                               tA, tB, bs, sBS, epi, e1, sE1, e2, sE2, alpha, beta);
}

struct Bufs {
    float *W, *T, *Zall, *sq, *dinv, *din0, *part;
};

static void run_layer(const float* X, int Cin, int Cout, int Kcheb,
                      const float* Wk, const float* bias,
                      float* OUT, float* r_out, const Bufs& bf)
{
    const int KC = Kcheb * Cin;
    const long long sX = (long long)NN * Cin;
    const long long sZ = (long long)NN * KC;
    const long long sO = (long long)NN * Cout;
    const long long sW = (long long)NN * NN;

    // 1) squared norms
    sqnorm_kernel<<<(BB * NN) / 8, 256>>>(X, bf.sq, Cin);

    // 2) W = exp(2*X@X^T - sq_i - sq_j)
    if (Cin % 16 == 0) {
        dim3 g(NN / 128, NN / 128, BB);
        fgemm_kernel<128, 8, 2, 0, 1, 0><<<g, 256>>>(
            X, X, bf.W, Cin, Cin, Cin, NN, sX, sX, sW,
            nullptr, 0, bf.sq, NN, bf.sq, NN, 1.f, 0.f, 0);
    } else {
        launch_generic(X, X, bf.W, NN, NN, Cin, Cin, Cin, NN, sX, sX, sW,
                       0, 1, nullptr, 0, 2, bf.sq, NN, bf.sq, NN, 1.f, 0.f, BB);
    }

    // 3) degrees
    degree_kernel<<<BB * NN, 256>>>(bf.W, bf.dinv, bf.din0);

    // 4) Zall slice 0 = X
    copy_slice_kernel<<<(unsigned)(((long long)BB * NN * Cin + 255) / 256), 256>>>(
        X, bf.Zall, Cin, KC, (long long)BB * NN * Cin);

    // 5) Chebyshev recursion into Zall slices 1..Kcheb-1
    for (int k = 1; k < Kcheb; k++) {
        float* Ck = bf.Zall + (long long)k * Cin;
        const float* Bk = bf.Zall + (long long)(k - 1) * Cin;
        const float* Ek = (k >= 2) ? (bf.Zall + (long long)(k - 2) * Cin) : nullptr;
        float alpha = (k == 1) ? -1.f : -2.f;
        if (Cin == 128) {
            dim3 g(Cin / 64, NN / 128, BB);
            fgemm_kernel<64, 4, 3, 0, 0, 1><<<g, 256>>>(
                bf.W, Bk, Ck, NN, NN, KC, KC, sW, sZ, sZ,
                bf.dinv, NN, bf.dinv, NN, Ek, sZ, alpha, -1.f, 0);
        } else if (Cin % 128 == 0) {
            dim3 g(Cin / 128, NN / 128, BB);
            fgemm_kernel<128, 8, 3, 0, 0, 1><<<g, 256>>>(
                bf.W, Bk, Ck, NN, NN, KC, KC, sW, sZ, sZ,
                bf.dinv, NN, bf.dinv, NN, Ek, sZ, alpha, -1.f, 0);
        } else {
            launch_generic(bf.W, Bk, Ck, NN, Cin, NN, NN, KC, KC, sW, sZ, sZ,
                           0, 0, bf.dinv, NN, 3, bf.dinv, NN, Ek, sZ,
                           alpha, -1.f, BB);
        }
    }

    // 6) OUT = relu(Zall @ Wk_flat + bias)  (fused combine, EPI 6)
    if (KC % 16 == 0 && Cout % 128 == 0) {
        dim3 g(Cout / 128, NN / 128, BB);
        fgemm_kernel<128, 8, 6, 0, 0, 0><<<g, 256>>>(
            bf.Zall, Wk, OUT, KC, KC, Cout, Cout, sZ, 0, sO,
            nullptr, 0, nullptr, 0, bias, 0, 1.f, 0.f, 0);
    } else {
        launch_generic(bf.Zall, Wk, OUT, NN, Cout, KC, KC, Cout, Cout, sZ, 0, sO,
                       0, 0, nullptr, 0, 6, nullptr, 0, bias, 0, 1.f, 0.f, BB);
    }

    // 7) reg: zero diag, T = out - d0 .* (W0 @ (d0 .* out))
    zero_diag_kernel<<<(BB * NN + 255) / 256, 256>>>(bf.W);
    {
        dim3 g(Cout / 128, NN / 128, BB);
        fgemm_kernel<128, 8, 5, 0, 0, 1><<<g, 256>>>(
            bf.W, OUT, bf.T, NN, NN, Cout, Cout, sW, sO, sO,
            bf.din0, NN, bf.din0, NN, OUT, sO, 1.f, 0.f, 0);
    }

    // 8) M partials: per (batch, K-chunk) slice of out^T @ T into g_W (dead now)
    int splitLog = (Cout == 128) ? 3 : (Cout == 512) ? 1 : 0;
    int chunkK = NN >> splitLog;
    int nsl = BB << splitLog;
    {
        dim3 g(Cout / 128, Cout / 128, nsl);
        fgemm_kernel<128, 8, 0, 1, 0, 0><<<g, 256>>>(
            OUT, bf.T, bf.W, chunkK, Cout, Cout, Cout,
            sO, sO, (long long)Cout * Cout,
            nullptr, 0, nullptr, 0, nullptr, 0, 1.f, 0.f, splitLog);
    }

    // 9) r = ||sum_z M_z||_F
    normsq_partial_kernel<<<256, 256>>>(bf.W, (long long)Cout * Cout, nsl, bf.part);
    normsq_final_kernel<<<1, 256>>>(bf.part, r_out);
}

extern "C" void kernel_launch(void* const* d_in, const int* in_sizes, int n_in,
                              void* d_out, int out_size)
{
    (void)in_sizes; (void)out_size;
    const float* x = (const float*)d_in[0];
    int base = n_in - 12;
    const float* w1  = (const float*)d_in[base + 0];
    const float* b1  = (const float*)d_in[base + 1];
    const float* w2  = (const float*)d_in[base + 2];
    const float* b2  = (const float*)d_in[base + 3];
    const float* w3  = (const float*)d_in[base + 4];
    const float* b3  = (const float*)d_in[base + 5];
    const float* fw1 = (const float*)d_in[base + 6];
    const float* fb1 = (const float*)d_in[base + 7];
    const float* fw2 = (const float*)d_in[base + 8];
    const float* fb2 = (const float*)d_in[base + 9];
    const float* fw3 = (const float*)d_in[base + 10];
    const float* fb3 = (const float*)d_in[base + 11];
    float* out = (float*)d_out;

    Bufs bf;
    float *o1, *o2, *o3, *pool, *h1, *h2;
    cudaGetSymbolAddress((void**)&bf.W,    g_W);
    cudaGetSymbolAddress((void**)&bf.T,    g_T);
    cudaGetSymbolAddress((void**)&bf.Zall, g_Zall);
    cudaGetSymbolAddress((void**)&bf.sq,   g_sq);
    cudaGetSymbolAddress((void**)&bf.dinv, g_dinv);
    cudaGetSymbolAddress((void**)&bf.din0, g_din0);
    cudaGetSymbolAddress((void**)&bf.part, g_part);
    cudaGetSymbolAddress((void**)&o1,      g_out1);
    cudaGetSymbolAddress((void**)&o2,      g_out2);
    cudaGetSymbolAddress((void**)&o3,      g_out3);
    cudaGetSymbolAddress((void**)&pool,    g_pool);
    cudaGetSymbolAddress((void**)&h1,      g_h1);
    cudaGetSymbolAddress((void**)&h2,      g_h2);

    run_layer(x,  6,   128,  6, w1, b1, o1, out + 160, bf);
    run_layer(o1, 128, 512,  5, w2, b2, o2, out + 161, bf);
    run_layer(o2, 512, 1024, 3, w3, b3, o3, out + 162, bf);

    {
        dim3 g(1024 / 256, BB);
        maxpool_kernel<<<g, 256>>>(o3, pool);
    }
    {
        dim3 g1((512 + 127) / 128, BB);
        fc_kernel<<<g1, 128>>>(pool, fw1, fb1, h1, 1024, 512, 1);
        dim3 g2(1, BB);
        fc_kernel<<<g2, 128>>>(h1, fw2, fb2, h2, 512, 128, 1);
        fc_kernel<<<g2, 128>>>(h2, fw3, fb3, out, 128, 10, 0);
    }
}

// round 8
// speedup vs baseline: 2.2106x; 1.0009x over previous
#include <cuda_runtime.h>
#include <math.h>

// ---------------------------------------------------------------------------
// B=16 graphs, N=1024 points.
//   Layer1: Cin=6,   Cout=128,  K=6
//   Layer2: Cin=128, Cout=512,  K=5
//   Layer3: Cin=512, Cout=1024, K=3
// Output: logits [16,10] -> 160 floats, then r1, r2, r3 -> 163 floats.
// ---------------------------------------------------------------------------

#define BB 16
#define NN 1024
#define KCMAX 1536   // max Kcheb*Cin (layer3: 3*512)

// Scratch (device globals; no allocation allowed)
__device__ float g_W   [BB * NN * NN];        // adjacency / M partials (reused)
__device__ float g_T   [BB * NN * 1024];      // reg L@out
__device__ float g_out1[BB * NN * 128];
__device__ float g_out2[BB * NN * 512];
__device__ float g_out3[BB * NN * 1024];
__device__ float g_Zall[BB * NN * KCMAX];     // interleaved Chebyshev basis
__device__ float g_sq  [BB * NN];
__device__ float g_dinv[BB * NN];
__device__ float g_din0[BB * NN];
__device__ float g_part[256];
__device__ float g_pool[BB * 1024];
__device__ float g_h1  [BB * 512];
__device__ float g_h2  [BB * 128];

// ---------------------------------------------------------------------------
// FAST SGEMM, double-buffered: BM=128, BN in {128,64}, BK=16, 256 threads,
// 8xTN microtile. Register-staged prefetch of tile k+1 overlaps the FMA block
// of tile k; ONE __syncthreads per K-tile.
// No bounds checks: requires M%128==0, N%BN==0, K%16==0, ld%4==0, 16B-aligned.
//  EPI: 0 C=alpha*acc | 2 C=exp(2acc-e1[i]-e2[j])
//       3 C=alpha*e1[i]*acc (+beta*e2[i,j] if e2) | 5 C=e2[i,j]-e1[i]*acc
//       6 C=relu(acc + e2[j])          (fused bias+relu combine)
//  TRA: A is [K,M]. TRB: B is [N,K]. BSC: scale B rows by bscale[k].
//  split-K: z -> b = z>>splitLog, ch = remainder; per-chunk K elements.
// ---------------------------------------------------------------------------
template<int BN, int TN, int EPI, int TRA, int TRB, int BSC>
__global__ __launch_bounds__(256)
void fgemm_kernel(const float* __restrict__ A, const float* __restrict__ B,
                  float* __restrict__ C, int K, int lda, int ldb, int ldc,
                  long long sA, long long sB, long long sC,
                  const float* __restrict__ bscale, long long sBS,
                  const float* __restrict__ e1, long long sE1,
                  const float* __restrict__ e2, long long sE2,
                  float alpha, float beta, int splitLog)
{
    const int z = blockIdx.z;
    const int b = z >> splitLog;
    const int ch = z - (b << splitLog);

    A += (long long)b * sA + (TRA ? (long long)ch * K * lda : (long long)ch * K);
    B += (long long)b * sB + (TRB ? (long long)ch * K : (long long)ch * K * ldb);
    C += (long long)z * sC;
    if (BSC) bscale += (long long)b * sBS + (long long)ch * K;
    if (e1) e1 += (long long)b * sE1;
    if (e2) e2 += (long long)b * sE2;

    __shared__ float As[2][16][128 + 4];
    __shared__ float Bs[2][16][BN + 4];

    const int tid = threadIdx.x;
    const int m0 = blockIdx.y * 128;
    const int n0 = blockIdx.x * BN;
    const int tm = (tid >> 4) * 8;
    const int tn = (tid & 15) * TN;

    float4 aReg[2], bReg[2];

    // ---- load tile k0 from gmem into registers (apply bscale on B) ----
    auto LOAD = [&](int k0) {
        if (TRA == 0) {
            const int arow = tid >> 2, ac4 = tid & 3;
            aReg[0] = *(const float4*)(A + (long long)(m0 + arow) * lda + k0 + ac4 * 4);
            aReg[1] = *(const float4*)(A + (long long)(m0 + arow + 64) * lda + k0 + ac4 * 4);
        } else {
            const int akk = tid >> 5, am4 = tid & 31;
            aReg[0] = *(const float4*)(A + (long long)(k0 + akk) * lda + m0 + am4 * 4);
            aReg[1] = *(const float4*)(A + (long long)(k0 + akk + 8) * lda + m0 + am4 * 4);
        }
        if (TRB == 0) {
            if (BN == 128) {
                const int bkk = tid >> 5, bn4 = tid & 31;
                bReg[0] = *(const float4*)(B + (long long)(k0 + bkk) * ldb + n0 + bn4 * 4);
                bReg[1] = *(const float4*)(B + (long long)(k0 + bkk + 8) * ldb + n0 + bn4 * 4);
                if (BSC) {
                    float s0 = bscale[k0 + bkk], s1 = bscale[k0 + bkk + 8];
                    bReg[0].x *= s0; bReg[0].y *= s0; bReg[0].z *= s0; bReg[0].w *= s0;
                    bReg[1].x *= s1; bReg[1].y *= s1; bReg[1].z *= s1; bReg[1].w *= s1;
                }
            } else {  // BN == 64
                const int bkk = tid >> 4, bn4 = tid & 15;
                bReg[0] = *(const float4*)(B + (long long)(k0 + bkk) * ldb + n0 + bn4 * 4);
                if (BSC) {
                    float s0 = bscale[k0 + bkk];
                    bReg[0].x *= s0; bReg[0].y *= s0; bReg[0].z *= s0; bReg[0].w *= s0;
                }
            }
        } else {  // TRB: B[n,k] (BN==128, no BSC at call sites)
            const int brow = tid >> 2, bc4 = tid & 3;
            bReg[0] = *(const float4*)(B + (long long)(n0 + brow) * ldb + k0 + bc4 * 4);
            bReg[1] = *(const float4*)(B + (long long)(n0 + brow + 64) * ldb + k0 + bc4 * 4);
        }
    };

    // ---- store staged registers into smem buffer `buf` ----
    auto STORE = [&](int buf) {
        if (TRA == 0) {
            const int arow = tid >> 2, ac4 = tid & 3;
            As[buf][ac4 * 4 + 0][arow] = aReg[0].x;
            As[buf][ac4 * 4 + 1][arow] = aReg[0].y;
            As[buf][ac4 * 4 + 2][arow] = aReg[0].z;
            As[buf][ac4 * 4 + 3][arow] = aReg[0].w;
            As[buf][ac4 * 4 + 0][arow + 64] = aReg[1].x;
            As[buf][ac4 * 4 + 1][arow + 64] = aReg[1].y;
            As[buf][ac4 * 4 + 2][arow + 64] = aReg[1].z;
            As[buf][ac4 * 4 + 3][arow + 64] = aReg[1].w;
        } else {
            const int akk = tid >> 5, am4 = tid & 31;
            *(float4*)&As[buf][akk][am4 * 4] = aReg[0];
            *(float4*)&As[buf][akk + 8][am4 * 4] = aReg[1];
        }
        if (TRB == 0) {
            if (BN == 128) {
                const int bkk = tid >> 5, bn4 = tid & 31;
                *(float4*)&Bs[buf][bkk][bn4 * 4] = bReg[0];
                *(float4*)&Bs[buf][bkk + 8][bn4 * 4] = bReg[1];
            } else {
                const int bkk = tid >> 4, bn4 = tid & 15;
                *(float4*)&Bs[buf][bkk][bn4 * 4] = bReg[0];
            }
        } else {
            const int brow = tid >> 2, bc4 = tid & 3;
            Bs[buf][bc4 * 4 + 0][brow] = bReg[0].x;
            Bs[buf][bc4 * 4 + 1][brow] = bReg[0].y;
            Bs[buf][bc4 * 4 + 2][brow] = bReg[0].z;
            Bs[buf][bc4 * 4 + 3][brow] = bReg[0].w;
            Bs[buf][bc4 * 4 + 0][brow + 64] = bReg[1].x;
            Bs[buf][bc4 * 4 + 1][brow + 64] = bReg[1].y;
            Bs[buf][bc4 * 4 + 2][brow + 64] = bReg[1].z;
            Bs[buf][bc4 * 4 + 3][brow + 64] = bReg[1].w;
        }
    };

    float acc[8][TN];
#pragma unroll
    for (int u = 0; u < 8; u++)
#pragma unroll
        for (int v = 0; v < TN; v++) acc[u][v] = 0.f;

    auto COMPUTE = [&](int buf) {
#pragma unroll
        for (int kk = 0; kk < 16; kk++) {
            float a[8], bv[TN];
            *(float4*)&a[0] = *(const float4*)&As[buf][kk][tm];
            *(float4*)&a[4] = *(const float4*)&As[buf][kk][tm + 4];
            *(float4*)&bv[0] = *(const float4*)&Bs[buf][kk][tn];
            if (TN == 8) *(float4*)&bv[4] = *(const float4*)&Bs[buf][kk][tn + 4];
#pragma unroll
            for (int u = 0; u < 8; u++)
#pragma unroll
                for (int v = 0; v < TN; v++) acc[u][v] += a[u] * bv[v];
        }
    };

    // ---- pipelined mainloop ----
    LOAD(0);
    STORE(0);
    __syncthreads();
    int cur = 0;
    for (int k0 = 16; k0 < K; k0 += 16) {
        LOAD(k0);          // prefetch next tile (latency hidden under COMPUTE)
        COMPUTE(cur);
        STORE(cur ^ 1);
        __syncthreads();
        cur ^= 1;
    }
    COMPUTE(cur);

    // ---- epilogue ----
#pragma unroll
    for (int u = 0; u < 8; u++) {
        int gi = m0 + tm + u;
#pragma unroll
        for (int v = 0; v < TN; v++) {
            int gj = n0 + tn + v;
            float r = acc[u][v];
            long long idx = (long long)gi * ldc + gj;
            if (EPI == 0) C[idx] = alpha * r;
            else if (EPI == 2) C[idx] = expf(2.f * r - e1[gi] - e2[gj]);
            else if (EPI == 3) {
                float t = alpha * e1[gi] * r;
                if (e2) t += beta * e2[idx];
                C[idx] = t;
            } else if (EPI == 5) C[idx] = e2[idx] - e1[gi] * r;
            else if (EPI == 6) C[idx] = fmaxf(r + e2[gj], 0.f);
        }
    }
}

// ---------------------------------------------------------------------------
// Generic fallback SGEMM (bounds-checked), used for layer-1 small dims.
// ---------------------------------------------------------------------------
#define TBM 64
#define TBN 64
#define TBK 16

__global__ void gemm_kernel(
    const float* __restrict__ A, const float* __restrict__ B, float* __restrict__ C,
    int M, int N, int K, int lda, int ldb, int ldc,
    long long sA, long long sB, long long sC,
    int transA, int transB,
    const float* __restrict__ bscale, long long sBS,
    int epi,
    const float* __restrict__ e1, long long sE1,
    const float* __restrict__ e2, long long sE2,
    float alpha, float beta)
{
    int b = blockIdx.z;
    A += (long long)b * sA;
    B += (long long)b * sB;
    C += (long long)b * sC;
    if (bscale) bscale += (long long)b * sBS;
    if (e1) e1 += (long long)b * sE1;
    if (e2) e2 += (long long)b * sE2;

    __shared__ float As[TBK][TBM];
    __shared__ float Bs[TBK][TBN];

    const int tx = threadIdx.x, ty = threadIdx.y;
    const int tid = ty * 16 + tx;
    const int m0 = blockIdx.y * TBM;
    const int n0 = blockIdx.x * TBN;

    float acc[4][4];
#pragma unroll
    for (int u = 0; u < 4; u++)
#pragma unroll
        for (int v = 0; v < 4; v++) acc[u][v] = 0.f;

    for (int k0 = 0; k0 < K; k0 += TBK) {
        if (!transA) {
            int kk = tid & 15, i0 = tid >> 4;
#pragma unroll
            for (int r = 0; r < 4; r++) {
                int i = i0 + r * 16;
                int gm = m0 + i, gk = k0 + kk;
                As[kk][i] = (gm < M && gk < K) ? A[(long long)gm * lda + gk] : 0.f;
            }
        } else {
            int i = tid & 63, kk0 = tid >> 6;
#pragma unroll
            for (int r = 0; r < 4; r++) {
                int kk = kk0 + r * 4;
                int gm = m0 + i, gk = k0 + kk;
                As[kk][i] = (gm < M && gk < K) ? A[(long long)gk * lda + gm] : 0.f;
            }
        }
        if (!transB) {
            int j = tid & 63, kk0 = tid >> 6;
#pragma unroll
            for (int r = 0; r < 4; r++) {
                int kk = kk0 + r * 4;
                int gn = n0 + j, gk = k0 + kk;
                float v = (gn < N && gk < K) ? B[(long long)gk * ldb + gn] : 0.f;
                if (bscale && gk < K) v *= bscale[gk];
                Bs[kk][j] = v;
            }
        } else {
            int kk = tid & 15, j0 = tid >> 4;
#pragma unroll
            for (int r = 0; r < 4; r++) {
                int j = j0 + r * 16;
                int gn = n0 + j, gk = k0 + kk;
                float v = (gn < N && gk < K) ? B[(long long)gn * ldb + gk] : 0.f;
                if (bscale && gk < K) v *= bscale[gk];
                Bs[kk][j] = v;
            }
        }
        __syncthreads();

#pragma unroll
        for (int kk = 0; kk < TBK; kk++) {
            float a[4], bv[4];
#pragma unroll
            for (int u = 0; u < 4; u++) a[u] = As[kk][ty * 4 + u];
#pragma unroll
            for (int v = 0; v < 4; v++) bv[v] = Bs[kk][tx * 4 + v];
#pragma unroll
            for (int u = 0; u < 4; u++)
#pragma unroll
                for (int v = 0; v < 4; v++) acc[u][v] += a[u] * bv[v];
        }
        __syncthreads();
    }

#pragma unroll
    for (int u = 0; u < 4; u++) {
        int gi = m0 + ty * 4 + u;
        if (gi >= M) continue;
#pragma unroll
        for (int v = 0; v < 4; v++) {
            int gj = n0 + tx * 4 + v;
            if (gj >= N) continue;
            float r = acc[u][v];
            long long idx = (long long)gi * ldc + gj;
            switch (epi) {
                case 0: C[idx] = alpha * r; break;
                case 1: C[idx] += alpha * r; break;
                case 2: C[idx] = expf(2.f * r - e1[gi] - e2[gj]); break;
                case 3: {
                    float t = alpha * e1[gi] * r;
                    if (e2) t += beta * e2[idx];
                    C[idx] = t;
                } break;
                case 5: C[idx] = e2[idx] - e1[gi] * r; break;
                case 6: C[idx] = fmaxf(r + e2[gj], 0.f); break;
            }
        }
    }
}

// ---------------------------------------------------------------------------
// Helper kernels
// ---------------------------------------------------------------------------
__global__ void sqnorm_kernel(const float* __restrict__ P, float* __restrict__ sq, int C)
{
    int row = blockIdx.x * (blockDim.x / 32) + (threadIdx.x >> 5);
    int lane = threadIdx.x & 31;
    if (row >= BB * NN) return;
    const float* p = P + (long long)row * C;
    float s = 0.f;
    for (int c = lane; c < C; c += 32) { float v = p[c]; s += v * v; }
#pragma unroll
    for (int o = 16; o; o >>= 1) s += __shfl_xor_sync(0xFFFFFFFFu, s, o);
    if (!lane) sq[row] = s;
}

__global__ void degree_kernel(const float* __restrict__ W,
                              float* __restrict__ dinv, float* __restrict__ din0)
{
    long long row = blockIdx.x;
    int col = (int)(row % NN);
    const float* w = W + row * NN;
    float s = 0.f, s0 = 0.f;
    for (int i = threadIdx.x; i < NN; i += 256) {
        float v = w[i];
        s += v;
        if (i != col) s0 += v;
    }
    __shared__ float sh[256], sh0[256];
    sh[threadIdx.x] = s;
    sh0[threadIdx.x] = s0;
    __syncthreads();
    for (int st = 128; st; st >>= 1) {
        if (threadIdx.x < st) {
            sh[threadIdx.x]  += sh[threadIdx.x + st];
            sh0[threadIdx.x] += sh0[threadIdx.x + st];
        }
        __syncthreads();
    }
    if (!threadIdx.x) {
        dinv[row] = rsqrtf(sh[0]);
        din0[row] = rsqrtf(sh0[0]);
    }
}

__global__ void zero_diag_kernel(float* __restrict__ W)
{
    int i = blockIdx.x * blockDim.x + threadIdx.x;
    if (i >= BB * NN) return;
    int b = i >> 10, n = i & 1023;
    W[(long long)b * NN * NN + (long long)n * NN + n] = 0.f;
}

// dst[row, 0:C] (row stride KC) = src[row, 0:C] (contiguous)
__global__ void copy_slice_kernel(const float* __restrict__ src, float* __restrict__ dst,
                                  int C, int KC, long long total)
{
    long long i = blockIdx.x * (long long)blockDim.x + threadIdx.x;
    if (i < total) {
        long long row = i / C;
        int c = (int)(i - row * C);
        dst[row * KC + c] = src[i];
    }
}

// sum slices, then Frobenius partial
__global__ void normsq_partial_kernel(const float* __restrict__ P, long long elems,
                                      int nsl, float* __restrict__ part)
{
    float s = 0.f;
    for (long long i = blockIdx.x * (long long)blockDim.x + threadIdx.x; i < elems;
         i += (long long)gridDim.x * blockDim.x) {
        float t = 0.f;
        for (int z = 0; z < nsl; z++) t += P[(long long)z * elems + i];
        s += t * t;
    }
    __shared__ float sh[256];
    sh[threadIdx.x] = s;
    __syncthreads();
    for (int st = 128; st; st >>= 1) {
        if (threadIdx.x < st) sh[threadIdx.x] += sh[threadIdx.x + st];
        __syncthreads();
    }
    if (!threadIdx.x) part[blockIdx.x] = sh[0];
}

__global__ void normsq_final_kernel(const float* __restrict__ part, float* __restrict__ r)
{
    __shared__ float sh[256];
    sh[threadIdx.x] = part[threadIdx.x];
    __syncthreads();
    for (int st = 128; st; st >>= 1) {
        if (threadIdx.x < st) sh[threadIdx.x] += sh[threadIdx.x + st];
        __syncthreads();
    }
    if (!threadIdx.x) *r = sqrtf(sh[0]);
}

__global__ void maxpool_kernel(const float* __restrict__ o3, float* __restrict__ pooled)
{
    int c = blockIdx.x * blockDim.x + threadIdx.x;
    int b = blockIdx.y;
    if (c >= 1024) return;
    const float* p = o3 + (long long)b * 1024 * 1024 + c;
    float m = p[0];
    for (int n = 1; n < 1024; n++) m = fmaxf(m, p[(long long)n * 1024]);
    pooled[b * 1024 + c] = m;
}

__global__ void fc_kernel(const float* __restrict__ in, const float* __restrict__ w,
                          const float* __restrict__ bias, float* __restrict__ out,
                          int K, int Nout, int do_relu)
{
    int j = blockIdx.x * blockDim.x + threadIdx.x;
    int b = blockIdx.y;
    if (j >= Nout) return;
    float s = bias[j];
    const float* ip = in + (long long)b * K;
    for (int k = 0; k < K; k++) s += ip[k] * w[(long long)k * Nout + j];
    if (do_relu) s = fmaxf(s, 0.f);
    out[(long long)b * Nout + j] = s;
}

// ---------------------------------------------------------------------------
// Host orchestration
// ---------------------------------------------------------------------------
static void launch_generic(const float* A, const float* B, float* C,
                           int M, int N, int K, int lda, int ldb, int ldc,
                           long long sA, long long sB, long long sC,
                           int tA, int tB,
                           const float* bs, long long sBS,
                           int epi, const float* e1, long long sE1,
                           const float* e2, long long sE2,
                           float alpha, float beta, int batch)
{
    dim3 grid((N + TBN - 1) / TBN, (M + TBM - 1) / TBM, batch);
    dim3 thr(16, 16);
    gemm_kernel<<<grid, thr>>>(A, B, C, M, N, K, lda, ldb, ldc, sA, sB, sC,
                               tA, tB, bs, sBS, epi, e1, sE1, e2, sE2, alpha, beta);
}

struct Bufs {
    float *W, *T, *Zall, *sq, *dinv, *din0, *part;
};

static void run_layer(const float* X, int Cin, int Cout, int Kcheb,
                      const float* Wk, const float* bias,
                      float* OUT, float* r_out, const Bufs& bf)
{
    const int KC = Kcheb * Cin;
    const long long sX = (long long)NN * Cin;
    const long long sZ = (long long)NN * KC;
    const long long sO = (long long)NN * Cout;
    const long long sW = (long long)NN * NN;

    // 1) squared norms
    sqnorm_kernel<<<(BB * NN) / 8, 256>>>(X, bf.sq, Cin);

    // 2) W = exp(2*X@X^T - sq_i - sq_j)
    if (Cin % 16 == 0) {
        dim3 g(NN / 128, NN / 128, BB);
        fgemm_kernel<128, 8, 2, 0, 1, 0><<<g, 256>>>(
            X, X, bf.W, Cin, Cin, Cin, NN, sX, sX, sW,
            nullptr, 0, bf.sq, NN, bf.sq, NN, 1.f, 0.f, 0);
    } else {
        launch_generic(X, X, bf.W, NN, NN, Cin, Cin, Cin, NN, sX, sX, sW,
                       0, 1, nullptr, 0, 2, bf.sq, NN, bf.sq, NN, 1.f, 0.f, BB);
    }

    // 3) degrees
    degree_kernel<<<BB * NN, 256>>>(bf.W, bf.dinv, bf.din0);

    // 4) Zall slice 0 = X
    copy_slice_kernel<<<(unsigned)(((long long)BB * NN * Cin + 255) / 256), 256>>>(
        X, bf.Zall, Cin, KC, (long long)BB * NN * Cin);

    // 5) Chebyshev recursion into Zall slices 1..Kcheb-1
    for (int k = 1; k < Kcheb; k++) {
        float* Ck = bf.Zall + (long long)k * Cin;
        const float* Bk = bf.Zall + (long long)(k - 1) * Cin;
        const float* Ek = (k >= 2) ? (bf.Zall + (long long)(k - 2) * Cin) : nullptr;
        float alpha = (k == 1) ? -1.f : -2.f;
        if (Cin == 128) {
            dim3 g(Cin / 64, NN / 128, BB);
            fgemm_kernel<64, 4, 3, 0, 0, 1><<<g, 256>>>(
                bf.W, Bk, Ck, NN, NN, KC, KC, sW, sZ, sZ,
                bf.dinv, NN, bf.dinv, NN, Ek, sZ, alpha, -1.f, 0);
        } else if (Cin % 128 == 0) {
            dim3 g(Cin / 128, NN / 128, BB);
            fgemm_kernel<128, 8, 3, 0, 0, 1><<<g, 256>>>(
                bf.W, Bk, Ck, NN, NN, KC, KC, sW, sZ, sZ,
                bf.dinv, NN, bf.dinv, NN, Ek, sZ, alpha, -1.f, 0);
        } else {
            launch_generic(bf.W, Bk, Ck, NN, Cin, NN, NN, KC, KC, sW, sZ, sZ,
                           0, 0, bf.dinv, NN, 3, bf.dinv, NN, Ek, sZ,
                           alpha, -1.f, BB);
        }
    }

    // 6) OUT = relu(Zall @ Wk_flat + bias)  (fused combine, EPI 6)
    if (KC % 16 == 0 && Cout % 128 == 0) {
        dim3 g(Cout / 128, NN / 128, BB);
        fgemm_kernel<128, 8, 6, 0, 0, 0><<<g, 256>>>(
            bf.Zall, Wk, OUT, KC, KC, Cout, Cout, sZ, 0, sO,
            nullptr, 0, nullptr, 0, bias, 0, 1.f, 0.f, 0);
    } else {
        launch_generic(bf.Zall, Wk, OUT, NN, Cout, KC, KC, Cout, Cout, sZ, 0, sO,
                       0, 0, nullptr, 0, 6, nullptr, 0, bias, 0, 1.f, 0.f, BB);
    }

    // 7) reg: zero diag, T = out - d0 .* (W0 @ (d0 .* out))
    zero_diag_kernel<<<(BB * NN + 255) / 256, 256>>>(bf.W);
    {
        dim3 g(Cout / 128, NN / 128, BB);
        fgemm_kernel<128, 8, 5, 0, 0, 1><<<g, 256>>>(
            bf.W, OUT, bf.T, NN, NN, Cout, Cout, sW, sO, sO,
            bf.din0, NN, bf.din0, NN, OUT, sO, 1.f, 0.f, 0);
    }

    // 8) M partials: per (batch, K-chunk) slice of out^T @ T into g_W (dead now)
    int splitLog = (Cout == 128) ? 3 : (Cout == 512) ? 1 : 0;
    int chunkK = NN >> splitLog;
    int nsl = BB << splitLog;
    {
        dim3 g(Cout / 128, Cout / 128, nsl);
        fgemm_kernel<128, 8, 0, 1, 0, 0><<<g, 256>>>(
            OUT, bf.T, bf.W, chunkK, Cout, Cout, Cout,
            sO, sO, (long long)Cout * Cout,
            nullptr, 0, nullptr, 0, nullptr, 0, 1.f, 0.f, splitLog);
    }

    // 9) r = ||sum_z M_z||_F
    normsq_partial_kernel<<<256, 256>>>(bf.W, (long long)Cout * Cout, nsl, bf.part);
    normsq_final_kernel<<<1, 256>>>(bf.part, r_out);
}

extern "C" void kernel_launch(void* const* d_in, const int* in_sizes, int n_in,
                              void* d_out, int out_size)
{
    (void)in_sizes; (void)out_size;
    const float* x = (const float*)d_in[0];
    int base = n_in - 12;
    const float* w1  = (const float*)d_in[base + 0];
    const float* b1  = (const float*)d_in[base + 1];
    const float* w2  = (const float*)d_in[base + 2];
    const float* b2  = (const float*)d_in[base + 3];
    const float* w3  = (const float*)d_in[base + 4];
    const float* b3  = (const float*)d_in[base + 5];
    const float* fw1 = (const float*)d_in[base + 6];
    const float* fb1 = (const float*)d_in[base + 7];
    const float* fw2 = (const float*)d_in[base + 8];
    const float* fb2 = (const float*)d_in[base + 9];
    const float* fw3 = (const float*)d_in[base + 10];
    const float* fb3 = (const float*)d_in[base + 11];
    float* out = (float*)d_out;

    Bufs bf;
    float *o1, *o2, *o3, *pool, *h1, *h2;
    cudaGetSymbolAddress((void**)&bf.W,    g_W);
    cudaGetSymbolAddress((void**)&bf.T,    g_T);
    cudaGetSymbolAddress((void**)&bf.Zall, g_Zall);
    cudaGetSymbolAddress((void**)&bf.sq,   g_sq);
    cudaGetSymbolAddress((void**)&bf.dinv, g_dinv);
    cudaGetSymbolAddress((void**)&bf.din0, g_din0);
    cudaGetSymbolAddress((void**)&bf.part, g_part);
    cudaGetSymbolAddress((void**)&o1,      g_out1);
    cudaGetSymbolAddress((void**)&o2,      g_out2);
    cudaGetSymbolAddress((void**)&o3,      g_out3);
    cudaGetSymbolAddress((void**)&pool,    g_pool);
    cudaGetSymbolAddress((void**)&h1,      g_h1);
    cudaGetSymbolAddress((void**)&h2,      g_h2);

    run_layer(x,  6,   128,  6, w1, b1, o1, out + 160, bf);
    run_layer(o1, 128, 512,  5, w2, b2, o2, out + 161, bf);
    run_layer(o2, 512, 1024, 3, w3, b3, o3, out + 162, bf);

    {
        dim3 g(1024 / 256, BB);
        maxpool_kernel<<<g, 256>>>(o3, pool);
    }
    {
        dim3 g1((512 + 127) / 128, BB);
        fc_kernel<<<g1, 128>>>(pool, fw1, fb1, h1, 1024, 512, 1);
        dim3 g2(1, BB);
        fc_kernel<<<g2, 128>>>(h1, fw2, fb2, h2, 512, 128, 1);
        fc_kernel<<<g2, 128>>>(h2, fw3, fb3, out, 128, 10, 0);
    }
}

// round 14
// speedup vs baseline: 3.4090x; 1.5421x over previous
#include <cuda_runtime.h>
#include <cuda_bf16.h>
#include <math.h>
#include <stdint.h>

#define BB 16
#define NN 1024
#define KCMAX 1536

// fp32 scratch
__device__ __align__(256) float g_W   [BB * NN * NN];
__device__ __align__(256) float g_T   [BB * NN * 1024];
__device__ __align__(256) float g_out1[BB * NN * 128];
__device__ __align__(256) float g_out2[BB * NN * 512];
__device__ __align__(256) float g_out3[BB * NN * 1024];
__device__ __align__(256) float g_Zall[BB * NN * KCMAX];
__device__ float g_sq  [BB * NN];
__device__ float g_dinv[BB * NN];
__device__ float g_din0[BB * NN];
__device__ float g_mu  [BB * 512];
__device__ float g_part[256];
__device__ float g_pool[BB * 1024];
__device__ float g_h1  [BB * 512];
__device__ float g_h2  [BB * 128];

// bf16 hi/lo scratch
__device__ __align__(256) __nv_bfloat16 g_Wh[BB*NN*NN], g_Wl[BB*NN*NN];
__device__ __align__(256) __nv_bfloat16 g_Ah[BB*NN*KCMAX], g_Al[BB*NN*KCMAX];
__device__ __align__(256) __nv_bfloat16 g_Bh[BB*NN*NN], g_Bl[BB*NN*NN];
__device__ __align__(256) __nv_bfloat16 g_Ch[BB*NN*NN], g_Cl[BB*NN*NN];

// ---------------- warp-MMA helpers (baseline PTX, sm_80+) ----------------
__device__ __forceinline__ uint32_t smem_u32(const void* p) {
    uint32_t a;
    asm("{ .reg .u64 t; cvta.to.shared.u64 t, %1; cvt.u32.u64 %0, t; }" : "=r"(a) : "l"(p));
    return a;
}
__device__ __forceinline__ void ldsm4(unsigned* r, uint32_t addr) {
    asm volatile("ldmatrix.sync.aligned.m8n8.x4.shared.b16 {%0,%1,%2,%3}, [%4];"
        : "=r"(r[0]), "=r"(r[1]), "=r"(r[2]), "=r"(r[3]) : "r"(addr));
}
__device__ __forceinline__ void mma16816(float* d, const unsigned* a, const unsigned* b) {
    asm volatile(
        "mma.sync.aligned.m16n8k16.row.col.f32.bf16.bf16.f32 "
        "{%0,%1,%2,%3}, {%4,%5,%6,%7}, {%8,%9}, {%0,%1,%2,%3};"
        : "+f"(d[0]), "+f"(d[1]), "+f"(d[2]), "+f"(d[3])
        : "r"(a[0]), "r"(a[1]), "r"(a[2]), "r"(a[3]), "r"(b[0]), "r"(b[1]));
}

// ---------------------------------------------------------------------------
// bf16x3 warp-MMA GEMM: C = epi(A @ B^T). A[M,K], B[N,K] K-major bf16 hi/lo.
// M%128, N%128, K%32, ld%8, 16B-aligned bases. acc = Ah*Bh + Ah*Bl + Al*Bh.
//  EPI: 0 C=alpha*acc | 2 C=exp(2acc-e1[i]-e2[j]) (+Oh/Ol bf16 split out)
//       3 C=alpha*e1[i]*acc (+beta*e2[idx] if e2) | 5 C=e2[idx]-e1[i]*acc
//       6 C=relu(acc+e2[j])
// smem: 4 parts (Ah,Al,Bh,Bl) x 128 rows x 32 bf16 (64B rows), 16B-seg XOR
// swizzle: seg' = seg ^ ((row>>1)&3).
// ---------------------------------------------------------------------------
template<int EPI>
__global__ __launch_bounds__(256, 2)
void mmagemm_kernel(const __nv_bfloat16* __restrict__ Ah, const __nv_bfloat16* __restrict__ Al,
                    const __nv_bfloat16* __restrict__ Bh, const __nv_bfloat16* __restrict__ Bl,
                    float* __restrict__ C, int K, int ldA, int ldB, int ldC,
                    long long sA, long long sB, long long sC,
                    const float* __restrict__ e1, long long sE1,
                    const float* __restrict__ e2, long long sE2,
                    __nv_bfloat16* __restrict__ Oh, __nv_bfloat16* __restrict__ Ol,
                    float alpha, float beta)
{
    __shared__ __align__(16) __nv_bfloat16 sm[4 * 128 * 32];

    const int z = blockIdx.z;
    const int m0 = blockIdx.y * 128, n0 = blockIdx.x * 128;

    Ah += z * sA + (long long)m0 * ldA;
    Al += z * sA + (long long)m0 * ldA;
    Bh += z * sB + (long long)n0 * ldB;
    Bl += z * sB + (long long)n0 * ldB;
    C += z * sC;
    if (EPI == 2) { Oh += z * sC; Ol += z * sC; }
    if (e1) e1 += z * sE1;
    if (e2) e2 += z * sE2;

    const int tid = threadIdx.x, lane = tid & 31, wid = tid >> 5;
    const int mw = wid & 3, nw = wid >> 2;   // warp tile: rows mw*32, cols nw*64
    const uint32_t smb = smem_u32(sm);

    float acc[2][8][4];
#pragma unroll
    for (int a = 0; a < 2; a++)
#pragma unroll
        for (int b = 0; b < 8; b++)
#pragma unroll
            for (int c = 0; c < 4; c++) acc[a][b][c] = 0.f;

    for (int k0 = 0; k0 < K; k0 += 32) {
        // stage 4 operand parts into smem (swizzled)
        {
            const __nv_bfloat16* srcs[4] = { Ah, Al, Bh, Bl };
#pragma unroll
            for (int p = 0; p < 4; p++) {
                const __nv_bfloat16* S = srcs[p];
                const int ldx = (p < 2) ? ldA : ldB;
#pragma unroll
                for (int i = 0; i < 2; i++) {
                    int u = tid * 2 + i;              // 0..511
                    int row = u >> 2, seg = u & 3;
                    uint4 v = *(const uint4*)(S + (long long)row * ldx + k0 + seg * 8);
                    int sp = seg ^ ((row >> 1) & 3);
                    *(uint4*)((char*)sm + p * 8192 + row * 64 + sp * 16) = v;
                }
            }
        }
        __syncthreads();

#pragma unroll
        for (int ks = 0; ks < 2; ks++) {
            unsigned aH[2][4], aL[2][4];
#pragma unroll
            for (int mt = 0; mt < 2; mt++) {
                int row = mw * 32 + mt * 16 + (lane & 15);
                int seg = ks * 2 + (lane >> 4);
                uint32_t off = row * 64 + ((seg ^ ((row >> 1) & 3)) * 16);
                ldsm4(aH[mt], smb + off);
                ldsm4(aL[mt], smb + 8192 + off);
            }
#pragma unroll
            for (int pr = 0; pr < 4; pr++) {
                int row = nw * 64 + pr * 16 + ((lane >> 4) << 3) + (lane & 7);
                int seg = ks * 2 + ((lane >> 3) & 1);
                uint32_t off = row * 64 + ((seg ^ ((row >> 1) & 3)) * 16);
                unsigned bh[4], bl[4];
                ldsm4(bh, smb + 16384 + off);
                ldsm4(bl, smb + 24576 + off);
#pragma unroll
                for (int mt = 0; mt < 2; mt++) {
                    mma16816(acc[mt][2 * pr],     aH[mt], bh);
                    mma16816(acc[mt][2 * pr],     aH[mt], bl);
                    mma16816(acc[mt][2 * pr],     aL[mt], bh);
                    mma16816(acc[mt][2 * pr + 1], aH[mt], bh + 2);
                    mma16816(acc[mt][2 * pr + 1], aH[mt], bl + 2);
                    mma16816(acc[mt][2 * pr + 1], aL[mt], bh + 2);
                }
            }
        }
        __syncthreads();
    }

    // epilogue: D fragment rows lane>>2 and +8, cols (lane&3)*2 and +1
#pragma unroll
    for (int mt = 0; mt < 2; mt++) {
        int gi0 = m0 + mw * 32 + mt * 16 + (lane >> 2);
#pragma unroll
        for (int nt = 0; nt < 8; nt++) {
            int gj = n0 + nw * 64 + nt * 8 + (lane & 3) * 2;
#pragma unroll
            for (int h = 0; h < 2; h++) {
                int gi = gi0 + h * 8;
                float v0 = acc[mt][nt][h * 2], v1 = acc[mt][nt][h * 2 + 1];
                long long idx = (long long)gi * ldC + gj;
                if (EPI == 0) {
                    C[idx] = alpha * v0; C[idx + 1] = alpha * v1;
                } else if (EPI == 2) {
                    float ei = e1[gi];
                    float w0 = expf(2.f * v0 - ei - e2[gj]);
                    float w1 = expf(2.f * v1 - ei - e2[gj + 1]);
                    C[idx] = w0; C[idx + 1] = w1;
                    __nv_bfloat16 h0 = __float2bfloat16(w0);
                    __nv_bfloat16 h1 = __float2bfloat16(w1);
                    Oh[idx] = h0; Oh[idx + 1] = h1;
                    Ol[idx] = __float2bfloat16(w0 - __bfloat162float(h0));
                    Ol[idx + 1] = __float2bfloat16(w1 - __bfloat162float(h1));
                } else if (EPI == 3) {
                    float s = alpha * e1[gi];
                    float t0 = s * v0, t1 = s * v1;
                    if (e2) { t0 += beta * e2[idx]; t1 += beta * e2[idx + 1]; }
                    C[idx] = t0; C[idx + 1] = t1;
                } else if (EPI == 5) {
                    float d = e1[gi];
                    C[idx] = e2[idx] - d * v0;
                    C[idx + 1] = e2[idx + 1] - d * v1;
                } else if (EPI == 6) {
                    C[idx] = fmaxf(v0 + e2[gj], 0.f);
                    C[idx + 1] = fmaxf(v1 + e2[gj + 1], 0.f);
                }
            }
        }
    }
}

// ---------------------------------------------------------------------------
// Generic fp32 SGEMM (bounds-checked) -- layer-1 conv path only.
// ---------------------------------------------------------------------------
#define TBM 64
#define TBN 64
#define TBK 16
__global__ void gemm_kernel(
    const float* __restrict__ A, const float* __restrict__ B, float* __restrict__ C,
    int M, int N, int K, int lda, int ldb, int ldc,
    long long sA, long long sB, long long sC, int transB,
    const float* __restrict__ bscale, long long sBS, int epi,
    const float* __restrict__ e1, long long sE1,
    const float* __restrict__ e2, long long sE2, float alpha, float beta)
{
    int b = blockIdx.z;
    A += (long long)b * sA; B += (long long)b * sB; C += (long long)b * sC;
    if (bscale) bscale += (long long)b * sBS;
    if (e1) e1 += (long long)b * sE1;
    if (e2) e2 += (long long)b * sE2;
    __shared__ float As[TBK][TBM], Bs[TBK][TBN];
    const int tx = threadIdx.x, ty = threadIdx.y;
    const int tid = ty * 16 + tx;
    const int m0 = blockIdx.y * TBM, n0 = blockIdx.x * TBN;
    float acc[4][4];
#pragma unroll
    for (int u = 0; u < 4; u++)
#pragma unroll
        for (int v = 0; v < 4; v++) acc[u][v] = 0.f;
    for (int k0 = 0; k0 < K; k0 += TBK) {
        {
            int kk = tid & 15, i0 = tid >> 4;
#pragma unroll
            for (int r = 0; r < 4; r++) {
                int i = i0 + r * 16, gm = m0 + i, gk = k0 + kk;
                As[kk][i] = (gm < M && gk < K) ? A[(long long)gm * lda + gk] : 0.f;
            }
        }
        if (!transB) {
            int j = tid & 63, kk0 = tid >> 6;
#pragma unroll
            for (int r = 0; r < 4; r++) {
                int kk = kk0 + r * 4, gn = n0 + j, gk = k0 + kk;
                float v = (gn < N && gk < K) ? B[(long long)gk * ldb + gn] : 0.f;
                if (bscale && gk < K) v *= bscale[gk];
                Bs[kk][j] = v;
            }
        } else {
            int kk = tid & 15, j0 = tid >> 4;
#pragma unroll
            for (int r = 0; r < 4; r++) {
                int j = j0 + r * 16, gn = n0 + j, gk = k0 + kk;
                float v = (gn < N && gk < K) ? B[(long long)gn * ldb + gk] : 0.f;
                if (bscale && gk < K) v *= bscale[gk];
                Bs[kk][j] = v;
            }
        }
        __syncthreads();
#pragma unroll
        for (int kk = 0; kk < TBK; kk++) {
            float a[4], bv[4];
#pragma unroll
            for (int u = 0; u < 4; u++) a[u] = As[kk][ty * 4 + u];
#pragma unroll
            for (int v = 0; v < 4; v++) bv[v] = Bs[kk][tx * 4 + v];
#pragma unroll
            for (int u = 0; u < 4; u++)
#pragma unroll
                for (int v = 0; v < 4; v++) acc[u][v] += a[u] * bv[v];
        }
        __syncthreads();
    }
#pragma unroll
    for (int u = 0; u < 4; u++) {
        int gi = m0 + ty * 4 + u;
        if (gi >= M) continue;
#pragma unroll
        for (int v = 0; v < 4; v++) {
            int gj = n0 + tx * 4 + v;
            if (gj >= N) continue;
            float r = acc[u][v];
            long long idx = (long long)gi * ldc + gj;
            switch (epi) {
                case 2: C[idx] = expf(2.f * r - e1[gi] - e2[gj]); break;
                case 3: {
                    float t = alpha * e1[gi] * r;
                    if (e2) t += beta * e2[idx];
                    C[idx] = t;
                } break;
                case 6: C[idx] = fmaxf(r + e2[gj], 0.f); break;
            }
        }
    }
}

// ---------------------------------------------------------------------------
// Helpers
// ---------------------------------------------------------------------------
__device__ __forceinline__ void bf_split(float v, __nv_bfloat16& h, __nv_bfloat16& l) {
    h = __float2bfloat16(v);
    l = __float2bfloat16(v - __bfloat162float(h));
}

__global__ void colmean_kernel(const float* __restrict__ X, float* __restrict__ mu, int C)
{
    int b = blockIdx.x, c = threadIdx.x;
    if (c >= C) return;
    const float* p = X + (long long)b * NN * C + c;
    float s = 0.f;
    for (int n = 0; n < NN; n++) s += p[(long long)n * C];
    mu[b * C + c] = s * (1.f / NN);
}

__global__ void sqnorm_kernel(const float* __restrict__ P, const float* __restrict__ mu,
                              float* __restrict__ sq, int C)
{
    int row = blockIdx.x * (blockDim.x / 32) + (threadIdx.x >> 5);
    int lane = threadIdx.x & 31;
    if (row >= BB * NN) return;
    const float* p = P + (long long)row * C;
    const float* m = mu ? mu + (row >> 10) * C : nullptr;
    float s = 0.f;
    for (int c = lane; c < C; c += 32) {
        float v = p[c];
        if (m) v -= m[c];
        s += v * v;
    }
#pragma unroll
    for (int o = 16; o; o >>= 1) s += __shfl_xor_sync(0xFFFFFFFFu, s, o);
    if (!lane) sq[row] = s;
}

__global__ void cvt_center_kernel(const float* __restrict__ X, const float* __restrict__ mu,
                                  __nv_bfloat16* __restrict__ dh, __nv_bfloat16* __restrict__ dl,
                                  int C, long long total)
{
    long long i = blockIdx.x * (long long)blockDim.x + threadIdx.x;
    if (i >= total) return;
    long long row = i / C;
    int c = (int)(i - row * C);
    float v = X[i] - mu[(row >> 10) * C + c];
    __nv_bfloat16 h, l;
    bf_split(v, h, l);
    dh[i] = h; dl[i] = l;
}

__global__ void cvt_flat_kernel(const float* __restrict__ src,
                                __nv_bfloat16* __restrict__ dh, __nv_bfloat16* __restrict__ dl,
                                long long n)
{
    long long i = blockIdx.x * (long long)blockDim.x + threadIdx.x;
    if (i >= n) return;
    __nv_bfloat16 h, l;
    bf_split(src[i], h, l);
    dh[i] = h; dl[i] = l;
}

__global__ void degree_kernel(const float* __restrict__ W,
                              float* __restrict__ dinv, float* __restrict__ din0)
{
    long long row = blockIdx.x;
    int col = (int)(row % NN);
    const float* w = W + row * NN;
    float s = 0.f, s0 = 0.f;
    for (int i = threadIdx.x; i < NN; i += 256) {
        float v = w[i];
        s += v;
        if (i != col) s0 += v;
    }
    __shared__ float sh[256], sh0[256];
    sh[threadIdx.x] = s; sh0[threadIdx.x] = s0;
    __syncthreads();
    for (int st = 128; st; st >>= 1) {
        if (threadIdx.x < st) { sh[threadIdx.x] += sh[threadIdx.x + st]; sh0[threadIdx.x] += sh0[threadIdx.x + st]; }
        __syncthreads();
    }
    if (!threadIdx.x) { dinv[row] = rsqrtf(sh[0]); din0[row] = rsqrtf(sh0[0]); }
}

__global__ void zero_diag_kernel(float* __restrict__ W,
                                 __nv_bfloat16* __restrict__ Wh, __nv_bfloat16* __restrict__ Wl)
{
    int i = blockIdx.x * blockDim.x + threadIdx.x;
    if (i >= BB * NN) return;
    int b = i >> 10, n = i & 1023;
    long long idx = (long long)b * NN * NN + (long long)n * NN + n;
    W[idx] = 0.f;
    if (Wh) { Wh[idx] = __float2bfloat16(0.f); Wl[idx] = __float2bfloat16(0.f); }
}

__global__ void copy_slice_kernel(const float* __restrict__ src, float* __restrict__ dst,
                                  int C, int KC, long long total)
{
    long long i = blockIdx.x * (long long)blockDim.x + threadIdx.x;
    if (i < total) {
        long long row = i / C;
        int c = (int)(i - row * C);
        dst[row * KC + c] = src[i];
    }
}

// fp32 slice [NN,C] -> strided bf16 split (dA, ldA) + optional transposed
// scaled bf16 (dB [C][NN], scale[b*NN + r])
__global__ void cvt_slice_kernel(const float* __restrict__ src, int ldS, long long sS,
    __nv_bfloat16* __restrict__ dAh, __nv_bfloat16* __restrict__ dAl, int ldA, long long sA,
    __nv_bfloat16* __restrict__ dBh, __nv_bfloat16* __restrict__ dBl, long long sB,
    const float* __restrict__ scale)
{
    __shared__ float t[32][33];
    int b = blockIdx.z;
    int r0 = blockIdx.x * 32, c0 = blockIdx.y * 32;
    src += (long long)b * sS; dAh += (long long)b * sA; dAl += (long long)b * sA;
    int tx = threadIdx.x, ty = threadIdx.y;
#pragma unroll
    for (int k = 0; k < 4; k++) {
        int r = r0 + ty + k * 8;
        float v = src[(long long)r * ldS + c0 + tx];
        __nv_bfloat16 h, l;
        bf_split(v, h, l);
        dAh[(long long)r * ldA + c0 + tx] = h;
        dAl[(long long)r * ldA + c0 + tx] = l;
        t[ty + k * 8][tx] = v;
    }
    if (dBh) {
        __syncthreads();
        dBh += (long long)b * sB; dBl += (long long)b * sB;
        const float* sc = scale ? scale + b * NN : nullptr;
#pragma unroll
        for (int k = 0; k < 4; k++) {
            int c = c0 + ty + k * 8;
            int r = r0 + tx;
            float v = t[tx][ty + k * 8];
            if (sc) v *= sc[r];
            __nv_bfloat16 h, l;
            bf_split(v, h, l);
            dBh[(long long)c * NN + r] = h;
            dBl[(long long)c * NN + r] = l;
        }
    }
}

// fp32 [R,C] -> transposed bf16 [C][R]: d1 (scaled by scale[b*R + r]), d2 optional unscaled
__global__ void cvt_trans2_kernel(const float* __restrict__ src, int R, int C, int ldS, long long sS,
    const float* __restrict__ scale,
    __nv_bfloat16* __restrict__ d1h, __nv_bfloat16* __restrict__ d1l,
    __nv_bfloat16* __restrict__ d2h, __nv_bfloat16* __restrict__ d2l, long long sD)
{
    __shared__ float t[32][33];
    int b = blockIdx.z;
    int r0 = blockIdx.x * 32, c0 = blockIdx.y * 32;
    src += (long long)b * sS;
    int tx = threadIdx.x, ty = threadIdx.y;
#pragma unroll
    for (int k = 0; k < 4; k++) {
        int r = r0 + ty + k * 8;
        t[ty + k * 8][tx] = src[(long long)r * ldS + c0 + tx];
    }
    __syncthreads();
    d1h += (long long)b * sD; d1l += (long long)b * sD;
    const float* sc = scale ? scale + (long long)b * R : nullptr;
#pragma unroll
    for (int k = 0; k < 4; k++) {
        int c = c0 + ty + k * 8;
        int r = r0 + tx;
        float v = t[tx][ty + k * 8];
        long long o = (long long)c * R + r;
        __nv_bfloat16 h, l;
        if (d2h) {
            bf_split(v, h, l);
            d2h[(long long)b * sD + o] = h;
            d2l[(long long)b * sD + o] = l;
        }
        if (sc) v *= sc[r];
        bf_split(v, h, l);
        d1h[o] = h; d1l[o] = l;
    }
}

__global__ void normsq_partial_kernel(const float* __restrict__ P, long long elems,
                                      int nsl, float* __restrict__ part)
{
    float s = 0.f;
    for (long long i = blockIdx.x * (long long)blockDim.x + threadIdx.x; i < elems;
         i += (long long)gridDim.x * blockDim.x) {
        float t = 0.f;
        for (int z = 0; z < nsl; z++) t += P[(long long)z * elems + i];
        s += t * t;
    }
    __shared__ float sh[256];
    sh[threadIdx.x] = s;
    __syncthreads();
    for (int st = 128; st; st >>= 1) {
        if (threadIdx.x < st) sh[threadIdx.x] += sh[threadIdx.x + st];
        __syncthreads();
    }
    if (!threadIdx.x) part[blockIdx.x] = sh[0];
}

__global__ void normsq_final_kernel(const float* __restrict__ part, float* __restrict__ r)
{
    __shared__ float sh[256];
    sh[threadIdx.x] = part[threadIdx.x];
    __syncthreads();
    for (int st = 128; st; st >>= 1) {
        if (threadIdx.x < st) sh[threadIdx.x] += sh[threadIdx.x + st];
        __syncthreads();
    }
    if (!threadIdx.x) *r = sqrtf(sh[0]);
}

__global__ void maxpool_kernel(const float* __restrict__ o3, float* __restrict__ pooled)
{
    int c = blockIdx.x * blockDim.x + threadIdx.x;
    int b = blockIdx.y;
    if (c >= 1024) return;
    const float* p = o3 + (long long)b * 1024 * 1024 + c;
    float m = p[0];
    for (int n = 1; n < 1024; n++) m = fmaxf(m, p[(long long)n * 1024]);
    pooled[b * 1024 + c] = m;
}

__global__ void fc_kernel(const float* __restrict__ in, const float* __restrict__ w,
                          const float* __restrict__ bias, float* __restrict__ out,
                          int K, int Nout, int do_relu)
{
    int j = blockIdx.x * blockDim.x + threadIdx.x;
    int b = blockIdx.y;
    if (j >= Nout) return;
    float s = bias[j];
    const float* ip = in + (long long)b * K;
    for (int k = 0; k < K; k++) s += ip[k] * w[(long long)k * Nout + j];
    if (do_relu) s = fmaxf(s, 0.f);
    out[(long long)b * Nout + j] = s;
}

// ---------------------------------------------------------------------------
// Host
// ---------------------------------------------------------------------------
typedef __nv_bfloat16 bf;
struct Bufs {
    float *W, *T, *Zall, *sq, *dinv, *din0, *mu, *part;
    bf *Wh, *Wl, *Ah, *Al, *Bh, *Bl, *Ch, *Cl;
};

static void mma_launch(int epi, int Nn, int Mm, int nb,
                       const bf* Ah, const bf* Al, const bf* Bh, const bf* Bl,
                       float* C, int K, int ldA, int ldB, int ldC,
                       long long sA, long long sB, long long sC,
                       const float* e1, long long sE1, const float* e2, long long sE2,
                       bf* Oh, bf* Ol, float alpha, float beta)
{
    dim3 g(Nn / 128, Mm / 128, nb);
    switch (epi) {
        case 0: mmagemm_kernel<0><<<g, 256>>>(Ah, Al, Bh, Bl, C, K, ldA, ldB, ldC,
                    sA, sB, sC, e1, sE1, e2, sE2, Oh, Ol, alpha, beta); break;
        case 2: mmagemm_kernel<2><<<g, 256>>>(Ah, Al, Bh, Bl, C, K, ldA, ldB, ldC,
                    sA, sB, sC, e1, sE1, e2, sE2, Oh, Ol, alpha, beta); break;
        case 3: mmagemm_kernel<3><<<g, 256>>>(Ah, Al, Bh, Bl, C, K, ldA, ldB, ldC,
                    sA, sB, sC, e1, sE1, e2, sE2, Oh, Ol, alpha, beta); break;
        case 5: mmagemm_kernel<5><<<g, 256>>>(Ah, Al, Bh, Bl, C, K, ldA, ldB, ldC,
                    sA, sB, sC, e1, sE1, e2, sE2, Oh, Ol, alpha, beta); break;
        case 6: mmagemm_kernel<6><<<g, 256>>>(Ah, Al, Bh, Bl, C, K, ldA, ldB, ldC,
                    sA, sB, sC, e1, sE1, e2, sE2, Oh, Ol, alpha, beta); break;
    }
}

// Shared reg + M + norm tail. Requires Wh/Wl diag-zeroed, din0 ready. Cout%128.
static void reg_tail_tc(float* OUT, int Cout, float* r_out, const Bufs& bf_)
{
    const long long sO = (long long)NN * Cout;
    {
        dim3 g(NN / 32, Cout / 32, BB);
        cvt_trans2_kernel<<<g, dim3(32, 8)>>>(OUT, NN, Cout, Cout, sO, bf_.din0,
            bf_.Bh, bf_.Bl, bf_.Ah, bf_.Al, (long long)Cout * NN);
    }
    // T = OUT - d0 .* (W0 @ (d0.*OUT))
    mma_launch(5, Cout, NN, BB, bf_.Wh, bf_.Wl, bf_.Bh, bf_.Bl, bf_.T, NN, NN, NN, Cout,
               (long long)NN * NN, (long long)Cout * NN, sO,
               bf_.din0, NN, OUT, sO, nullptr, nullptr, 0.f, 0.f);
    {
        dim3 g(NN / 32, Cout / 32, BB);
        cvt_trans2_kernel<<<g, dim3(32, 8)>>>(bf_.T, NN, Cout, Cout, sO, nullptr,
            bf_.Ch, bf_.Cl, nullptr, nullptr, (long long)Cout * NN);
    }
    // M partials per batch into g_W
    mma_launch(0, Cout, Cout, BB, bf_.Ah, bf_.Al, bf_.Ch, bf_.Cl, bf_.W, NN, NN, NN, Cout,
               (long long)Cout * NN, (long long)Cout * NN, (long long)Cout * Cout,
               nullptr, 0, nullptr, 0, nullptr, nullptr, 1.f, 0.f);
    normsq_partial_kernel<<<256, 256>>>(bf_.W, (long long)Cout * Cout, BB, bf_.part);
    normsq_final_kernel<<<1, 256>>>(bf_.part, r_out);
}

static void run_layer_tc(const float* X, int Cin, int Cout, int Kcheb,
                         const float* Wk, const float* bias,
                         float* OUT, float* r_out, const Bufs& bf_)
{
    const int KC = Kcheb * Cin;
    const long long sX = (long long)NN * Cin;
    const long long sZ = (long long)NN * KC;
    const long long sO = (long long)NN * Cout;
    const long long sW = (long long)NN * NN;

    // gram (mean-centered) -> W fp32 + Wh/Wl bf16 split
    colmean_kernel<<<BB, Cin>>>(X, bf_.mu, Cin);
    sqnorm_kernel<<<(BB * NN) / 8, 256>>>(X, bf_.mu, bf_.sq, Cin);
    cvt_center_kernel<<<(unsigned)((BB * sX + 255) / 256), 256>>>(X, bf_.mu, bf_.Bh, bf_.Bl,
                                                                  Cin, BB * sX);
    mma_launch(2, NN, NN, BB, bf_.Bh, bf_.Bl, bf_.Bh, bf_.Bl, bf_.W, Cin, Cin, Cin, NN,
               sX, sX, sW, bf_.sq, NN, bf_.sq, NN, bf_.Wh, bf_.Wl, 0.f, 0.f);
    degree_kernel<<<BB * NN, 256>>>(bf_.W, bf_.dinv, bf_.din0);

    // Zall slice 0 = X; A-side split + transposed-scaled B-side for cheb1
    copy_slice_kernel<<<(unsigned)((BB * sX + 255) / 256), 256>>>(X, bf_.Zall, Cin, KC, BB * sX);
    {
        dim3 g(NN / 32, Cin / 32, BB);
        cvt_slice_kernel<<<g, dim3(32, 8)>>>(bf_.Zall, KC, sZ, bf_.Ah, bf_.Al, KC, sZ,
                                             nullptr, nullptr, 0, nullptr);
        cvt_trans2_kernel<<<g, dim3(32, 8)>>>(bf_.Zall, NN, Cin, KC, sZ, bf_.dinv,
            bf_.Bh, bf_.Bl, nullptr, nullptr, (long long)Cin * NN);
    }
    // Chebyshev recursion
    for (int k = 1; k < Kcheb; k++) {
        float* Ck = bf_.Zall + (long long)k * Cin;
        const float* Ek = (k >= 2) ? (bf_.Zall + (long long)(k - 2) * Cin) : nullptr;
        float alpha = (k == 1) ? -1.f : -2.f;
        mma_launch(3, Cin, NN, BB, bf_.Wh, bf_.Wl, bf_.Bh, bf_.Bl, Ck, NN, NN, NN, KC,
                   sW, (long long)Cin * NN, sZ, bf_.dinv, NN, Ek, sZ,
                   nullptr, nullptr, alpha, -1.f);
        dim3 g(NN / 32, Cin / 32, BB);
        bool more = (k < Kcheb - 1);
        cvt_slice_kernel<<<g, dim3(32, 8)>>>(Ck, KC, sZ, bf_.Ah + (long long)k * Cin,
            bf_.Al + (long long)k * Cin, KC, sZ,
            more ? bf_.Bh : nullptr, more ? bf_.Bl : nullptr,
            (long long)Cin * NN, bf_.dinv);
    }
    // combine: Wk^T -> Ch/Cl; OUT = relu(Zall @ Wk + bias)
    {
        dim3 g(KC / 32, Cout / 32, 1);
        cvt_trans2_kernel<<<g, dim3(32, 8)>>>(Wk, KC, Cout, Cout, 0, nullptr,
            bf_.Ch, bf_.Cl, nullptr, nullptr, 0);
    }
    mma_launch(6, Cout, NN, BB, bf_.Ah, bf_.Al, bf_.Ch, bf_.Cl, OUT, KC, KC, KC, Cout,
               sZ, 0, sO, nullptr, 0, bias, 0, nullptr, nullptr, 0.f, 0.f);

    zero_diag_kernel<<<(BB * NN + 255) / 256, 256>>>(bf_.W, bf_.Wh, bf_.Wl);
    reg_tail_tc(OUT, Cout, r_out, bf_);
}

// Layer 1: fp32 conv path (Cin=6), then MMA reg tail.
static void run_layer1(const float* X, const float* Wk, const float* bias,
                       float* OUT, float* r_out, const Bufs& bf_)
{
    const int Cin = 6, Cout = 128, Kcheb = 6, KC = 36;
    const long long sX = (long long)NN * Cin;
    const long long sZ = (long long)NN * KC;
    const long long sO = (long long)NN * Cout;
    const long long sW = (long long)NN * NN;

    sqnorm_kernel<<<(BB * NN) / 8, 256>>>(X, nullptr, bf_.sq, Cin);
    {
        dim3 g(NN / TBN, NN / TBM, BB);
        gemm_kernel<<<g, dim3(16, 16)>>>(X, X, bf_.W, NN, NN, Cin, Cin, Cin, NN, sX, sX, sW,
            1, nullptr, 0, 2, bf_.sq, NN, bf_.sq, NN, 1.f, 0.f);
    }
    degree_kernel<<<BB * NN, 256>>>(bf_.W, bf_.dinv, bf_.din0);
    copy_slice_kernel<<<(unsigned)((BB * sX + 255) / 256), 256>>>(X, bf_.Zall, Cin, KC, BB * sX);
    for (int k = 1; k < Kcheb; k++) {
        float* Ck = bf_.Zall + (long long)k * Cin;
        const float* Bk = bf_.Zall + (long long)(k - 1) * Cin;
        const float* Ek = (k >= 2) ? (bf_.Zall + (long long)(k - 2) * Cin) : nullptr;
        float alpha = (k == 1) ? -1.f : -2.f;
        dim3 g(1, NN / TBM, BB);
        gemm_kernel<<<g, dim3(16, 16)>>>(bf_.W, Bk, Ck, NN, Cin, NN, NN, KC, KC, sW, sZ, sZ,
            0, bf_.dinv, NN, 3, bf_.dinv, NN, Ek, sZ, alpha, -1.f);
    }
    {
        dim3 g(Cout / TBN, NN / TBM, BB);
        gemm_kernel<<<g, dim3(16, 16)>>>(bf_.Zall, Wk, OUT, NN, Cout, KC, KC, Cout, Cout,
            sZ, 0, sO, 0, nullptr, 0, 6, nullptr, 0, bias, 0, 1.f, 0.f);
    }
    zero_diag_kernel<<<(BB * NN + 255) / 256, 256>>>(bf_.W, nullptr, nullptr);
    cvt_flat_kernel<<<(unsigned)(((long long)BB * sW + 255) / 256), 256>>>(bf_.W, bf_.Wh, bf_.Wl,
                                                                           (long long)BB * sW);
    reg_tail_tc(OUT, Cout, r_out, bf_);
}

extern "C" void kernel_launch(void* const* d_in, const int* in_sizes, int n_in,
                              void* d_out, int out_size)
{
    (void)in_sizes; (void)out_size;
    const float* x = (const float*)d_in[0];
    int base = n_in - 12;
    const float* w1  = (const float*)d_in[base + 0];
    const float* b1  = (const float*)d_in[base + 1];
    const float* w2  = (const float*)d_in[base + 2];
    const float* b2  = (const float*)d_in[base + 3];
    const float* w3  = (const float*)d_in[base + 4];
    const float* b3  = (const float*)d_in[base + 5];
    const float* fw1 = (const float*)d_in[base + 6];
    const float* fb1 = (const float*)d_in[base + 7];
    const float* fw2 = (const float*)d_in[base + 8];
    const float* fb2 = (const float*)d_in[base + 9];
    const float* fw3 = (const float*)d_in[base + 10];
    const float* fb3 = (const float*)d_in[base + 11];
    float* out = (float*)d_out;

    Bufs bf_;
    float *o1, *o2, *o3, *pool, *h1, *h2;
    cudaGetSymbolAddress((void**)&bf_.W,    g_W);
    cudaGetSymbolAddress((void**)&bf_.T,    g_T);
    cudaGetSymbolAddress((void**)&bf_.Zall, g_Zall);
    cudaGetSymbolAddress((void**)&bf_.sq,   g_sq);
    cudaGetSymbolAddress((void**)&bf_.dinv, g_dinv);
    cudaGetSymbolAddress((void**)&bf_.din0, g_din0);
    cudaGetSymbolAddress((void**)&bf_.mu,   g_mu);
    cudaGetSymbolAddress((void**)&bf_.part, g_part);
    cudaGetSymbolAddress((void**)&bf_.Wh,   g_Wh);
    cudaGetSymbolAddress((void**)&bf_.Wl,   g_Wl);
    cudaGetSymbolAddress((void**)&bf_.Ah,   g_Ah);
    cudaGetSymbolAddress((void**)&bf_.Al,   g_Al);
    cudaGetSymbolAddress((void**)&bf_.Bh,   g_Bh);
    cudaGetSymbolAddress((void**)&bf_.Bl,   g_Bl);
    cudaGetSymbolAddress((void**)&bf_.Ch,   g_Ch);
    cudaGetSymbolAddress((void**)&bf_.Cl,   g_Cl);
    cudaGetSymbolAddress((void**)&o1,   g_out1);
    cudaGetSymbolAddress((void**)&o2,   g_out2);
    cudaGetSymbolAddress((void**)&o3,   g_out3);
    cudaGetSymbolAddress((void**)&pool, g_pool);
    cudaGetSymbolAddress((void**)&h1,   g_h1);
    cudaGetSymbolAddress((void**)&h2,   g_h2);

    run_layer1(x, w1, b1, o1, out + 160, bf_);
    run_layer_tc(o1, 128, 512,  5, w2, b2, o2, out + 161, bf_);
    run_layer_tc(o2, 512, 1024, 3, w3, b3, o3, out + 162, bf_);

    {
        dim3 g(1024 / 256, BB);
        maxpool_kernel<<<g, 256>>>(o3, pool);
    }
    {
        dim3 g1((512 + 127) / 128, BB);
        fc_kernel<<<g1, 128>>>(pool, fw1, fb1, h1, 1024, 512, 1);
        dim3 g2(1, BB);
        fc_kernel<<<g2, 128>>>(h1, fw2, fb2, h2, 512, 128, 1);
        fc_kernel<<<g2, 128>>>(h2, fw3, fb3, out, 128, 10, 0);
    }
}

// round 15
// speedup vs baseline: 3.7778x; 1.1082x over previous
#include <cuda_runtime.h>
#include <cuda_bf16.h>
#include <math.h>
#include <stdint.h>

#define BB 16
#define NN 1024
#define KCMAX 1536

// fp32 scratch
__device__ __align__(256) float g_W   [BB * NN * NN];
__device__ __align__(256) float g_T   [BB * NN * 1024];
__device__ __align__(256) float g_out1[BB * NN * 128];
__device__ __align__(256) float g_out2[BB * NN * 512];
__device__ __align__(256) float g_out3[BB * NN * 1024];
__device__ __align__(256) float g_Zall[BB * NN * KCMAX];
__device__ float g_sq  [BB * NN];
__device__ float g_dinv[BB * NN];
__device__ float g_din0[BB * NN];
__device__ float g_mu  [BB * 512];
__device__ float g_part[256];
__device__ float g_pool[BB * 1024];
__device__ float g_h1  [BB * 512];
__device__ float g_h2  [BB * 128];

// bf16 hi/lo scratch
__device__ __align__(256) __nv_bfloat16 g_Wh[BB*NN*NN], g_Wl[BB*NN*NN];
__device__ __align__(256) __nv_bfloat16 g_Ah[BB*NN*KCMAX], g_Al[BB*NN*KCMAX];
__device__ __align__(256) __nv_bfloat16 g_Bh[BB*NN*NN], g_Bl[BB*NN*NN];
__device__ __align__(256) __nv_bfloat16 g_Ch[BB*NN*NN], g_Cl[BB*NN*NN];

// ---------------- warp-MMA helpers (baseline PTX, sm_80+) ----------------
__device__ __forceinline__ uint32_t smem_u32(const void* p) {
    uint32_t a;
    asm("{ .reg .u64 t; cvta.to.shared.u64 t, %1; cvt.u32.u64 %0, t; }" : "=r"(a) : "l"(p));
    return a;
}
__device__ __forceinline__ void ldsm4(unsigned* r, uint32_t addr) {
    asm volatile("ldmatrix.sync.aligned.m8n8.x4.shared.b16 {%0,%1,%2,%3}, [%4];"
        : "=r"(r[0]), "=r"(r[1]), "=r"(r[2]), "=r"(r[3]) : "r"(addr));
}
__device__ __forceinline__ void mma16816(float* d, const unsigned* a, const unsigned* b) {
    asm volatile(
        "mma.sync.aligned.m16n8k16.row.col.f32.bf16.bf16.f32 "
        "{%0,%1,%2,%3}, {%4,%5,%6,%7}, {%8,%9}, {%0,%1,%2,%3};"
        : "+f"(d[0]), "+f"(d[1]), "+f"(d[2]), "+f"(d[3])
        : "r"(a[0]), "r"(a[1]), "r"(a[2]), "r"(a[3]), "r"(b[0]), "r"(b[1]));
}
__device__ __forceinline__ void cpasync16(uint32_t saddr, const void* gaddr) {
    asm volatile("cp.async.cg.shared.global [%0], [%1], 16;" :: "r"(saddr), "l"(gaddr));
}
__device__ __forceinline__ void cpasync_commit() {
    asm volatile("cp.async.commit_group;" ::: "memory");
}
__device__ __forceinline__ void cpasync_wait1() {
    asm volatile("cp.async.wait_group 1;" ::: "memory");
}
__device__ __forceinline__ void cpasync_wait0() {
    asm volatile("cp.async.wait_group 0;" ::: "memory");
}

// ---------------------------------------------------------------------------
// bf16x3 warp-MMA GEMM, cp.async double-buffered.
// C = epi(A @ B^T). A[M,K], B[N,K] K-major bf16 hi/lo.
// M%128, N%128, K%32, ld%8, 16B-aligned bases. acc = Ah*Bh + Ah*Bl + Al*Bh.
//  EPI: 0 C=alpha*acc | 2 C=exp(2acc-e1[i]-e2[j]) (+Oh/Ol bf16 split out)
//       3 C=alpha*e1[i]*acc (+beta*e2[idx] if e2) | 5 C=e2[idx]-e1[i]*acc
//       6 C=relu(acc+e2[j])
// smem per stage: 4 parts (Ah,Al,Bh,Bl) x 128 rows x 32 bf16 (64B rows),
// 16B-seg XOR swizzle seg' = seg ^ ((row>>1)&3). 2 stages = 64 KB dynamic.
// ---------------------------------------------------------------------------
#define MM_DSMEM (2 * 32768)

template<int EPI>
__global__ __launch_bounds__(256, 2)
void mmagemm_kernel(const __nv_bfloat16* __restrict__ Ah, const __nv_bfloat16* __restrict__ Al,
                    const __nv_bfloat16* __restrict__ Bh, const __nv_bfloat16* __restrict__ Bl,
                    float* __restrict__ C, int K, int ldA, int ldB, int ldC,
                    long long sA, long long sB, long long sC,
                    const float* __restrict__ e1, long long sE1,
                    const float* __restrict__ e2, long long sE2,
                    __nv_bfloat16* __restrict__ Oh, __nv_bfloat16* __restrict__ Ol,
                    float alpha, float beta)
{
    extern __shared__ __align__(16) char dsm[];

    const int z = blockIdx.z;
    const int m0 = blockIdx.y * 128, n0 = blockIdx.x * 128;

    Ah += z * sA + (long long)m0 * ldA;
    Al += z * sA + (long long)m0 * ldA;
    Bh += z * sB + (long long)n0 * ldB;
    Bl += z * sB + (long long)n0 * ldB;
    C += z * sC;
    if (EPI == 2) { Oh += z * sC; Ol += z * sC; }
    if (e1) e1 += z * sE1;
    if (e2) e2 += z * sE2;

    const int tid = threadIdx.x, lane = tid & 31, wid = tid >> 5;
    const int mw = wid & 3, nw = wid >> 2;   // warp tile: rows mw*32, cols nw*64
    const uint32_t smb = smem_u32(dsm);

    // per-thread staging coords (2 elements of 512 per part)
    const int u0 = tid * 2, u1 = tid * 2 + 1;
    const int row0 = u0 >> 2, seg0 = u0 & 3;
    const int row1 = u1 >> 2, seg1 = u1 & 3;
    const int sp0 = seg0 ^ ((row0 >> 1) & 3);
    const int sp1 = seg1 ^ ((row1 >> 1) & 3);
    const uint32_t so0 = row0 * 64 + sp0 * 16;
    const uint32_t so1 = row1 * 64 + sp1 * 16;

    auto LOADCH = [&](int k0, int buf) {
        const uint32_t base = smb + buf * 32768;
        const __nv_bfloat16* srcs[4] = { Ah, Al, Bh, Bl };
#pragma unroll
        for (int p = 0; p < 4; p++) {
            const __nv_bfloat16* S = srcs[p];
            const int ldx = (p < 2) ? ldA : ldB;
            cpasync16(base + p * 8192 + so0, S + (long long)row0 * ldx + k0 + seg0 * 8);
            cpasync16(base + p * 8192 + so1, S + (long long)row1 * ldx + k0 + seg1 * 8);
        }
    };

    float acc[2][8][4];
#pragma unroll
    for (int a = 0; a < 2; a++)
#pragma unroll
        for (int b = 0; b < 8; b++)
#pragma unroll
            for (int c = 0; c < 4; c++) acc[a][b][c] = 0.f;

    const int nch = K >> 5;
    LOADCH(0, 0);
    cpasync_commit();

    for (int ch = 0; ch < nch; ch++) {
        if (ch + 1 < nch) {
            LOADCH((ch + 1) << 5, (ch + 1) & 1);
            cpasync_commit();
            cpasync_wait1();
        } else {
            cpasync_wait0();
        }
        __syncthreads();

        const uint32_t sbase = smb + (ch & 1) * 32768;
#pragma unroll
        for (int ks = 0; ks < 2; ks++) {
            unsigned aH[2][4], aL[2][4];
#pragma unroll
            for (int mt = 0; mt < 2; mt++) {
                int row = mw * 32 + mt * 16 + (lane & 15);
                int seg = ks * 2 + (lane >> 4);
                uint32_t off = row * 64 + ((seg ^ ((row >> 1) & 3)) * 16);
                ldsm4(aH[mt], sbase + off);
                ldsm4(aL[mt], sbase + 8192 + off);
            }
#pragma unroll
            for (int pr = 0; pr < 4; pr++) {
                int row = nw * 64 + pr * 16 + ((lane >> 4) << 3) + (lane & 7);
                int seg = ks * 2 + ((lane >> 3) & 1);
                uint32_t off = row * 64 + ((seg ^ ((row >> 1) & 3)) * 16);
                unsigned bh[4], bl[4];
                ldsm4(bh, sbase + 16384 + off);
                ldsm4(bl, sbase + 24576 + off);
#pragma unroll
                for (int mt = 0; mt < 2; mt++) {
                    mma16816(acc[mt][2 * pr],     aH[mt], bh);
                    mma16816(acc[mt][2 * pr],     aH[mt], bl);
                    mma16816(acc[mt][2 * pr],     aL[mt], bh);
                    mma16816(acc[mt][2 * pr + 1], aH[mt], bh + 2);
                    mma16816(acc[mt][2 * pr + 1], aH[mt], bl + 2);
                    mma16816(acc[mt][2 * pr + 1], aL[mt], bh + 2);
                }
            }
        }
        __syncthreads();
    }

    // epilogue: D fragment rows lane>>2 and +8, cols (lane&3)*2 and +1
#pragma unroll
    for (int mt = 0; mt < 2; mt++) {
        int gi0 = m0 + mw * 32 + mt * 16 + (lane >> 2);
#pragma unroll
        for (int nt = 0; nt < 8; nt++) {
            int gj = n0 + nw * 64 + nt * 8 + (lane & 3) * 2;
#pragma unroll
            for (int h = 0; h < 2; h++) {
                int gi = gi0 + h * 8;
                float v0 = acc[mt][nt][h * 2], v1 = acc[mt][nt][h * 2 + 1];
                long long idx = (long long)gi * ldC + gj;
                if (EPI == 0) {
                    C[idx] = alpha * v0; C[idx + 1] = alpha * v1;
                } else if (EPI == 2) {
                    float ei = e1[gi];
                    float w0 = expf(2.f * v0 - ei - e2[gj]);
                    float w1 = expf(2.f * v1 - ei - e2[gj + 1]);
                    C[idx] = w0; C[idx + 1] = w1;
                    __nv_bfloat16 h0 = __float2bfloat16(w0);
                    __nv_bfloat16 h1 = __float2bfloat16(w1);
                    Oh[idx] = h0; Oh[idx + 1] = h1;
                    Ol[idx] = __float2bfloat16(w0 - __bfloat162float(h0));
                    Ol[idx + 1] = __float2bfloat16(w1 - __bfloat162float(h1));
                } else if (EPI == 3) {
                    float s = alpha * e1[gi];
                    float t0 = s * v0, t1 = s * v1;
                    if (e2) { t0 += beta * e2[idx]; t1 += beta * e2[idx + 1]; }
                    C[idx] = t0; C[idx + 1] = t1;
                } else if (EPI == 5) {
                    float d = e1[gi];
                    C[idx] = e2[idx] - d * v0;
                    C[idx + 1] = e2[idx + 1] - d * v1;
                } else if (EPI == 6) {
                    C[idx] = fmaxf(v0 + e2[gj], 0.f);
                    C[idx + 1] = fmaxf(v1 + e2[gj + 1], 0.f);
                }
            }
        }
    }
}

// ---------------------------------------------------------------------------
// Generic fp32 SGEMM (bounds-checked) -- layer-1 conv path only.
// ---------------------------------------------------------------------------
#define TBM 64
#define TBN 64
#define TBK 16
__global__ void gemm_kernel(
    const float* __restrict__ A, const float* __restrict__ B, float* __restrict__ C,
    int M, int N, int K, int lda, int ldb, int ldc,
    long long sA, long long sB, long long sC, int transB,
    const float* __restrict__ bscale, long long sBS, int epi,
    const float* __restrict__ e1, long long sE1,
    const float* __restrict__ e2, long long sE2, float alpha, float beta)
{
    int b = blockIdx.z;
    A += (long long)b * sA; B += (long long)b * sB; C += (long long)b * sC;
    if (bscale) bscale += (long long)b * sBS;
    if (e1) e1 += (long long)b * sE1;
    if (e2) e2 += (long long)b * sE2;
    __shared__ float As[TBK][TBM], Bs[TBK][TBN];
    const int tx = threadIdx.x, ty = threadIdx.y;
    const int tid = ty * 16 + tx;
    const int m0 = blockIdx.y * TBM, n0 = blockIdx.x * TBN;
    float acc[4][4];
#pragma unroll
    for (int u = 0; u < 4; u++)
#pragma unroll
        for (int v = 0; v < 4; v++) acc[u][v] = 0.f;
    for (int k0 = 0; k0 < K; k0 += TBK) {
        {
            int kk = tid & 15, i0 = tid >> 4;
#pragma unroll
            for (int r = 0; r < 4; r++) {
                int i = i0 + r * 16, gm = m0 + i, gk = k0 + kk;
                As[kk][i] = (gm < M && gk < K) ? A[(long long)gm * lda + gk] : 0.f;
            }
        }
        if (!transB) {
            int j = tid & 63, kk0 = tid >> 6;
#pragma unroll
            for (int r = 0; r < 4; r++) {
                int kk = kk0 + r * 4, gn = n0 + j, gk = k0 + kk;
                float v = (gn < N && gk < K) ? B[(long long)gk * ldb + gn] : 0.f;
                if (bscale && gk < K) v *= bscale[gk];
                Bs[kk][j] = v;
            }
        } else {
            int kk = tid & 15, j0 = tid >> 4;
#pragma unroll
            for (int r = 0; r < 4; r++) {
                int j = j0 + r * 16, gn = n0 + j, gk = k0 + kk;
                float v = (gn < N && gk < K) ? B[(long long)gn * ldb + gk] : 0.f;
                if (bscale && gk < K) v *= bscale[gk];
                Bs[kk][j] = v;
            }
        }
        __syncthreads();
#pragma unroll
        for (int kk = 0; kk < TBK; kk++) {
            float a[4], bv[4];
#pragma unroll
            for (int u = 0; u < 4; u++) a[u] = As[kk][ty * 4 + u];
#pragma unroll
            for (int v = 0; v < 4; v++) bv[v] = Bs[kk][tx * 4 + v];
#pragma unroll
            for (int u = 0; u < 4; u++)
#pragma unroll
                for (int v = 0; v < 4; v++) acc[u][v] += a[u] * bv[v];
        }
        __syncthreads();
    }
#pragma unroll
    for (int u = 0; u < 4; u++) {
        int gi = m0 + ty * 4 + u;
        if (gi >= M) continue;
#pragma unroll
        for (int v = 0; v < 4; v++) {
            int gj = n0 + tx * 4 + v;
            if (gj >= N) continue;
            float r = acc[u][v];
            long long idx = (long long)gi * ldc + gj;
            switch (epi) {
                case 2: C[idx] = expf(2.f * r - e1[gi] - e2[gj]); break;
                case 3: {
                    float t = alpha * e1[gi] * r;
                    if (e2) t += beta * e2[idx];
                    C[idx] = t;
                } break;
                case 6: C[idx] = fmaxf(r + e2[gj], 0.f); break;
            }
        }
    }
}

// ---------------------------------------------------------------------------
// Helpers
// ---------------------------------------------------------------------------
__device__ __forceinline__ void bf_split(float v, __nv_bfloat16& h, __nv_bfloat16& l) {
    h = __float2bfloat16(v);
    l = __float2bfloat16(v - __bfloat162float(h));
}

__global__ void colmean_kernel(const float* __restrict__ X, float* __restrict__ mu, int C)
{
    int b = blockIdx.x, c = threadIdx.x;
    if (c >= C) return;
    const float* p = X + (long long)b * NN * C + c;
    float s = 0.f;
    for (int n = 0; n < NN; n++) s += p[(long long)n * C];
    mu[b * C + c] = s * (1.f / NN);
}

__global__ void sqnorm_kernel(const float* __restrict__ P, const float* __restrict__ mu,
                              float* __restrict__ sq, int C)
{
    int row = blockIdx.x * (blockDim.x / 32) + (threadIdx.x >> 5);
    int lane = threadIdx.x & 31;
    if (row >= BB * NN) return;
    const float* p = P + (long long)row * C;
    const float* m = mu ? mu + (row >> 10) * C : nullptr;
    float s = 0.f;
    for (int c = lane; c < C; c += 32) {
        float v = p[c];
        if (m) v -= m[c];
        s += v * v;
    }
#pragma unroll
    for (int o = 16; o; o >>= 1) s += __shfl_xor_sync(0xFFFFFFFFu, s, o);
    if (!lane) sq[row] = s;
}

__global__ void cvt_center_kernel(const float* __restrict__ X, const float* __restrict__ mu,
                                  __nv_bfloat16* __restrict__ dh, __nv_bfloat16* __restrict__ dl,
                                  int C, long long total)
{
    long long i = blockIdx.x * (long long)blockDim.x + threadIdx.x;
    if (i >= total) return;
    long long row = i / C;
    int c = (int)(i - row * C);
    float v = X[i] - mu[(row >> 10) * C + c];
    __nv_bfloat16 h, l;
    bf_split(v, h, l);
    dh[i] = h; dl[i] = l;
}

__global__ void cvt_flat_kernel(const float* __restrict__ src,
                                __nv_bfloat16* __restrict__ dh, __nv_bfloat16* __restrict__ dl,
                                long long n)
{
    long long i = blockIdx.x * (long long)blockDim.x + threadIdx.x;
    if (i >= n) return;
    __nv_bfloat16 h, l;
    bf_split(src[i], h, l);
    dh[i] = h; dl[i] = l;
}

__global__ void degree_kernel(const float* __restrict__ W,
                              float* __restrict__ dinv, float* __restrict__ din0)
{
    long long row = blockIdx.x;
    int col = (int)(row % NN);
    const float* w = W + row * NN;
    float s = 0.f, s0 = 0.f;
    for (int i = threadIdx.x; i < NN; i += 256) {
        float v = w[i];
        s += v;
        if (i != col) s0 += v;
    }
    __shared__ float sh[256], sh0[256];
    sh[threadIdx.x] = s; sh0[threadIdx.x] = s0;
    __syncthreads();
    for (int st = 128; st; st >>= 1) {
        if (threadIdx.x < st) { sh[threadIdx.x] += sh[threadIdx.x + st]; sh0[threadIdx.x] += sh0[threadIdx.x + st]; }
        __syncthreads();
    }
    if (!threadIdx.x) { dinv[row] = rsqrtf(sh[0]); din0[row] = rsqrtf(sh0[0]); }
}

__global__ void zero_diag_kernel(float* __restrict__ W,
                                 __nv_bfloat16* __restrict__ Wh, __nv_bfloat16* __restrict__ Wl)
{
    int i = blockIdx.x * blockDim.x + threadIdx.x;
    if (i >= BB * NN) return;
    int b = i >> 10, n = i & 1023;
    long long idx = (long long)b * NN * NN + (long long)n * NN + n;
    W[idx] = 0.f;
    if (Wh) { Wh[idx] = __float2bfloat16(0.f); Wl[idx] = __float2bfloat16(0.f); }
}

__global__ void copy_slice_kernel(const float* __restrict__ src, float* __restrict__ dst,
                                  int C, int KC, long long total)
{
    long long i = blockIdx.x * (long long)blockDim.x + threadIdx.x;
    if (i < total) {
        long long row = i / C;
        int c = (int)(i - row * C);
        dst[row * KC + c] = src[i];
    }
}

// fp32 slice [NN,C] -> strided bf16 split (dA, ldA) + optional transposed
// scaled bf16 (dB [C][NN], scale[b*NN + r])
__global__ void cvt_slice_kernel(const float* __restrict__ src, int ldS, long long sS,
    __nv_bfloat16* __restrict__ dAh, __nv_bfloat16* __restrict__ dAl, int ldA, long long sA,
    __nv_bfloat16* __restrict__ dBh, __nv_bfloat16* __restrict__ dBl, long long sB,
    const float* __restrict__ scale)
{
    __shared__ float t[32][33];
    int b = blockIdx.z;
    int r0 = blockIdx.x * 32, c0 = blockIdx.y * 32;
    src += (long long)b * sS; dAh += (long long)b * sA; dAl += (long long)b * sA;
    int tx = threadIdx.x, ty = threadIdx.y;
#pragma unroll
    for (int k = 0; k < 4; k++) {
        int r = r0 + ty + k * 8;
        float v = src[(long long)r * ldS + c0 + tx];
        __nv_bfloat16 h, l;
        bf_split(v, h, l);
        dAh[(long long)r * ldA + c0 + tx] = h;
        dAl[(long long)r * ldA + c0 + tx] = l;
        t[ty + k * 8][tx] = v;
    }
    if (dBh) {
        __syncthreads();
        dBh += (long long)b * sB; dBl += (long long)b * sB;
        const float* sc = scale ? scale + b * NN : nullptr;
#pragma unroll
        for (int k = 0; k < 4; k++) {
            int c = c0 + ty + k * 8;
            int r = r0 + tx;
            float v = t[tx][ty + k * 8];
            if (sc) v *= sc[r];
            __nv_bfloat16 h, l;
            bf_split(v, h, l);
            dBh[(long long)c * NN + r] = h;
            dBl[(long long)c * NN + r] = l;
        }
    }
}

// fp32 [R,C] -> transposed bf16 [C][R]: d1 (scaled by scale[b*R + r]), d2 optional unscaled
__global__ void cvt_trans2_kernel(const float* __restrict__ src, int R, int C, int ldS, long long sS,
    const float* __restrict__ scale,
    __nv_bfloat16* __restrict__ d1h, __nv_bfloat16* __restrict__ d1l,
    __nv_bfloat16* __restrict__ d2h, __nv_bfloat16* __restrict__ d2l, long long sD)
{
    __shared__ float t[32][33];
    int b = blockIdx.z;
    int r0 = blockIdx.x * 32, c0 = blockIdx.y * 32;
    src += (long long)b * sS;
    int tx = threadIdx.x, ty = threadIdx.y;
#pragma unroll
    for (int k = 0; k < 4; k++) {
        int r = r0 + ty + k * 8;
        t[ty + k * 8][tx] = src[(long long)r * ldS + c0 + tx];
    }
    __syncthreads();
    d1h += (long long)b * sD; d1l += (long long)b * sD;
    const float* sc = scale ? scale + (long long)b * R : nullptr;
#pragma unroll
    for (int k = 0; k < 4; k++) {
        int c = c0 + ty + k * 8;
        int r = r0 + tx;
        float v = t[tx][ty + k * 8];
        long long o = (long long)c * R + r;
        __nv_bfloat16 h, l;
        if (d2h) {
            bf_split(v, h, l);
            d2h[(long long)b * sD + o] = h;
            d2l[(long long)b * sD + o] = l;
        }
        if (sc) v *= sc[r];
        bf_split(v, h, l);
        d1h[o] = h; d1l[o] = l;
    }
}

__global__ void normsq_partial_kernel(const float* __restrict__ P, long long elems,
                                      int nsl, float* __restrict__ part)
{
    float s = 0.f;
    for (long long i = blockIdx.x * (long long)blockDim.x + threadIdx.x; i < elems;
         i += (long long)gridDim.x * blockDim.x) {
        float t = 0.f;
        for (int z = 0; z < nsl; z++) t += P[(long long)z * elems + i];
        s += t * t;
    }
    __shared__ float sh[256];
    sh[threadIdx.x] = s;
    __syncthreads();
    for (int st = 128; st; st >>= 1) {
        if (threadIdx.x < st) sh[threadIdx.x] += sh[threadIdx.x + st];
        __syncthreads();
    }
    if (!threadIdx.x) part[blockIdx.x] = sh[0];
}

__global__ void normsq_final_kernel(const float* __restrict__ part, float* __restrict__ r)
{
    __shared__ float sh[256];
    sh[threadIdx.x] = part[threadIdx.x];
    __syncthreads();
    for (int st = 128; st; st >>= 1) {
        if (threadIdx.x < st) sh[threadIdx.x] += sh[threadIdx.x + st];
        __syncthreads();
    }
    if (!threadIdx.x) *r = sqrtf(sh[0]);
}

__global__ void maxpool_kernel(const float* __restrict__ o3, float* __restrict__ pooled)
{
    int c = blockIdx.x * blockDim.x + threadIdx.x;
    int b = blockIdx.y;
    if (c >= 1024) return;
    const float* p = o3 + (long long)b * 1024 * 1024 + c;
    float m = p[0];
    for (int n = 1; n < 1024; n++) m = fmaxf(m, p[(long long)n * 1024]);
    pooled[b * 1024 + c] = m;
}

__global__ void fc_kernel(const float* __restrict__ in, const float* __restrict__ w,
                          const float* __restrict__ bias, float* __restrict__ out,
                          int K, int Nout, int do_relu)
{
    int j = blockIdx.x * blockDim.x + threadIdx.x;
    int b = blockIdx.y;
    if (j >= Nout) return;
    float s = bias[j];
    const float* ip = in + (long long)b * K;
    for (int k = 0; k < K; k++) s += ip[k] * w[(long long)k * Nout + j];
    if (do_relu) s = fmaxf(s, 0.f);
    out[(long long)b * Nout + j] = s;
}

// ---------------------------------------------------------------------------
// Host
// ---------------------------------------------------------------------------
typedef __nv_bfloat16 bf;
struct Bufs {
    float *W, *T, *Zall, *sq, *dinv, *din0, *mu, *part;
    bf *Wh, *Wl, *Ah, *Al, *Bh, *Bl, *Ch, *Cl;
};

static void mma_launch(int epi, int Nn, int Mm, int nb,
                       const bf* Ah, const bf* Al, const bf* Bh, const bf* Bl,
                       float* C, int K, int ldA, int ldB, int ldC,
                       long long sA, long long sB, long long sC,
                       const float* e1, long long sE1, const float* e2, long long sE2,
                       bf* Oh, bf* Ol, float alpha, float beta)
{
    dim3 g(Nn / 128, Mm / 128, nb);
    switch (epi) {
        case 0: mmagemm_kernel<0><<<g, 256, MM_DSMEM>>>(Ah, Al, Bh, Bl, C, K, ldA, ldB, ldC,
                    sA, sB, sC, e1, sE1, e2, sE2, Oh, Ol, alpha, beta); break;
        case 2: mmagemm_kernel<2><<<g, 256, MM_DSMEM>>>(Ah, Al, Bh, Bl, C, K, ldA, ldB, ldC,
                    sA, sB, sC, e1, sE1, e2, sE2, Oh, Ol, alpha, beta); break;
        case 3: mmagemm_kernel<3><<<g, 256, MM_DSMEM>>>(Ah, Al, Bh, Bl, C, K, ldA, ldB, ldC,
                    sA, sB, sC, e1, sE1, e2, sE2, Oh, Ol, alpha, beta); break;
        case 5: mmagemm_kernel<5><<<g, 256, MM_DSMEM>>>(Ah, Al, Bh, Bl, C, K, ldA, ldB, ldC,
                    sA, sB, sC, e1, sE1, e2, sE2, Oh, Ol, alpha, beta); break;
        case 6: mmagemm_kernel<6><<<g, 256, MM_DSMEM>>>(Ah, Al, Bh, Bl, C, K, ldA, ldB, ldC,
                    sA, sB, sC, e1, sE1, e2, sE2, Oh, Ol, alpha, beta); break;
    }
}

// Shared reg + M + norm tail. Requires Wh/Wl diag-zeroed, din0 ready. Cout%128.
static void reg_tail_tc(float* OUT, int Cout, float* r_out, const Bufs& bf_)
{
    const long long sO = (long long)NN * Cout;
    {
        dim3 g(NN / 32, Cout / 32, BB);
        cvt_trans2_kernel<<<g, dim3(32, 8)>>>(OUT, NN, Cout, Cout, sO, bf_.din0,
            bf_.Bh, bf_.Bl, bf_.Ah, bf_.Al, (long long)Cout * NN);
    }
    // T = OUT - d0 .* (W0 @ (d0.*OUT))
    mma_launch(5, Cout, NN, BB, bf_.Wh, bf_.Wl, bf_.Bh, bf_.Bl, bf_.T, NN, NN, NN, Cout,
               (long long)NN * NN, (long long)Cout * NN, sO,
               bf_.din0, NN, OUT, sO, nullptr, nullptr, 0.f, 0.f);
    {
        dim3 g(NN / 32, Cout / 32, BB);
        cvt_trans2_kernel<<<g, dim3(32, 8)>>>(bf_.T, NN, Cout, Cout, sO, nullptr,
            bf_.Ch, bf_.Cl, nullptr, nullptr, (long long)Cout * NN);
    }
    // M partials per batch into g_W
    mma_launch(0, Cout, Cout, BB, bf_.Ah, bf_.Al, bf_.Ch, bf_.Cl, bf_.W, NN, NN, NN, Cout,
               (long long)Cout * NN, (long long)Cout * NN, (long long)Cout * Cout,
               nullptr, 0, nullptr, 0, nullptr, nullptr, 1.f, 0.f);
    normsq_partial_kernel<<<256, 256>>>(bf_.W, (long long)Cout * Cout, BB, bf_.part);
    normsq_final_kernel<<<1, 256>>>(bf_.part, r_out);
}

static void run_layer_tc(const float* X, int Cin, int Cout, int Kcheb,
                         const float* Wk, const float* bias,
                         float* OUT, float* r_out, const Bufs& bf_)
{
    const int KC = Kcheb * Cin;
    const long long sX = (long long)NN * Cin;
    const long long sZ = (long long)NN * KC;
    const long long sO = (long long)NN * Cout;
    const long long sW = (long long)NN * NN;

    // gram (mean-centered) -> W fp32 + Wh/Wl bf16 split
    colmean_kernel<<<BB, Cin>>>(X, bf_.mu, Cin);
    sqnorm_kernel<<<(BB * NN) / 8, 256>>>(X, bf_.mu, bf_.sq, Cin);
    cvt_center_kernel<<<(unsigned)((BB * sX + 255) / 256), 256>>>(X, bf_.mu, bf_.Bh, bf_.Bl,
                                                                  Cin, BB * sX);
    mma_launch(2, NN, NN, BB, bf_.Bh, bf_.Bl, bf_.Bh, bf_.Bl, bf_.W, Cin, Cin, Cin, NN,
               sX, sX, sW, bf_.sq, NN, bf_.sq, NN, bf_.Wh, bf_.Wl, 0.f, 0.f);
    degree_kernel<<<BB * NN, 256>>>(bf_.W, bf_.dinv, bf_.din0);

    // Zall slice 0 = X; A-side split + transposed-scaled B-side for cheb1
    copy_slice_kernel<<<(unsigned)((BB * sX + 255) / 256), 256>>>(X, bf_.Zall, Cin, KC, BB * sX);
    {
        dim3 g(NN / 32, Cin / 32, BB);
        cvt_slice_kernel<<<g, dim3(32, 8)>>>(bf_.Zall, KC, sZ, bf_.Ah, bf_.Al, KC, sZ,
                                             nullptr, nullptr, 0, nullptr);
        cvt_trans2_kernel<<<g, dim3(32, 8)>>>(bf_.Zall, NN, Cin, KC, sZ, bf_.dinv,
            bf_.Bh, bf_.Bl, nullptr, nullptr, (long long)Cin * NN);
    }
    // Chebyshev recursion
    for (int k = 1; k < Kcheb; k++) {
        float* Ck = bf_.Zall + (long long)k * Cin;
        const float* Ek = (k >= 2) ? (bf_.Zall + (long long)(k - 2) * Cin) : nullptr;
        float alpha = (k == 1) ? -1.f : -2.f;
        mma_launch(3, Cin, NN, BB, bf_.Wh, bf_.Wl, bf_.Bh, bf_.Bl, Ck, NN, NN, NN, KC,
                   sW, (long long)Cin * NN, sZ, bf_.dinv, NN, Ek, sZ,
                   nullptr, nullptr, alpha, -1.f);
        dim3 g(NN / 32, Cin / 32, BB);
        bool more = (k < Kcheb - 1);
        cvt_slice_kernel<<<g, dim3(32, 8)>>>(Ck, KC, sZ, bf_.Ah + (long long)k * Cin,
            bf_.Al + (long long)k * Cin, KC, sZ,
            more ? bf_.Bh : nullptr, more ? bf_.Bl : nullptr,
            (long long)Cin * NN, bf_.dinv);
    }
    // combine: Wk^T -> Ch/Cl; OUT = relu(Zall @ Wk + bias)
    {
        dim3 g(KC / 32, Cout / 32, 1);
        cvt_trans2_kernel<<<g, dim3(32, 8)>>>(Wk, KC, Cout, Cout, 0, nullptr,
            bf_.Ch, bf_.Cl, nullptr, nullptr, 0);
    }
    mma_launch(6, Cout, NN, BB, bf_.Ah, bf_.Al, bf_.Ch, bf_.Cl, OUT, KC, KC, KC, Cout,
               sZ, 0, sO, nullptr, 0, bias, 0, nullptr, nullptr, 0.f, 0.f);

    zero_diag_kernel<<<(BB * NN + 255) / 256, 256>>>(bf_.W, bf_.Wh, bf_.Wl);
    reg_tail_tc(OUT, Cout, r_out, bf_);
}

// Layer 1: fp32 conv path (Cin=6), then MMA reg tail.
static void run_layer1(const float* X, const float* Wk, const float* bias,
                       float* OUT, float* r_out, const Bufs& bf_)
{
    const int Cin = 6, Cout = 128, Kcheb = 6, KC = 36;
    const long long sX = (long long)NN * Cin;
    const long long sZ = (long long)NN * KC;
    const long long sO = (long long)NN * Cout;
    const long long sW = (long long)NN * NN;

    sqnorm_kernel<<<(BB * NN) / 8, 256>>>(X, nullptr, bf_.sq, Cin);
    {
        dim3 g(NN / TBN, NN / TBM, BB);
        gemm_kernel<<<g, dim3(16, 16)>>>(X, X, bf_.W, NN, NN, Cin, Cin, Cin, NN, sX, sX, sW,
            1, nullptr, 0, 2, bf_.sq, NN, bf_.sq, NN, 1.f, 0.f);
    }
    degree_kernel<<<BB * NN, 256>>>(bf_.W, bf_.dinv, bf_.din0);
    copy_slice_kernel<<<(unsigned)((BB * sX + 255) / 256), 256>>>(X, bf_.Zall, Cin, KC, BB * sX);
    for (int k = 1; k < Kcheb; k++) {
        float* Ck = bf_.Zall + (long long)k * Cin;
        const float* Bk = bf_.Zall + (long long)(k - 1) * Cin;
        const float* Ek = (k >= 2) ? (bf_.Zall + (long long)(k - 2) * Cin) : nullptr;
        float alpha = (k == 1) ? -1.f : -2.f;
        dim3 g(1, NN / TBM, BB);
        gemm_kernel<<<g, dim3(16, 16)>>>(bf_.W, Bk, Ck, NN, Cin, NN, NN, KC, KC, sW, sZ, sZ,
            0, bf_.dinv, NN, 3, bf_.dinv, NN, Ek, sZ, alpha, -1.f);
    }
    {
        dim3 g(Cout / TBN, NN / TBM, BB);
        gemm_kernel<<<g, dim3(16, 16)>>>(bf_.Zall, Wk, OUT, NN, Cout, KC, KC, Cout, Cout,
            sZ, 0, sO, 0, nullptr, 0, 6, nullptr, 0, bias, 0, 1.f, 0.f);
    }
    zero_diag_kernel<<<(BB * NN + 255) / 256, 256>>>(bf_.W, nullptr, nullptr);
    cvt_flat_kernel<<<(unsigned)(((long long)BB * sW + 255) / 256), 256>>>(bf_.W, bf_.Wh, bf_.Wl,
                                                                           (long long)BB * sW);
    reg_tail_tc(OUT, Cout, r_out, bf_);
}

extern "C" void kernel_launch(void* const* d_in, const int* in_sizes, int n_in,
                              void* d_out, int out_size)
{
    (void)in_sizes; (void)out_size;
    cudaFuncSetAttribute(mmagemm_kernel<0>, cudaFuncAttributeMaxDynamicSharedMemorySize, MM_DSMEM);
    cudaFuncSetAttribute(mmagemm_kernel<2>, cudaFuncAttributeMaxDynamicSharedMemorySize, MM_DSMEM);
    cudaFuncSetAttribute(mmagemm_kernel<3>, cudaFuncAttributeMaxDynamicSharedMemorySize, MM_DSMEM);
    cudaFuncSetAttribute(mmagemm_kernel<5>, cudaFuncAttributeMaxDynamicSharedMemorySize, MM_DSMEM);
    cudaFuncSetAttribute(mmagemm_kernel<6>, cudaFuncAttributeMaxDynamicSharedMemorySize, MM_DSMEM);

    const float* x = (const float*)d_in[0];
    int base = n_in - 12;
    const float* w1  = (const float*)d_in[base + 0];
    const float* b1  = (const float*)d_in[base + 1];
    const float* w2  = (const float*)d_in[base + 2];
    const float* b2  = (const float*)d_in[base + 3];
    const float* w3  = (const float*)d_in[base + 4];
    const float* b3  = (const float*)d_in[base + 5];
    const float* fw1 = (const float*)d_in[base + 6];
    const float* fb1 = (const float*)d_in[base + 7];
    const float* fw2 = (const float*)d_in[base + 8];
    const float* fb2 = (const float*)d_in[base + 9];
    const float* fw3 = (const float*)d_in[base + 10];
    const float* fb3 = (const float*)d_in[base + 11];
    float* out = (float*)d_out;

    Bufs bf_;
    float *o1, *o2, *o3, *pool, *h1, *h2;
    cudaGetSymbolAddress((void**)&bf_.W,    g_W);
    cudaGetSymbolAddress((void**)&bf_.T,    g_T);
    cudaGetSymbolAddress((void**)&bf_.Zall, g_Zall);
    cudaGetSymbolAddress((void**)&bf_.sq,   g_sq);
    cudaGetSymbolAddress((void**)&bf_.dinv, g_dinv);
    cudaGetSymbolAddress((void**)&bf_.din0, g_din0);
    cudaGetSymbolAddress((void**)&bf_.mu,   g_mu);
    cudaGetSymbolAddress((void**)&bf_.part, g_part);
    cudaGetSymbolAddress((void**)&bf_.Wh,   g_Wh);
    cudaGetSymbolAddress((void**)&bf_.Wl,   g_Wl);
    cudaGetSymbolAddress((void**)&bf_.Ah,   g_Ah);
    cudaGetSymbolAddress((void**)&bf_.Al,   g_Al);
    cudaGetSymbolAddress((void**)&bf_.Bh,   g_Bh);
    cudaGetSymbolAddress((void**)&bf_.Bl,   g_Bl);
    cudaGetSymbolAddress((void**)&bf_.Ch,   g_Ch);
    cudaGetSymbolAddress((void**)&bf_.Cl,   g_Cl);
    cudaGetSymbolAddress((void**)&o1,   g_out1);
    cudaGetSymbolAddress((void**)&o2,   g_out2);
    cudaGetSymbolAddress((void**)&o3,   g_out3);
    cudaGetSymbolAddress((void**)&pool, g_pool);
    cudaGetSymbolAddress((void**)&h1,   g_h1);
    cudaGetSymbolAddress((void**)&h2,   g_h2);

    run_layer1(x, w1, b1, o1, out + 160, bf_);
    run_layer_tc(o1, 128, 512,  5, w2, b2, o2, out + 161, bf_);
    run_layer_tc(o2, 512, 1024, 3, w3, b3, o3, out + 162, bf_);

    {
        dim3 g(1024 / 256, BB);
        maxpool_kernel<<<g, 256>>>(o3, pool);
    }
    {
        dim3 g1((512 + 127) / 128, BB);
        fc_kernel<<<g1, 128>>>(pool, fw1, fb1, h1, 1024, 512, 1);
        dim3 g2(1, BB);
        fc_kernel<<<g2, 128>>>(h1, fw2, fb2, h2, 512, 128, 1);
        fc_kernel<<<g2, 128>>>(h2, fw3, fb3, out, 128, 10, 0);
    }
}

// round 16
// speedup vs baseline: 3.8297x; 1.0138x over previous
#include <cuda_runtime.h>
#include <cuda_bf16.h>
#include <math.h>
#include <stdint.h>

#define BB 16
#define NN 1024
#define KCMAX 1536

// fp32 scratch
__device__ __align__(256) float g_W   [BB * NN * NN];
__device__ __align__(256) float g_T   [BB * NN * 1024];
__device__ __align__(256) float g_out1[BB * NN * 128];
__device__ __align__(256) float g_out2[BB * NN * 512];
__device__ __align__(256) float g_out3[BB * NN * 1024];
__device__ __align__(256) float g_Zall[BB * NN * KCMAX];
__device__ float g_sq  [BB * NN];
__device__ float g_dinv[BB * NN];
__device__ float g_din0[BB * NN];
__device__ float g_mu  [BB * 512];
__device__ float g_part[256];
__device__ float g_pool[BB * 1024];
__device__ float g_h1  [BB * 512];
__device__ float g_h2  [BB * 128];

// bf16 hi/lo scratch
__device__ __align__(256) __nv_bfloat16 g_Wh[BB*NN*NN], g_Wl[BB*NN*NN];
__device__ __align__(256) __nv_bfloat16 g_Ah[BB*NN*KCMAX], g_Al[BB*NN*KCMAX];
__device__ __align__(256) __nv_bfloat16 g_Bh[BB*NN*NN], g_Bl[BB*NN*NN];
__device__ __align__(256) __nv_bfloat16 g_Ch[BB*NN*NN], g_Cl[BB*NN*NN];

// ---------------- warp-MMA helpers (baseline PTX, sm_80+) ----------------
__device__ __forceinline__ uint32_t smem_u32(const void* p) {
    uint32_t a;
    asm("{ .reg .u64 t; cvta.to.shared.u64 t, %1; cvt.u32.u64 %0, t; }" : "=r"(a) : "l"(p));
    return a;
}
__device__ __forceinline__ void ldsm4(unsigned* r, uint32_t addr) {
    asm volatile("ldmatrix.sync.aligned.m8n8.x4.shared.b16 {%0,%1,%2,%3}, [%4];"
        : "=r"(r[0]), "=r"(r[1]), "=r"(r[2]), "=r"(r[3]) : "r"(addr));
}
__device__ __forceinline__ void mma16816(float* d, const unsigned* a, const unsigned* b) {
    asm volatile(
        "mma.sync.aligned.m16n8k16.row.col.f32.bf16.bf16.f32 "
        "{%0,%1,%2,%3}, {%4,%5,%6,%7}, {%8,%9}, {%0,%1,%2,%3};"
        : "+f"(d[0]), "+f"(d[1]), "+f"(d[2]), "+f"(d[3])
        : "r"(a[0]), "r"(a[1]), "r"(a[2]), "r"(a[3]), "r"(b[0]), "r"(b[1]));
}
__device__ __forceinline__ void cpasync16(uint32_t saddr, const void* gaddr) {
    asm volatile("cp.async.cg.shared.global [%0], [%1], 16;" :: "r"(saddr), "l"(gaddr));
}
__device__ __forceinline__ void cpasync_commit() {
    asm volatile("cp.async.commit_group;" ::: "memory");
}
__device__ __forceinline__ void cpasync_wait1() {
    asm volatile("cp.async.wait_group 1;" ::: "memory");
}
__device__ __forceinline__ void cpasync_wait0() {
    asm volatile("cp.async.wait_group 0;" ::: "memory");
}

// ---------------------------------------------------------------------------
// bf16x3 warp-MMA GEMM, cp.async 3-stage pipelined (one barrier per chunk).
// C = epi(A @ B^T). A[M,K], B[N,K] K-major bf16 hi/lo.
// M%128, N%128, K%32, ld%8, 16B-aligned bases. acc = Ah*Bh + Ah*Bl + Al*Bh.
//  EPI: 0 C=alpha*acc | 2 C=exp(2acc-e1[i]-e2[j]) (+Oh/Ol bf16 split out)
//       3 C=alpha*e1[i]*acc (+beta*e2[idx] if e2) | 5 C=e2[idx]-e1[i]*acc
//       6 C=relu(acc+e2[j])
// smem per stage: 4 parts (Ah,Al,Bh,Bl) x 128 rows x 32 bf16 (64B rows),
// 16B-seg XOR swizzle seg' = seg ^ ((row>>1)&3). 3 stages = 96 KB dynamic.
// ---------------------------------------------------------------------------
#define MM_DSMEM (3 * 32768)

template<int EPI>
__global__ __launch_bounds__(256, 2)
void mmagemm_kernel(const __nv_bfloat16* __restrict__ Ah, const __nv_bfloat16* __restrict__ Al,
                    const __nv_bfloat16* __restrict__ Bh, const __nv_bfloat16* __restrict__ Bl,
                    float* __restrict__ C, int K, int ldA, int ldB, int ldC,
                    long long sA, long long sB, long long sC,
                    const float* __restrict__ e1, long long sE1,
                    const float* __restrict__ e2, long long sE2,
                    __nv_bfloat16* __restrict__ Oh, __nv_bfloat16* __restrict__ Ol,
                    float alpha, float beta)
{
    extern __shared__ __align__(16) char dsm[];

    const int z = blockIdx.z;
    const int m0 = blockIdx.y * 128, n0 = blockIdx.x * 128;

    Ah += z * sA + (long long)m0 * ldA;
    Al += z * sA + (long long)m0 * ldA;
    Bh += z * sB + (long long)n0 * ldB;
    Bl += z * sB + (long long)n0 * ldB;
    C += z * sC;
    if (EPI == 2) { Oh += z * sC; Ol += z * sC; }
    if (e1) e1 += z * sE1;
    if (e2) e2 += z * sE2;

    const int tid = threadIdx.x, lane = tid & 31, wid = tid >> 5;
    const int mw = wid & 3, nw = wid >> 2;   // warp tile: rows mw*32, cols nw*64
    const uint32_t smb = smem_u32(dsm);

    // per-thread staging coords (2 elements of 512 per part)
    const int u0 = tid * 2, u1 = tid * 2 + 1;
    const int row0 = u0 >> 2, seg0 = u0 & 3;
    const int row1 = u1 >> 2, seg1 = u1 & 3;
    const int sp0 = seg0 ^ ((row0 >> 1) & 3);
    const int sp1 = seg1 ^ ((row1 >> 1) & 3);
    const uint32_t so0 = row0 * 64 + sp0 * 16;
    const uint32_t so1 = row1 * 64 + sp1 * 16;

    auto LOADCH = [&](int k0, int buf) {
        const uint32_t base = smb + buf * 32768;
        const __nv_bfloat16* srcs[4] = { Ah, Al, Bh, Bl };
#pragma unroll
        for (int p = 0; p < 4; p++) {
            const __nv_bfloat16* S = srcs[p];
            const int ldx = (p < 2) ? ldA : ldB;
            cpasync16(base + p * 8192 + so0, S + (long long)row0 * ldx + k0 + seg0 * 8);
            cpasync16(base + p * 8192 + so1, S + (long long)row1 * ldx + k0 + seg1 * 8);
        }
    };

    float acc[2][8][4];
#pragma unroll
    for (int a = 0; a < 2; a++)
#pragma unroll
        for (int b = 0; b < 8; b++)
#pragma unroll
            for (int c = 0; c < 4; c++) acc[a][b][c] = 0.f;

    const int nch = K >> 5;
    LOADCH(0, 0);
    cpasync_commit();
    if (nch > 1) {
        LOADCH(32, 1);
        cpasync_commit();
    }

    int buf = 0;           // buffer holding chunk ch (cycles 0,1,2)
    for (int ch = 0; ch < nch; ch++) {
        if (ch + 1 < nch) cpasync_wait1(); else cpasync_wait0();
        __syncthreads();
        if (ch + 2 < nch) {
            int nb = buf + 2; if (nb >= 3) nb -= 3;
            LOADCH((ch + 2) << 5, nb);
            cpasync_commit();
        }

        const uint32_t sbase = smb + buf * 32768;
#pragma unroll
        for (int ks = 0; ks < 2; ks++) {
            unsigned aH[2][4], aL[2][4];
#pragma unroll
            for (int mt = 0; mt < 2; mt++) {
                int row = mw * 32 + mt * 16 + (lane & 15);
                int seg = ks * 2 + (lane >> 4);
                uint32_t off = row * 64 + ((seg ^ ((row >> 1) & 3)) * 16);
                ldsm4(aH[mt], sbase + off);
                ldsm4(aL[mt], sbase + 8192 + off);
            }
#pragma unroll
            for (int pr = 0; pr < 4; pr++) {
                int row = nw * 64 + pr * 16 + ((lane >> 4) << 3) + (lane & 7);
                int seg = ks * 2 + ((lane >> 3) & 1);
                uint32_t off = row * 64 + ((seg ^ ((row >> 1) & 3)) * 16);
                unsigned bh[4], bl[4];
                ldsm4(bh, sbase + 16384 + off);
                ldsm4(bl, sbase + 24576 + off);
#pragma unroll
                for (int mt = 0; mt < 2; mt++) {
                    mma16816(acc[mt][2 * pr],     aH[mt], bh);
                    mma16816(acc[mt][2 * pr],     aH[mt], bl);
                    mma16816(acc[mt][2 * pr],     aL[mt], bh);
                    mma16816(acc[mt][2 * pr + 1], aH[mt], bh + 2);
                    mma16816(acc[mt][2 * pr + 1], aH[mt], bl + 2);
                    mma16816(acc[mt][2 * pr + 1], aL[mt], bh + 2);
                }
            }
        }
        buf++; if (buf >= 3) buf = 0;
    }

    // epilogue: D fragment rows lane>>2 and +8, cols (lane&3)*2 and +1
#pragma unroll
    for (int mt = 0; mt < 2; mt++) {
        int gi0 = m0 + mw * 32 + mt * 16 + (lane >> 2);
#pragma unroll
        for (int nt = 0; nt < 8; nt++) {
            int gj = n0 + nw * 64 + nt * 8 + (lane & 3) * 2;
#pragma unroll
            for (int h = 0; h < 2; h++) {
                int gi = gi0 + h * 8;
                float v0 = acc[mt][nt][h * 2], v1 = acc[mt][nt][h * 2 + 1];
                long long idx = (long long)gi * ldC + gj;
                if (EPI == 0) {
                    C[idx] = alpha * v0; C[idx + 1] = alpha * v1;
                } else if (EPI == 2) {
                    float ei = e1[gi];
                    float w0 = __expf(2.f * v0 - ei - e2[gj]);
                    float w1 = __expf(2.f * v1 - ei - e2[gj + 1]);
                    C[idx] = w0; C[idx + 1] = w1;
                    __nv_bfloat16 h0 = __float2bfloat16(w0);
                    __nv_bfloat16 h1 = __float2bfloat16(w1);
                    Oh[idx] = h0; Oh[idx + 1] = h1;
                    Ol[idx] = __float2bfloat16(w0 - __bfloat162float(h0));
                    Ol[idx + 1] = __float2bfloat16(w1 - __bfloat162float(h1));
                } else if (EPI == 3) {
                    float s = alpha * e1[gi];
                    float t0 = s * v0, t1 = s * v1;
                    if (e2) { t0 += beta * e2[idx]; t1 += beta * e2[idx + 1]; }
                    C[idx] = t0; C[idx + 1] = t1;
                } else if (EPI == 5) {
                    float d = e1[gi];
                    C[idx] = e2[idx] - d * v0;
                    C[idx + 1] = e2[idx + 1] - d * v1;
                } else if (EPI == 6) {
                    C[idx] = fmaxf(v0 + e2[gj], 0.f);
                    C[idx + 1] = fmaxf(v1 + e2[gj + 1], 0.f);
                }
            }
        }
    }
}

// ---------------------------------------------------------------------------
// Generic fp32 SGEMM (bounds-checked) -- layer-1 conv path only.
// ---------------------------------------------------------------------------
#define TBM 64
#define TBN 64
#define TBK 16
__global__ void gemm_kernel(
    const float* __restrict__ A, const float* __restrict__ B, float* __restrict__ C,
    int M, int N, int K, int lda, int ldb, int ldc,
    long long sA, long long sB, long long sC, int transB,
    const float* __restrict__ bscale, long long sBS, int epi,
    const float* __restrict__ e1, long long sE1,
    const float* __restrict__ e2, long long sE2, float alpha, float beta)
{
    int b = blockIdx.z;
    A += (long long)b * sA; B += (long long)b * sB; C += (long long)b * sC;
    if (bscale) bscale += (long long)b * sBS;
    if (e1) e1 += (long long)b * sE1;
    if (e2) e2 += (long long)b * sE2;
    __shared__ float As[TBK][TBM], Bs[TBK][TBN];
    const int tx = threadIdx.x, ty = threadIdx.y;
    const int tid = ty * 16 + tx;
    const int m0 = blockIdx.y * TBM, n0 = blockIdx.x * TBN;
    float acc[4][4];
#pragma unroll
    for (int u = 0; u < 4; u++)
#pragma unroll
        for (int v = 0; v < 4; v++) acc[u][v] = 0.f;
    for (int k0 = 0; k0 < K; k0 += TBK) {
        {
            int kk = tid & 15, i0 = tid >> 4;
#pragma unroll
            for (int r = 0; r < 4; r++) {
                int i = i0 + r * 16, gm = m0 + i, gk = k0 + kk;
                As[kk][i] = (gm < M && gk < K) ? A[(long long)gm * lda + gk] : 0.f;
            }
        }
        if (!transB) {
            int j = tid & 63, kk0 = tid >> 6;
#pragma unroll
            for (int r = 0; r < 4; r++) {
                int kk = kk0 + r * 4, gn = n0 + j, gk = k0 + kk;
                float v = (gn < N && gk < K) ? B[(long long)gk * ldb + gn] : 0.f;
                if (bscale && gk < K) v *= bscale[gk];
                Bs[kk][j] = v;
            }
        } else {
            int kk = tid & 15, j0 = tid >> 4;
#pragma unroll
            for (int r = 0; r < 4; r++) {
                int j = j0 + r * 16, gn = n0 + j, gk = k0 + kk;
                float v = (gn < N && gk < K) ? B[(long long)gn * ldb + gk] : 0.f;
                if (bscale && gk < K) v *= bscale[gk];
                Bs[kk][j] = v;
            }
        }
        __syncthreads();
#pragma unroll
        for (int kk = 0; kk < TBK; kk++) {
            float a[4], bv[4];
#pragma unroll
            for (int u = 0; u < 4; u++) a[u] = As[kk][ty * 4 + u];
#pragma unroll
            for (int v = 0; v < 4; v++) bv[v] = Bs[kk][tx * 4 + v];
#pragma unroll
            for (int u = 0; u < 4; u++)
#pragma unroll
                for (int v = 0; v < 4; v++) acc[u][v] += a[u] * bv[v];
        }
        __syncthreads();
    }
#pragma unroll
    for (int u = 0; u < 4; u++) {
        int gi = m0 + ty * 4 + u;
        if (gi >= M) continue;
#pragma unroll
        for (int v = 0; v < 4; v++) {
            int gj = n0 + tx * 4 + v;
            if (gj >= N) continue;
            float r = acc[u][v];
            long long idx = (long long)gi * ldc + gj;
            switch (epi) {
                case 2: C[idx] = __expf(2.f * r - e1[gi] - e2[gj]); break;
                case 3: {
                    float t = alpha * e1[gi] * r;
                    if (e2) t += beta * e2[idx];
                    C[idx] = t;
                } break;
                case 6: C[idx] = fmaxf(r + e2[gj], 0.f); break;
            }
        }
    }
}

// ---------------------------------------------------------------------------
// Helpers
// ---------------------------------------------------------------------------
__device__ __forceinline__ void bf_split(float v, __nv_bfloat16& h, __nv_bfloat16& l) {
    h = __float2bfloat16(v);
    l = __float2bfloat16(v - __bfloat162float(h));
}

__global__ void colmean_kernel(const float* __restrict__ X, float* __restrict__ mu, int C)
{
    int b = blockIdx.x, c = threadIdx.x;
    if (c >= C) return;
    const float* p = X + (long long)b * NN * C + c;
    float s = 0.f;
    for (int n = 0; n < NN; n++) s += p[(long long)n * C];
    mu[b * C + c] = s * (1.f / NN);
}

__global__ void sqnorm_kernel(const float* __restrict__ P, const float* __restrict__ mu,
                              float* __restrict__ sq, int C)
{
    int row = blockIdx.x * (blockDim.x / 32) + (threadIdx.x >> 5);
    int lane = threadIdx.x & 31;
    if (row >= BB * NN) return;
    const float* p = P + (long long)row * C;
    const float* m = mu ? mu + (row >> 10) * C : nullptr;
    float s = 0.f;
    for (int c = lane; c < C; c += 32) {
        float v = p[c];
        if (m) v -= m[c];
        s += v * v;
    }
#pragma unroll
    for (int o = 16; o; o >>= 1) s += __shfl_xor_sync(0xFFFFFFFFu, s, o);
    if (!lane) sq[row] = s;
}

__global__ void cvt_center_kernel(const float* __restrict__ X, const float* __restrict__ mu,
                                  __nv_bfloat16* __restrict__ dh, __nv_bfloat16* __restrict__ dl,
                                  int C, long long total)
{
    long long i = blockIdx.x * (long long)blockDim.x + threadIdx.x;
    if (i >= total) return;
    long long row = i / C;
    int c = (int)(i - row * C);
    float v = X[i] - mu[(row >> 10) * C + c];
    __nv_bfloat16 h, l;
    bf_split(v, h, l);
    dh[i] = h; dl[i] = l;
}

__global__ void cvt_flat_kernel(const float* __restrict__ src,
                                __nv_bfloat16* __restrict__ dh, __nv_bfloat16* __restrict__ dl,
                                long long n)
{
    long long i = blockIdx.x * (long long)blockDim.x + threadIdx.x;
    if (i >= n) return;
    __nv_bfloat16 h, l;
    bf_split(src[i], h, l);
    dh[i] = h; dl[i] = l;
}

__global__ void degree_kernel(const float* __restrict__ W,
                              float* __restrict__ dinv, float* __restrict__ din0)
{
    long long row = blockIdx.x;
    int col = (int)(row % NN);
    const float* w = W + row * NN;
    float s = 0.f, s0 = 0.f;
    for (int i = threadIdx.x; i < NN; i += 256) {
        float v = w[i];
        s += v;
        if (i != col) s0 += v;
    }
    __shared__ float sh[256], sh0[256];
    sh[threadIdx.x] = s; sh0[threadIdx.x] = s0;
    __syncthreads();
    for (int st = 128; st; st >>= 1) {
        if (threadIdx.x < st) { sh[threadIdx.x] += sh[threadIdx.x + st]; sh0[threadIdx.x] += sh0[threadIdx.x + st]; }
        __syncthreads();
    }
    if (!threadIdx.x) { dinv[row] = rsqrtf(sh[0]); din0[row] = rsqrtf(sh0[0]); }
}

__global__ void zero_diag_kernel(float* __restrict__ W,
                                 __nv_bfloat16* __restrict__ Wh, __nv_bfloat16* __restrict__ Wl)
{
    int i = blockIdx.x * blockDim.x + threadIdx.x;
    if (i >= BB * NN) return;
    int b = i >> 10, n = i & 1023;
    long long idx = (long long)b * NN * NN + (long long)n * NN + n;
    W[idx] = 0.f;
    if (Wh) { Wh[idx] = __float2bfloat16(0.f); Wl[idx] = __float2bfloat16(0.f); }
}

__global__ void copy_slice_kernel(const float* __restrict__ src, float* __restrict__ dst,
                                  int C, int KC, long long total)
{
    long long i = blockIdx.x * (long long)blockDim.x + threadIdx.x;
    if (i < total) {
        long long row = i / C;
        int c = (int)(i - row * C);
        dst[row * KC + c] = src[i];
    }
}

// fp32 slice [NN,C] -> strided bf16 split (dA, ldA) + optional transposed
// scaled bf16 (dB [C][NN], scale[b*NN + r])
__global__ void cvt_slice_kernel(const float* __restrict__ src, int ldS, long long sS,
    __nv_bfloat16* __restrict__ dAh, __nv_bfloat16* __restrict__ dAl, int ldA, long long sA,
    __nv_bfloat16* __restrict__ dBh, __nv_bfloat16* __restrict__ dBl, long long sB,
    const float* __restrict__ scale)
{
    __shared__ float t[32][33];
    int b = blockIdx.z;
    int r0 = blockIdx.x * 32, c0 = blockIdx.y * 32;
    src += (long long)b * sS; dAh += (long long)b * sA; dAl += (long long)b * sA;
    int tx = threadIdx.x, ty = threadIdx.y;
#pragma unroll
    for (int k = 0; k < 4; k++) {
        int r = r0 + ty + k * 8;
        float v = src[(long long)r * ldS + c0 + tx];
        __nv_bfloat16 h, l;
        bf_split(v, h, l);
        dAh[(long long)r * ldA + c0 + tx] = h;
        dAl[(long long)r * ldA + c0 + tx] = l;
        t[ty + k * 8][tx] = v;
    }
    if (dBh) {
        __syncthreads();
        dBh += (long long)b * sB; dBl += (long long)b * sB;
        const float* sc = scale ? scale + b * NN : nullptr;
#pragma unroll
        for (int k = 0; k < 4; k++) {
            int c = c0 + ty + k * 8;
            int r = r0 + tx;
            float v = t[tx][ty + k * 8];
            if (sc) v *= sc[r];
            __nv_bfloat16 h, l;
            bf_split(v, h, l);
            dBh[(long long)c * NN + r] = h;
            dBl[(long long)c * NN + r] = l;
        }
    }
}

// fp32 [R,C] -> transposed bf16 [C][R]: d1 (scaled by scale[b*R + r]), d2 optional unscaled
__global__ void cvt_trans2_kernel(const float* __restrict__ src, int R, int C, int ldS, long long sS,
    const float* __restrict__ scale,
    __nv_bfloat16* __restrict__ d1h, __nv_bfloat16* __restrict__ d1l,
    __nv_bfloat16* __restrict__ d2h, __nv_bfloat16* __restrict__ d2l, long long sD)
{
    __shared__ float t[32][33];
    int b = blockIdx.z;
    int r0 = blockIdx.x * 32, c0 = blockIdx.y * 32;
    src += (long long)b * sS;
    int tx = threadIdx.x, ty = threadIdx.y;
#pragma unroll
    for (int k = 0; k < 4; k++) {
        int r = r0 + ty + k * 8;
        t[ty + k * 8][tx] = src[(long long)r * ldS + c0 + tx];
    }
    __syncthreads();
    d1h += (long long)b * sD; d1l += (long long)b * sD;
    const float* sc = scale ? scale + (long long)b * R : nullptr;
#pragma unroll
    for (int k = 0; k < 4; k++) {
        int c = c0 + ty + k * 8;
        int r = r0 + tx;
        float v = t[tx][ty + k * 8];
        long long o = (long long)c * R + r;
        __nv_bfloat16 h, l;
        if (d2h) {
            bf_split(v, h, l);
            d2h[(long long)b * sD + o] = h;
            d2l[(long long)b * sD + o] = l;
        }
        if (sc) v *= sc[r];
        bf_split(v, h, l);
        d1h[o] = h; d1l[o] = l;
    }
}

__global__ void normsq_partial_kernel(const float* __restrict__ P, long long elems,
                                      int nsl, float* __restrict__ part)
{
    float s = 0.f;
    for (long long i = blockIdx.x * (long long)blockDim.x + threadIdx.x; i < elems;
         i += (long long)gridDim.x * blockDim.x) {
        float t = 0.f;
        for (int z = 0; z < nsl; z++) t += P[(long long)z * elems + i];
        s += t * t;
    }
    __shared__ float sh[256];
    sh[threadIdx.x] = s;
    __syncthreads();
    for (int st = 128; st; st >>= 1) {
        if (threadIdx.x < st) sh[threadIdx.x] += sh[threadIdx.x + st];
        __syncthreads();
    }
    if (!threadIdx.x) part[blockIdx.x] = sh[0];
}

__global__ void normsq_final_kernel(const float* __restrict__ part, float* __restrict__ r)
{
    __shared__ float sh[256];
    sh[threadIdx.x] = part[threadIdx.x];
    __syncthreads();
    for (int st = 128; st; st >>= 1) {
        if (threadIdx.x < st) sh[threadIdx.x] += sh[threadIdx.x + st];
        __syncthreads();
    }
    if (!threadIdx.x) *r = sqrtf(sh[0]);
}

__global__ void maxpool_kernel(const float* __restrict__ o3, float* __restrict__ pooled)
{
    int c = blockIdx.x * blockDim.x + threadIdx.x;
    int b = blockIdx.y;
    if (c >= 1024) return;
    const float* p = o3 + (long long)b * 1024 * 1024 + c;
    float m = p[0];
    for (int n = 1; n < 1024; n++) m = fmaxf(m, p[(long long)n * 1024]);
    pooled[b * 1024 + c] = m;
}

__global__ void fc_kernel(const float* __restrict__ in, const float* __restrict__ w,
                          const float* __restrict__ bias, float* __restrict__ out,
                          int K, int Nout, int do_relu)
{
    int j = blockIdx.x * blockDim.x + threadIdx.x;
    int b = blockIdx.y;
    if (j >= Nout) return;
    float s = bias[j];
    const float* ip = in + (long long)b * K;
    for (int k = 0; k < K; k++) s += ip[k] * w[(long long)k * Nout + j];
    if (do_relu) s = fmaxf(s, 0.f);
    out[(long long)b * Nout + j] = s;
}

// ---------------------------------------------------------------------------
// Host
// ---------------------------------------------------------------------------
typedef __nv_bfloat16 bf;
struct Bufs {
    float *W, *T, *Zall, *sq, *dinv, *din0, *mu, *part;
    bf *Wh, *Wl, *Ah, *Al, *Bh, *Bl, *Ch, *Cl;
};

static void mma_launch(int epi, int Nn, int Mm, int nb,
                       const bf* Ah, const bf* Al, const bf* Bh, const bf* Bl,
                       float* C, int K, int ldA, int ldB, int ldC,
                       long long sA, long long sB, long long sC,
                       const float* e1, long long sE1, const float* e2, long long sE2,
                       bf* Oh, bf* Ol, float alpha, float beta)
{
    dim3 g(Nn / 128, Mm / 128, nb);
    switch (epi) {
        case 0: mmagemm_kernel<0><<<g, 256, MM_DSMEM>>>(Ah, Al, Bh, Bl, C, K, ldA, ldB, ldC,
                    sA, sB, sC, e1, sE1, e2, sE2, Oh, Ol, alpha, beta); break;
        case 2: mmagemm_kernel<2><<<g, 256, MM_DSMEM>>>(Ah, Al, Bh, Bl, C, K, ldA, ldB, ldC,
                    sA, sB, sC, e1, sE1, e2, sE2, Oh, Ol, alpha, beta); break;
        case 3: mmagemm_kernel<3><<<g, 256, MM_DSMEM>>>(Ah, Al, Bh, Bl, C, K, ldA, ldB, ldC,
                    sA, sB, sC, e1, sE1, e2, sE2, Oh, Ol, alpha, beta); break;
        case 5: mmagemm_kernel<5><<<g, 256, MM_DSMEM>>>(Ah, Al, Bh, Bl, C, K, ldA, ldB, ldC,
                    sA, sB, sC, e1, sE1, e2, sE2, Oh, Ol, alpha, beta); break;
        case 6: mmagemm_kernel<6><<<g, 256, MM_DSMEM>>>(Ah, Al, Bh, Bl, C, K, ldA, ldB, ldC,
                    sA, sB, sC, e1, sE1, e2, sE2, Oh, Ol, alpha, beta); break;
    }
}

// Shared reg + M + norm tail. Requires Wh/Wl diag-zeroed, din0 ready. Cout%128.
static void reg_tail_tc(float* OUT, int Cout, float* r_out, const Bufs& bf_)
{
    const long long sO = (long long)NN * Cout;
    {
        dim3 g(NN / 32, Cout / 32, BB);
        cvt_trans2_kernel<<<g, dim3(32, 8)>>>(OUT, NN, Cout, Cout, sO, bf_.din0,
            bf_.Bh, bf_.Bl, bf_.Ah, bf_.Al, (long long)Cout * NN);
    }
    // T = OUT - d0 .* (W0 @ (d0.*OUT))
    mma_launch(5, Cout, NN, BB, bf_.Wh, bf_.Wl, bf_.Bh, bf_.Bl, bf_.T, NN, NN, NN, Cout,
               (long long)NN * NN, (long long)Cout * NN, sO,
               bf_.din0, NN, OUT, sO, nullptr, nullptr, 0.f, 0.f);
    {
        dim3 g(NN / 32, Cout / 32, BB);
        cvt_trans2_kernel<<<g, dim3(32, 8)>>>(bf_.T, NN, Cout, Cout, sO, nullptr,
            bf_.Ch, bf_.Cl, nullptr, nullptr, (long long)Cout * NN);
    }
    // M partials per batch into g_W
    mma_launch(0, Cout, Cout, BB, bf_.Ah, bf_.Al, bf_.Ch, bf_.Cl, bf_.W, NN, NN, NN, Cout,
               (long long)Cout * NN, (long long)Cout * NN, (long long)Cout * Cout,
               nullptr, 0, nullptr, 0, nullptr, nullptr, 1.f, 0.f);
    normsq_partial_kernel<<<256, 256>>>(bf_.W, (long long)Cout * Cout, BB, bf_.part);
    normsq_final_kernel<<<1, 256>>>(bf_.part, r_out);
}

static void run_layer_tc(const float* X, int Cin, int Cout, int Kcheb,
                         const float* Wk, const float* bias,
                         float* OUT, float* r_out, const Bufs& bf_)
{
    const int KC = Kcheb * Cin;
    const long long sX = (long long)NN * Cin;
    const long long sZ = (long long)NN * KC;
    const long long sO = (long long)NN * Cout;
    const long long sW = (long long)NN * NN;

    // gram (mean-centered) -> W fp32 + Wh/Wl bf16 split
    colmean_kernel<<<BB, Cin>>>(X, bf_.mu, Cin);
    sqnorm_kernel<<<(BB * NN) / 8, 256>>>(X, bf_.mu, bf_.sq, Cin);
    cvt_center_kernel<<<(unsigned)((BB * sX + 255) / 256), 256>>>(X, bf_.mu, bf_.Bh, bf_.Bl,
                                                                  Cin, BB * sX);
    mma_launch(2, NN, NN, BB, bf_.Bh, bf_.Bl, bf_.Bh, bf_.Bl, bf_.W, Cin, Cin, Cin, NN,
               sX, sX, sW, bf_.sq, NN, bf_.sq, NN, bf_.Wh, bf_.Wl, 0.f, 0.f);
    degree_kernel<<<BB * NN, 256>>>(bf_.W, bf_.dinv, bf_.din0);

    // Zall slice 0 = X; A-side split + transposed-scaled B-side for cheb1
    copy_slice_kernel<<<(unsigned)((BB * sX + 255) / 256), 256>>>(X, bf_.Zall, Cin, KC, BB * sX);
    {
        dim3 g(NN / 32, Cin / 32, BB);
        cvt_slice_kernel<<<g, dim3(32, 8)>>>(bf_.Zall, KC, sZ, bf_.Ah, bf_.Al, KC, sZ,
                                             nullptr, nullptr, 0, nullptr);
        cvt_trans2_kernel<<<g, dim3(32, 8)>>>(bf_.Zall, NN, Cin, KC, sZ, bf_.dinv,
            bf_.Bh, bf_.Bl, nullptr, nullptr, (long long)Cin * NN);
    }
    // Chebyshev recursion
    for (int k = 1; k < Kcheb; k++) {
        float* Ck = bf_.Zall + (long long)k * Cin;
        const float* Ek = (k >= 2) ? (bf_.Zall + (long long)(k - 2) * Cin) : nullptr;
        float alpha = (k == 1) ? -1.f : -2.f;
        mma_launch(3, Cin, NN, BB, bf_.Wh, bf_.Wl, bf_.Bh, bf_.Bl, Ck, NN, NN, NN, KC,
                   sW, (long long)Cin * NN, sZ, bf_.dinv, NN, Ek, sZ,
                   nullptr, nullptr, alpha, -1.f);
        dim3 g(NN / 32, Cin / 32, BB);
        bool more = (k < Kcheb - 1);
        cvt_slice_kernel<<<g, dim3(32, 8)>>>(Ck, KC, sZ, bf_.Ah + (long long)k * Cin,
            bf_.Al + (long long)k * Cin, KC, sZ,
            more ? bf_.Bh : nullptr, more ? bf_.Bl : nullptr,
            (long long)Cin * NN, bf_.dinv);
    }
    // combine: Wk^T -> Ch/Cl; OUT = relu(Zall @ Wk + bias)
    {
        dim3 g(KC / 32, Cout / 32, 1);
        cvt_trans2_kernel<<<g, dim3(32, 8)>>>(Wk, KC, Cout, Cout, 0, nullptr,
            bf_.Ch, bf_.Cl, nullptr, nullptr, 0);
    }
    mma_launch(6, Cout, NN, BB, bf_.Ah, bf_.Al, bf_.Ch, bf_.Cl, OUT, KC, KC, KC, Cout,
               sZ, 0, sO, nullptr, 0, bias, 0, nullptr, nullptr, 0.f, 0.f);

    zero_diag_kernel<<<(BB * NN + 255) / 256, 256>>>(bf_.W, bf_.Wh, bf_.Wl);
    reg_tail_tc(OUT, Cout, r_out, bf_);
}

// Layer 1: fp32 conv path (Cin=6), then MMA reg tail.
static void run_layer1(const float* X, const float* Wk, const float* bias,
                       float* OUT, float* r_out, const Bufs& bf_)
{
    const int Cin = 6, Cout = 128, Kcheb = 6, KC = 36;
    const long long sX = (long long)NN * Cin;
    const long long sZ = (long long)NN * KC;
    const long long sO = (long long)NN * Cout;
    const long long sW = (long long)NN * NN;

    sqnorm_kernel<<<(BB * NN) / 8, 256>>>(X, nullptr, bf_.sq, Cin);
    {
        dim3 g(NN / TBN, NN / TBM, BB);
        gemm_kernel<<<g, dim3(16, 16)>>>(X, X, bf_.W, NN, NN, Cin, Cin, Cin, NN, sX, sX, sW,
            1, nullptr, 0, 2, bf_.sq, NN, bf_.sq, NN, 1.f, 0.f);
    }
    degree_kernel<<<BB * NN, 256>>>(bf_.W, bf_.dinv, bf_.din0);
    copy_slice_kernel<<<(unsigned)((BB * sX + 255) / 256), 256>>>(X, bf_.Zall, Cin, KC, BB * sX);
    for (int k = 1; k < Kcheb; k++) {
        float* Ck = bf_.Zall + (long long)k * Cin;
        const float* Bk = bf_.Zall + (long long)(k - 1) * Cin;
        const float* Ek = (k >= 2) ? (bf_.Zall + (long long)(k - 2) * Cin) : nullptr;
        float alpha = (k == 1) ? -1.f : -2.f;
        dim3 g(1, NN / TBM, BB);
        gemm_kernel<<<g, dim3(16, 16)>>>(bf_.W, Bk, Ck, NN, Cin, NN, NN, KC, KC, sW, sZ, sZ,
            0, bf_.dinv, NN, 3, bf_.dinv, NN, Ek, sZ, alpha, -1.f);
    }
    {
        dim3 g(Cout / TBN, NN / TBM, BB);
        gemm_kernel<<<g, dim3(16, 16)>>>(bf_.Zall, Wk, OUT, NN, Cout, KC, KC, Cout, Cout,
            sZ, 0, sO, 0, nullptr, 0, 6, nullptr, 0, bias, 0, 1.f, 0.f);
    }
    zero_diag_kernel<<<(BB * NN + 255) / 256, 256>>>(bf_.W, nullptr, nullptr);
    cvt_flat_kernel<<<(unsigned)(((long long)BB * sW + 255) / 256), 256>>>(bf_.W, bf_.Wh, bf_.Wl,
                                                                           (long long)BB * sW);
    reg_tail_tc(OUT, Cout, r_out, bf_);
}

extern "C" void kernel_launch(void* const* d_in, const int* in_sizes, int n_in,
                              void* d_out, int out_size)
{
    (void)in_sizes; (void)out_size;
    cudaFuncSetAttribute(mmagemm_kernel<0>, cudaFuncAttributeMaxDynamicSharedMemorySize, MM_DSMEM);
    cudaFuncSetAttribute(mmagemm_kernel<2>, cudaFuncAttributeMaxDynamicSharedMemorySize, MM_DSMEM);
    cudaFuncSetAttribute(mmagemm_kernel<3>, cudaFuncAttributeMaxDynamicSharedMemorySize, MM_DSMEM);
    cudaFuncSetAttribute(mmagemm_kernel<5>, cudaFuncAttributeMaxDynamicSharedMemorySize, MM_DSMEM);
    cudaFuncSetAttribute(mmagemm_kernel<6>, cudaFuncAttributeMaxDynamicSharedMemorySize, MM_DSMEM);

    const float* x = (const float*)d_in[0];
    int base = n_in - 12;
    const float* w1  = (const float*)d_in[base + 0];
    const float* b1  = (const float*)d_in[base + 1];
    const float* w2  = (const float*)d_in[base + 2];
    const float* b2  = (const float*)d_in[base + 3];
    const float* w3  = (const float*)d_in[base + 4];
    const float* b3  = (const float*)d_in[base + 5];
    const float* fw1 = (const float*)d_in[base + 6];
    const float* fb1 = (const float*)d_in[base + 7];
    const float* fw2 = (const float*)d_in[base + 8];
    const float* fb2 = (const float*)d_in[base + 9];
    const float* fw3 = (const float*)d_in[base + 10];
    const float* fb3 = (const float*)d_in[base + 11];
    float* out = (float*)d_out;

    Bufs bf_;
    float *o1, *o2, *o3, *pool, *h1, *h2;
    cudaGetSymbolAddress((void**)&bf_.W,    g_W);
    cudaGetSymbolAddress((void**)&bf_.T,    g_T);
    cudaGetSymbolAddress((void**)&bf_.Zall, g_Zall);
    cudaGetSymbolAddress((void**)&bf_.sq,   g_sq);
    cudaGetSymbolAddress((void**)&bf_.dinv, g_dinv);
    cudaGetSymbolAddress((void**)&bf_.din0, g_din0);
    cudaGetSymbolAddress((void**)&bf_.mu,   g_mu);
    cudaGetSymbolAddress((void**)&bf_.part, g_part);
    cudaGetSymbolAddress((void**)&bf_.Wh,   g_Wh);
    cudaGetSymbolAddress((void**)&bf_.Wl,   g_Wl);
    cudaGetSymbolAddress((void**)&bf_.Ah,   g_Ah);
    cudaGetSymbolAddress((void**)&bf_.Al,   g_Al);
    cudaGetSymbolAddress((void**)&bf_.Bh,   g_Bh);
    cudaGetSymbolAddress((void**)&bf_.Bl,   g_Bl);
    cudaGetSymbolAddress((void**)&bf_.Ch,   g_Ch);
    cudaGetSymbolAddress((void**)&bf_.Cl,   g_Cl);
    cudaGetSymbolAddress((void**)&o1,   g_out1);
    cudaGetSymbolAddress((void**)&o2,   g_out2);
    cudaGetSymbolAddress((void**)&o3,   g_out3);
    cudaGetSymbolAddress((void**)&pool, g_pool);
    cudaGetSymbolAddress((void**)&h1,   g_h1);
    cudaGetSymbolAddress((void**)&h2,   g_h2);

    run_layer1(x, w1, b1, o1, out + 160, bf_);
    run_layer_tc(o1, 128, 512,  5, w2, b2, o2, out + 161, bf_);
    run_layer_tc(o2, 512, 1024, 3, w3, b3, o3, out + 162, bf_);

    {
        dim3 g(1024 / 256, BB);
        maxpool_kernel<<<g, 256>>>(o3, pool);
    }
    {
        dim3 g1((512 + 127) / 128, BB);
        fc_kernel<<<g1, 128>>>(pool, fw1, fb1, h1, 1024, 512, 1);
        dim3 g2(1, BB);
        fc_kernel<<<g2, 128>>>(h1, fw2, fb2, h2, 512, 128, 1);
        fc_kernel<<<g2, 128>>>(h2, fw3, fb3, out, 128, 10, 0);
    }
}